// round 1
// baseline (speedup 1.0000x reference)
#include <cuda_runtime.h>

// Problem constants (fixed by the dataset)
#define NMAX 20000
#define EMAX 200000
#define C_   14
#define D_   3
#define A_   16
#define F_   128
#define TIL  32
#define PAD  36

// ---- scratch (device globals: no allocations allowed) ----
__device__ float g_radial[(size_t)EMAX * F_];   // [E,128]
__device__ float g_ef_sum[(size_t)NMAX * F_];   // per-col accumulation of ef
__device__ float g_x_acc [(size_t)NMAX * C_ * D_];
__device__ float g_cnt_row[NMAX];
__device__ float g_cnt_col[NMAX];
__device__ float g_pooled [NMAX * D_];          // masked channel-mean of x per node
__device__ int   g_csum   [NMAX];               // # valid channels per node

__device__ __forceinline__ float sigm_(float v) { return 1.f / (1.f + __expf(-v)); }
__device__ __forceinline__ float silu_(float v) { return v * sigm_(v); }

// ---------------------------------------------------------------------------
// K0: zero the accumulators (must happen every launch - graph replays)
// ---------------------------------------------------------------------------
__global__ void k_zero(int n_nodes) {
    int t0 = n_nodes * F_;
    int t1 = t0 + n_nodes * C_ * D_;
    int t2 = t1 + n_nodes;
    int t3 = t2 + n_nodes;
    for (int i = blockIdx.x * blockDim.x + threadIdx.x; i < t3;
         i += gridDim.x * blockDim.x) {
        if (i < t0)       g_ef_sum[i] = 0.f;
        else if (i < t1)  g_x_acc[i - t0] = 0.f;
        else if (i < t2)  g_cnt_row[i - t1] = 0.f;
        else              g_cnt_col[i - t2] = 0.f;
    }
}

// ---------------------------------------------------------------------------
// K1: per-node prep: channel_sum + masked channel-mean of x
// ---------------------------------------------------------------------------
__global__ void k_prep(const float* __restrict__ x, const float* __restrict__ cw,
                       int N) {
    int n = blockIdx.x * blockDim.x + threadIdx.x;
    if (n >= N) return;
    int s = 0;
    float px = 0.f, py = 0.f, pz = 0.f;
    #pragma unroll
    for (int i = 0; i < C_; ++i) {
        float w = cw[n * C_ + i];
        if (w != 0.f) {
            s++;
            px += x[n * C_ * D_ + i * 3 + 0];
            py += x[n * C_ * D_ + i * 3 + 1];
            pz += x[n * C_ * D_ + i * 3 + 2];
        }
    }
    g_csum[n] = s;
    float inv = 1.f / (float)(s > 0 ? s : 1);
    g_pooled[n * 3 + 0] = px * inv;
    g_pooled[n * 3 + 1] = py * inv;
    g_pooled[n * 3 + 2] = pz * inv;
}

// ---------------------------------------------------------------------------
// K2: per-edge radial feature: einsum prologue + GEMV 256->128 / (||R||+1)
//     block = 128 threads, TIL=32 edges
// ---------------------------------------------------------------------------
__global__ __launch_bounds__(128) void k_radial(
    const float* __restrict__ x, const float* __restrict__ attr,
    const float* __restrict__ cw, const int* __restrict__ row,
    const int* __restrict__ col, const float* __restrict__ rad_w,
    const float* __restrict__ rad_b, int E)
{
    extern __shared__ float sm[];
    float* in_s     = sm;                 // [256][PAD]  (R flattened, k-major)
    float* wsc      = sm + 256 * PAD;     // 4 warps * 1024
    float* inv_norm = wsc + 4 * 1024;     // [32]

    int tid = threadIdx.x, lane = tid & 31, wp = tid >> 5;
    int e0 = blockIdx.x * TIL;

    float* W     = wsc + wp * 1024;
    float* s_xr  = W;           // 42
    float* s_xc  = W + 48;      // 42
    float* s_cwr = W + 96;      // 14
    float* s_cwc = W + 112;     // 14
    float* s_ar  = W + 128;     // 224
    float* s_ac  = W + 352;     // 224
    float* s_msg = W + 576;     // 196
    float* s_T   = W + 772;     // 224  (ends at 996 <= 1024)

    for (int it = 0; it < 8; ++it) {
        int m = it * 4 + wp;
        int e = e0 + m;
        int r = 0, c = 0;
        if (e < E) { r = row[e]; c = col[e]; }
        for (int i = lane; i < 42; i += 32) {
            s_xr[i] = x[r * 42 + i];
            s_xc[i] = x[c * 42 + i];
        }
        for (int i = lane; i < 14; i += 32) {
            s_cwr[i] = cw[r * C_ + i];
            s_cwc[i] = cw[c * C_ + i];
        }
        for (int i = lane; i < 224; i += 32) {
            s_ar[i] = attr[r * 224 + i];
            s_ac[i] = attr[c * 224 + i];
        }
        __syncwarp();
        // msg[ci][cj] = ||x_r[ci]-x_c[cj]|| * cw_r[ci]*cw_c[cj]
        for (int i = lane; i < 196; i += 32) {
            int ci = i / 14, cj = i - ci * 14;
            float dx = s_xr[ci * 3 + 0] - s_xc[cj * 3 + 0];
            float dy = s_xr[ci * 3 + 1] - s_xc[cj * 3 + 1];
            float dz = s_xr[ci * 3 + 2] - s_xc[cj * 3 + 2];
            s_msg[i] = sqrtf(dx * dx + dy * dy + dz * dz) * s_cwr[ci] * s_cwc[cj];
        }
        __syncwarp();
        // T[ci][b] = sum_cj msg[ci][cj] * attr_c[cj][b]
        for (int i = lane; i < 224; i += 32) {
            int ci = i >> 4, b = i & 15;
            float t = 0.f;
            #pragma unroll
            for (int jj = 0; jj < C_; ++jj) t += s_msg[ci * 14 + jj] * s_ac[jj * 16 + b];
            s_T[i] = t;
        }
        __syncwarp();
        // R[a][b] = sum_ci attr_r[ci][a] * T[ci][b]  -> in_s[a*16+b][m], + norm
        float ss = 0.f;
        for (int i = lane; i < 256; i += 32) {
            int a = i >> 4, b = i & 15;
            float t = 0.f;
            #pragma unroll
            for (int jj = 0; jj < C_; ++jj) t += s_ar[jj * 16 + a] * s_T[jj * 16 + b];
            in_s[i * PAD + m] = t;
            ss += t * t;
        }
        #pragma unroll
        for (int o = 16; o; o >>= 1) ss += __shfl_xor_sync(0xffffffffu, ss, o);
        if (lane == 0) inv_norm[m] = 1.f / (sqrtf(ss) + 1.f);
        __syncwarp();
    }
    __syncthreads();

    // GEMV: radial[e][j] = (R_flat . rad_w[:,j] + rad_b[j]) * inv_norm
    int j = tid;
    float acc[TIL];
    #pragma unroll
    for (int m = 0; m < TIL; ++m) acc[m] = 0.f;
    #pragma unroll 4
    for (int k = 0; k < 256; ++k) {
        float wv = rad_w[k * F_ + j];
        const float4* p = reinterpret_cast<const float4*>(in_s + k * PAD);
        #pragma unroll
        for (int q = 0; q < 8; ++q) {
            float4 v = p[q];
            acc[q * 4 + 0] += v.x * wv;
            acc[q * 4 + 1] += v.y * wv;
            acc[q * 4 + 2] += v.z * wv;
            acc[q * 4 + 3] += v.w * wv;
        }
    }
    float bj = rad_b[j];
    #pragma unroll
    for (int m = 0; m < TIL; ++m) {
        int e = e0 + m;
        if (e < E) g_radial[(size_t)e * F_ + j] = (acc[m] + bj) * inv_norm[m];
    }
}

// ---------------------------------------------------------------------------
// K3: fused edge kernel: edge MLP + attention gate + agg scatter +
//     coord MLP + RollerPooling + trans scatter
// ---------------------------------------------------------------------------
__global__ __launch_bounds__(128) void k_edge(
    const float* __restrict__ h, const float* __restrict__ x,
    const int* __restrict__ row, const int* __restrict__ col,
    const float* __restrict__ e_w1, const float* __restrict__ e_b1,
    const float* __restrict__ e_w2, const float* __restrict__ e_b2,
    const float* __restrict__ att_w, const float* __restrict__ att_b,
    const float* __restrict__ c_w1, const float* __restrict__ c_b1,
    const float* __restrict__ c_w2, const float* __restrict__ c_b2,
    int E)
{
    extern __shared__ float sm[];
    float* in_s   = sm;                    // [384][PAD]
    float* t1_s   = in_s + 384 * PAD;      // [128][PAD]
    float* cm_s   = t1_s + 128 * PAD;      // [32][16]
    float* red_s  = cm_s + 32 * 16;        // [4][32]
    float* gate_s = red_s + 128;           // [32]
    int*   s_row  = (int*)(gate_s + 32);
    int*   s_col  = s_row + 32;
    int*   s_cs   = s_col + 32;

    int tid = threadIdx.x, lane = tid & 31, wp = tid >> 5;
    int e0 = blockIdx.x * TIL;
    if (tid < TIL) {
        int e = e0 + tid;
        int r = 0, c = 0;
        if (e < E) { r = row[e]; c = col[e]; }
        s_row[tid] = r;
        s_col[tid] = c;
        s_cs[tid]  = g_csum[r];
    }
    __syncthreads();

    // gather: in = [h[row] | h[col] | radial]
    for (int m = 0; m < TIL; ++m) {
        int r = s_row[m], c = s_col[m];
        int e = e0 + m;
        in_s[tid * PAD + m]         = h[(size_t)r * F_ + tid];
        in_s[(128 + tid) * PAD + m] = h[(size_t)c * F_ + tid];
        in_s[(256 + tid) * PAD + m] = (e < E) ? g_radial[(size_t)e * F_ + tid] : 0.f;
    }
    __syncthreads();

    int j = tid;
    float acc[TIL];

    // GEMM1: 384 -> 128, silu
    #pragma unroll
    for (int m = 0; m < TIL; ++m) acc[m] = 0.f;
    #pragma unroll 4
    for (int k = 0; k < 384; ++k) {
        float wv = e_w1[k * F_ + j];
        const float4* p = reinterpret_cast<const float4*>(in_s + k * PAD);
        #pragma unroll
        for (int q = 0; q < 8; ++q) {
            float4 v = p[q];
            acc[q * 4 + 0] += v.x * wv;
            acc[q * 4 + 1] += v.y * wv;
            acc[q * 4 + 2] += v.z * wv;
            acc[q * 4 + 3] += v.w * wv;
        }
    }
    {
        float b1 = e_b1[j];
        #pragma unroll
        for (int m = 0; m < TIL; ++m) t1_s[j * PAD + m] = silu_(acc[m] + b1);
    }
    __syncthreads();

    // GEMM2: 128 -> 128, silu -> t2
    float t2[TIL];
    #pragma unroll
    for (int m = 0; m < TIL; ++m) acc[m] = 0.f;
    #pragma unroll 4
    for (int k = 0; k < 128; ++k) {
        float wv = e_w2[k * F_ + j];
        const float4* p = reinterpret_cast<const float4*>(t1_s + k * PAD);
        #pragma unroll
        for (int q = 0; q < 8; ++q) {
            float4 v = p[q];
            acc[q * 4 + 0] += v.x * wv;
            acc[q * 4 + 1] += v.y * wv;
            acc[q * 4 + 2] += v.z * wv;
            acc[q * 4 + 3] += v.w * wv;
        }
    }
    {
        float b2 = e_b2[j];
        #pragma unroll
        for (int m = 0; m < TIL; ++m) t2[m] = silu_(acc[m] + b2);
    }

    // attention gate: sigmoid(t2 . att_w + att_b) per edge
    {
        float aw = att_w[j];
        #pragma unroll
        for (int m = 0; m < TIL; ++m) {
            float pm = t2[m] * aw;
            #pragma unroll
            for (int o = 16; o; o >>= 1) pm += __shfl_xor_sync(0xffffffffu, pm, o);
            if (lane == 0) red_s[wp * 32 + m] = pm;
        }
    }
    __syncthreads();
    if (tid < TIL) {
        float av = red_s[tid] + red_s[32 + tid] + red_s[64 + tid] + red_s[96 + tid]
                 + att_b[0];
        gate_s[tid] = sigm_(av);
    }
    __syncthreads();

    // ef = t2 * gate; scatter into per-col sum; stage ef for GEMM3 (reuse in_s)
    #pragma unroll
    for (int m = 0; m < TIL; ++m) {
        float ef = t2[m] * gate_s[m];
        t2[m] = ef;
        in_s[j * PAD + m] = ef;
        if (e0 + m < E) atomicAdd(&g_ef_sum[(size_t)s_col[m] * F_ + j], ef);
    }
    if (tid < TIL && e0 + tid < E) {
        atomicAdd(&g_cnt_col[s_col[tid]], 1.f);
        atomicAdd(&g_cnt_row[s_row[tid]], 1.f);
    }
    __syncthreads();

    // GEMM3: ef (128) -> 128, silu -> cmh (store to t1_s)
    #pragma unroll
    for (int m = 0; m < TIL; ++m) acc[m] = 0.f;
    #pragma unroll 4
    for (int k = 0; k < 128; ++k) {
        float wv = c_w1[k * F_ + j];
        const float4* p = reinterpret_cast<const float4*>(in_s + k * PAD);
        #pragma unroll
        for (int q = 0; q < 8; ++q) {
            float4 v = p[q];
            acc[q * 4 + 0] += v.x * wv;
            acc[q * 4 + 1] += v.y * wv;
            acc[q * 4 + 2] += v.z * wv;
            acc[q * 4 + 3] += v.w * wv;
        }
    }
    {
        float b1 = c_b1[j];
        #pragma unroll
        for (int m = 0; m < TIL; ++m) t1_s[j * PAD + m] = silu_(acc[m] + b1);
    }
    __syncthreads();

    // c_w2: 128 -> 14 per edge (448 outputs over 128 threads)
    for (int it = 0; it < 4; ++it) {
        int idx = it * 128 + tid;
        if (idx < TIL * C_) {
            int m = idx & 31, o = idx >> 5;
            float s = c_b2[o];
            #pragma unroll 4
            for (int k = 0; k < 128; ++k) s += t1_s[k * PAD + m] * c_w2[k * C_ + o];
            cm_s[m * 16 + o] = s;
        }
    }
    __syncthreads();

    // RollerPooling + trans scatter: ws = C - (channel_sum-1)
    for (int idx = tid; idx < TIL * 42; idx += 128) {
        int m = idx / 42, rem = idx - m * 42;
        int e = e0 + m;
        if (e < E) {
            int i = rem / 3;
            int d = rem - i * 3;
            int ws = (C_ + 1) - s_cs[m];
            if (ws < 1)  ws = 1;
            if (ws > C_) ws = C_;
            int end = i + ws;
            if (end > C_) end = C_;
            float ps = 0.f;
            for (int q = i; q < end; ++q) ps += cm_s[m * 16 + q];
            float pooled = ps / (float)ws;
            float cd = x[(size_t)s_row[m] * 42 + rem] - g_pooled[s_col[m] * 3 + d];
            atomicAdd(&g_x_acc[(size_t)s_row[m] * 42 + rem], cd * pooled);
        }
    }
}

// ---------------------------------------------------------------------------
// K4: node update: agg mean -> node MLP -> residual -> LayerNorm, plus x_new
// ---------------------------------------------------------------------------
__global__ __launch_bounds__(128) void k_node(
    const float* __restrict__ h, const float* __restrict__ x,
    const float* __restrict__ n_w1, const float* __restrict__ n_b1,
    const float* __restrict__ n_w2, const float* __restrict__ n_b2,
    const float* __restrict__ ln_g, const float* __restrict__ ln_b,
    float* __restrict__ out, int N)
{
    extern __shared__ float sm[];
    float* in_s = sm;                  // [256][PAD]
    float* t1_s = in_s + 256 * PAD;    // [128][PAD]
    float* red1 = t1_s + 128 * PAD;    // [4][32]
    float* red2 = red1 + 128;          // [4][32]
    float* mu_s = red2 + 128;          // [32]
    float* rs_s = mu_s + 32;           // [32]
    float* ic_s = rs_s + 32;           // [32]

    int tid = threadIdx.x, lane = tid & 31, wp = tid >> 5;
    int n0 = blockIdx.x * TIL;

    if (tid < TIL) {
        int n = n0 + tid;
        float c = (n < N) ? g_cnt_col[n] : 1.f;
        ic_s[tid] = 1.f / fmaxf(c, 1.f);
    }
    __syncthreads();

    for (int m = 0; m < TIL; ++m) {
        int n = n0 + m;
        if (n >= N) n = N - 1;
        in_s[tid * PAD + m]         = h[(size_t)n * F_ + tid];
        in_s[(128 + tid) * PAD + m] = g_ef_sum[(size_t)n * F_ + tid] * ic_s[m];
    }
    __syncthreads();

    int j = tid;
    float acc[TIL];

    // GEMM1: 256 -> 128, silu
    #pragma unroll
    for (int m = 0; m < TIL; ++m) acc[m] = 0.f;
    #pragma unroll 4
    for (int k = 0; k < 256; ++k) {
        float wv = n_w1[k * F_ + j];
        const float4* p = reinterpret_cast<const float4*>(in_s + k * PAD);
        #pragma unroll
        for (int q = 0; q < 8; ++q) {
            float4 v = p[q];
            acc[q * 4 + 0] += v.x * wv;
            acc[q * 4 + 1] += v.y * wv;
            acc[q * 4 + 2] += v.z * wv;
            acc[q * 4 + 3] += v.w * wv;
        }
    }
    {
        float b1 = n_b1[j];
        #pragma unroll
        for (int m = 0; m < TIL; ++m) t1_s[j * PAD + m] = silu_(acc[m] + b1);
    }
    __syncthreads();

    // GEMM2: 128 -> 128, + residual h
    #pragma unroll
    for (int m = 0; m < TIL; ++m) acc[m] = 0.f;
    #pragma unroll 4
    for (int k = 0; k < 128; ++k) {
        float wv = n_w2[k * F_ + j];
        const float4* p = reinterpret_cast<const float4*>(t1_s + k * PAD);
        #pragma unroll
        for (int q = 0; q < 8; ++q) {
            float4 v = p[q];
            acc[q * 4 + 0] += v.x * wv;
            acc[q * 4 + 1] += v.y * wv;
            acc[q * 4 + 2] += v.z * wv;
            acc[q * 4 + 3] += v.w * wv;
        }
    }
    float hr[TIL];
    {
        float b2 = n_b2[j];
        #pragma unroll
        for (int m = 0; m < TIL; ++m) hr[m] = in_s[j * PAD + m] + acc[m] + b2;
    }

    // LayerNorm stats over the 128 features (128 threads)
    #pragma unroll
    for (int m = 0; m < TIL; ++m) {
        float s1 = hr[m];
        float s2 = hr[m] * hr[m];
        #pragma unroll
        for (int o = 16; o; o >>= 1) {
            s1 += __shfl_xor_sync(0xffffffffu, s1, o);
            s2 += __shfl_xor_sync(0xffffffffu, s2, o);
        }
        if (lane == 0) {
            red1[wp * 32 + m] = s1;
            red2[wp * 32 + m] = s2;
        }
    }
    __syncthreads();
    if (tid < TIL) {
        float s1 = red1[tid] + red1[32 + tid] + red1[64 + tid] + red1[96 + tid];
        float s2 = red2[tid] + red2[32 + tid] + red2[64 + tid] + red2[96 + tid];
        float mu = s1 * (1.f / 128.f);
        float var = fmaxf(s2 * (1.f / 128.f) - mu * mu, 0.f);
        mu_s[tid] = mu;
        rs_s[tid] = rsqrtf(var + 1e-5f);
    }
    __syncthreads();

    {
        float g = ln_g[j], b = ln_b[j];
        #pragma unroll
        for (int m = 0; m < TIL; ++m) {
            int n = n0 + m;
            if (n < N)
                out[(size_t)n * F_ + j] = (hr[m] - mu_s[m]) * rs_s[m] * g + b;
        }
    }

    // x_new = x + x_acc / max(cnt_row, 1)
    float* out_x = out + (size_t)N * F_;
    for (int idx = tid; idx < TIL * 42; idx += 128) {
        int m = idx / 42, rem = idx - m * 42;
        int n = n0 + m;
        if (n < N) {
            out_x[(size_t)n * 42 + rem] =
                x[(size_t)n * 42 + rem] +
                g_x_acc[(size_t)n * 42 + rem] / fmaxf(g_cnt_row[n], 1.f);
        }
    }
}

// ---------------------------------------------------------------------------
// launch
// ---------------------------------------------------------------------------
extern "C" void kernel_launch(void* const* d_in, const int* in_sizes, int n_in,
                              void* d_out, int out_size) {
    const float* h     = (const float*)d_in[0];
    const float* x     = (const float*)d_in[1];
    const float* attr  = (const float*)d_in[2];
    const float* cw    = (const float*)d_in[3];
    const int*   row   = (const int*)d_in[4];
    const int*   col   = (const int*)d_in[5];
    const float* rad_w = (const float*)d_in[6];
    const float* rad_b = (const float*)d_in[7];
    const float* e_w1  = (const float*)d_in[8];
    const float* e_b1  = (const float*)d_in[9];
    const float* e_w2  = (const float*)d_in[10];
    const float* e_b2  = (const float*)d_in[11];
    const float* att_w = (const float*)d_in[12];
    const float* att_b = (const float*)d_in[13];
    const float* c_w1  = (const float*)d_in[14];
    const float* c_b1  = (const float*)d_in[15];
    const float* c_w2  = (const float*)d_in[16];
    const float* c_b2  = (const float*)d_in[17];
    const float* n_w1  = (const float*)d_in[18];
    const float* n_b1  = (const float*)d_in[19];
    const float* n_w2  = (const float*)d_in[20];
    const float* n_b2  = (const float*)d_in[21];
    const float* ln_g  = (const float*)d_in[22];
    const float* ln_b  = (const float*)d_in[23];

    int N = in_sizes[0] / F_;
    int E = in_sizes[4];

    const int SMEM2 = (256 * PAD + 4 * 1024 + 32) * 4;
    const int SMEM3 = (384 * PAD + 128 * PAD + 32 * 16 + 128 + 32) * 4 + 3 * 32 * 4;
    const int SMEM4 = (256 * PAD + 128 * PAD + 128 + 128 + 32 + 32 + 32) * 4;

    cudaFuncSetAttribute(k_radial, cudaFuncAttributeMaxDynamicSharedMemorySize, SMEM2);
    cudaFuncSetAttribute(k_edge,   cudaFuncAttributeMaxDynamicSharedMemorySize, SMEM3);
    cudaFuncSetAttribute(k_node,   cudaFuncAttributeMaxDynamicSharedMemorySize, SMEM4);

    k_zero<<<256, 256>>>(N);
    k_prep<<<(N + 255) / 256, 256>>>(x, cw, N);
    k_radial<<<(E + TIL - 1) / TIL, 128, SMEM2>>>(x, attr, cw, row, col,
                                                  rad_w, rad_b, E);
    k_edge<<<(E + TIL - 1) / TIL, 128, SMEM3>>>(h, x, row, col,
                                                e_w1, e_b1, e_w2, e_b2,
                                                att_w, att_b,
                                                c_w1, c_b1, c_w2, c_b2, E);
    k_node<<<(N + TIL - 1) / TIL, 128, SMEM4>>>(h, x, n_w1, n_b1, n_w2, n_b2,
                                                ln_g, ln_b, (float*)d_out, N);
}

// round 2
// speedup vs baseline: 1.1797x; 1.1797x over previous
#include <cuda_runtime.h>

// Problem constants (fixed by the dataset)
#define NMAX 20000
#define EMAX 200000
#define C_   14
#define D_   3
#define A_   16
#define F_   128
#define TIL  32
#define PAD  36

// ---- scratch (device globals: no allocations allowed) ----
__device__ float g_radial[(size_t)EMAX * F_];   // [E,128]
__device__ float g_ef_sum[(size_t)NMAX * F_];   // per-col accumulation of ef
__device__ float g_x_acc [(size_t)NMAX * C_ * D_];
__device__ float g_cnt_row[NMAX];
__device__ float g_cnt_col[NMAX];
__device__ float g_pooled [NMAX * D_];          // masked channel-mean of x per node
__device__ int   g_csum   [NMAX];               // # valid channels per node

__device__ __forceinline__ float sigm_(float v) { return 1.f / (1.f + __expf(-v)); }
__device__ __forceinline__ float silu_(float v) { return v * sigm_(v); }

// ---- packed f32x2 helpers (sm_10x) ----
__device__ __forceinline__ unsigned long long pack2(float v) {
    unsigned long long r;
    asm("mov.b64 %0, {%1, %1};" : "=l"(r) : "f"(v));
    return r;
}
__device__ __forceinline__ void fma2(unsigned long long& acc,
                                     unsigned long long a, unsigned long long b) {
    asm("fma.rn.f32x2 %0, %1, %2, %0;" : "+l"(acc) : "l"(a), "l"(b));
}
__device__ __forceinline__ float2 unpack2(unsigned long long v) {
    float2 f;
    asm("mov.b64 {%0, %1}, %2;" : "=f"(f.x), "=f"(f.y) : "l"(v));
    return f;
}

// ---------------------------------------------------------------------------
// Register-blocked GEMM tile: 128 threads compute [32 edges x 128 outputs].
// Thread (jg = tid&31, eg = tid>>5) computes outputs jg*4..+3 for edges
// eg*8..+7. Inputs k-major in smem (in_s[k*PAD + m]); weights row-major
// W[k*128 + j] from global (coalesced LDG.128 across jg lanes).
// Inner loop: 2x LDS.128 (broadcast) + 1x LDG.128 + 4 packs + 16 fma.f32x2.
// ---------------------------------------------------------------------------
template<int K>
__device__ __forceinline__ void gemm_tile(const float* __restrict__ W,
                                          const float* __restrict__ in_s,
                                          int jg, int eg, float out[4][8])
{
    unsigned long long acc[4][4];
    #pragma unroll
    for (int a = 0; a < 4; ++a)
        #pragma unroll
        for (int p = 0; p < 4; ++p) acc[a][p] = 0ull;

    const float* wp  = W + jg * 4;
    const char*  ip0 = (const char*)(in_s + eg * 8);

    #pragma unroll 4
    for (int k = 0; k < K; ++k) {
        float4 w4 = *(const float4*)(wp + (size_t)k * F_);
        ulonglong2 ia = *(const ulonglong2*)(ip0 + (size_t)k * (PAD * 4));
        ulonglong2 ib = *(const ulonglong2*)(ip0 + (size_t)k * (PAD * 4) + 16);
        unsigned long long w0 = pack2(w4.x);
        unsigned long long w1 = pack2(w4.y);
        unsigned long long w2 = pack2(w4.z);
        unsigned long long w3 = pack2(w4.w);
        fma2(acc[0][0], ia.x, w0); fma2(acc[0][1], ia.y, w0);
        fma2(acc[0][2], ib.x, w0); fma2(acc[0][3], ib.y, w0);
        fma2(acc[1][0], ia.x, w1); fma2(acc[1][1], ia.y, w1);
        fma2(acc[1][2], ib.x, w1); fma2(acc[1][3], ib.y, w1);
        fma2(acc[2][0], ia.x, w2); fma2(acc[2][1], ia.y, w2);
        fma2(acc[2][2], ib.x, w2); fma2(acc[2][3], ib.y, w2);
        fma2(acc[3][0], ia.x, w3); fma2(acc[3][1], ia.y, w3);
        fma2(acc[3][2], ib.x, w3); fma2(acc[3][3], ib.y, w3);
    }
    #pragma unroll
    for (int a = 0; a < 4; ++a)
        #pragma unroll
        for (int p = 0; p < 4; ++p) {
            float2 f = unpack2(acc[a][p]);
            out[a][p * 2 + 0] = f.x;
            out[a][p * 2 + 1] = f.y;
        }
}

// ---------------------------------------------------------------------------
// K0: zero the accumulators (must happen every launch - graph replays)
// ---------------------------------------------------------------------------
__global__ void k_zero(int n_nodes) {
    int t0 = n_nodes * F_;
    int t1 = t0 + n_nodes * C_ * D_;
    int t2 = t1 + n_nodes;
    int t3 = t2 + n_nodes;
    for (int i = blockIdx.x * blockDim.x + threadIdx.x; i < t3;
         i += gridDim.x * blockDim.x) {
        if (i < t0)       g_ef_sum[i] = 0.f;
        else if (i < t1)  g_x_acc[i - t0] = 0.f;
        else if (i < t2)  g_cnt_row[i - t1] = 0.f;
        else              g_cnt_col[i - t2] = 0.f;
    }
}

// ---------------------------------------------------------------------------
// K1: per-node prep: channel_sum + masked channel-mean of x
// ---------------------------------------------------------------------------
__global__ void k_prep(const float* __restrict__ x, const float* __restrict__ cw,
                       int N) {
    int n = blockIdx.x * blockDim.x + threadIdx.x;
    if (n >= N) return;
    int s = 0;
    float px = 0.f, py = 0.f, pz = 0.f;
    #pragma unroll
    for (int i = 0; i < C_; ++i) {
        float w = cw[n * C_ + i];
        if (w != 0.f) {
            s++;
            px += x[n * C_ * D_ + i * 3 + 0];
            py += x[n * C_ * D_ + i * 3 + 1];
            pz += x[n * C_ * D_ + i * 3 + 2];
        }
    }
    g_csum[n] = s;
    float inv = 1.f / (float)(s > 0 ? s : 1);
    g_pooled[n * 3 + 0] = px * inv;
    g_pooled[n * 3 + 1] = py * inv;
    g_pooled[n * 3 + 2] = pz * inv;
}

// ---------------------------------------------------------------------------
// K2: per-edge radial feature: einsum prologue + GEMM 256->128 / (||R||+1)
// ---------------------------------------------------------------------------
__global__ __launch_bounds__(128) void k_radial(
    const float* __restrict__ x, const float* __restrict__ attr,
    const float* __restrict__ cw, const int* __restrict__ row,
    const int* __restrict__ col, const float* __restrict__ rad_w,
    const float* __restrict__ rad_b, int E)
{
    extern __shared__ float sm[];
    float* in_s     = sm;                 // [256][PAD]  (R flattened, k-major)
    float* wsc      = sm + 256 * PAD;     // 4 warps * 1024
    float* inv_norm = wsc + 4 * 1024;     // [32]

    int tid = threadIdx.x, lane = tid & 31, wp = tid >> 5;
    int e0 = blockIdx.x * TIL;

    float* W     = wsc + wp * 1024;
    float* s_xr  = W;           // 42
    float* s_xc  = W + 48;      // 42
    float* s_cwr = W + 96;      // 14
    float* s_cwc = W + 112;     // 14
    float* s_ar  = W + 128;     // 224
    float* s_ac  = W + 352;     // 224
    float* s_msg = W + 576;     // 196
    float* s_T   = W + 772;     // 224

    for (int it = 0; it < 8; ++it) {
        int m = it * 4 + wp;
        int e = e0 + m;
        int r = 0, c = 0;
        if (e < E) { r = row[e]; c = col[e]; }
        for (int i = lane; i < 42; i += 32) {
            s_xr[i] = x[r * 42 + i];
            s_xc[i] = x[c * 42 + i];
        }
        for (int i = lane; i < 14; i += 32) {
            s_cwr[i] = cw[r * C_ + i];
            s_cwc[i] = cw[c * C_ + i];
        }
        for (int i = lane; i < 224; i += 32) {
            s_ar[i] = attr[r * 224 + i];
            s_ac[i] = attr[c * 224 + i];
        }
        __syncwarp();
        for (int i = lane; i < 196; i += 32) {
            int ci = i / 14, cj = i - ci * 14;
            float dx = s_xr[ci * 3 + 0] - s_xc[cj * 3 + 0];
            float dy = s_xr[ci * 3 + 1] - s_xc[cj * 3 + 1];
            float dz = s_xr[ci * 3 + 2] - s_xc[cj * 3 + 2];
            s_msg[i] = sqrtf(dx * dx + dy * dy + dz * dz) * s_cwr[ci] * s_cwc[cj];
        }
        __syncwarp();
        for (int i = lane; i < 224; i += 32) {
            int ci = i >> 4, b = i & 15;
            float t = 0.f;
            #pragma unroll
            for (int jj = 0; jj < C_; ++jj) t += s_msg[ci * 14 + jj] * s_ac[jj * 16 + b];
            s_T[i] = t;
        }
        __syncwarp();
        float ss = 0.f;
        for (int i = lane; i < 256; i += 32) {
            int a = i >> 4, b = i & 15;
            float t = 0.f;
            #pragma unroll
            for (int jj = 0; jj < C_; ++jj) t += s_ar[jj * 16 + a] * s_T[jj * 16 + b];
            in_s[i * PAD + m] = t;
            ss += t * t;
        }
        #pragma unroll
        for (int o = 16; o; o >>= 1) ss += __shfl_xor_sync(0xffffffffu, ss, o);
        if (lane == 0) inv_norm[m] = 1.f / (sqrtf(ss) + 1.f);
        __syncwarp();
    }
    __syncthreads();

    int jg = tid & 31, eg = tid >> 5;
    float out[4][8];
    gemm_tile<256>(rad_w, in_s, jg, eg, out);
    float4 b4 = *(const float4*)(rad_b + jg * 4);
    #pragma unroll
    for (int e = 0; e < 8; ++e) {
        int m = eg * 8 + e;
        int ee = e0 + m;
        if (ee < E) {
            float inv = inv_norm[m];
            float4 o;
            o.x = (out[0][e] + b4.x) * inv;
            o.y = (out[1][e] + b4.y) * inv;
            o.z = (out[2][e] + b4.z) * inv;
            o.w = (out[3][e] + b4.w) * inv;
            *(float4*)(g_radial + (size_t)ee * F_ + jg * 4) = o;
        }
    }
}

// ---------------------------------------------------------------------------
// K3: fused edge kernel
// ---------------------------------------------------------------------------
__global__ __launch_bounds__(128) void k_edge(
    const float* __restrict__ h, const float* __restrict__ x,
    const int* __restrict__ row, const int* __restrict__ col,
    const float* __restrict__ e_w1, const float* __restrict__ e_b1,
    const float* __restrict__ e_w2, const float* __restrict__ e_b2,
    const float* __restrict__ att_w, const float* __restrict__ att_b,
    const float* __restrict__ c_w1, const float* __restrict__ c_b1,
    const float* __restrict__ c_w2, const float* __restrict__ c_b2,
    int E)
{
    extern __shared__ float sm[];
    float* in_s   = sm;                    // [384][PAD]
    float* t1_s   = in_s + 384 * PAD;      // [128][PAD]
    float* cm_s   = t1_s + 128 * PAD;      // [32][16]
    int*   s_row  = (int*)(cm_s + 32 * 16);
    int*   s_col  = s_row + 32;
    int*   s_cs   = s_col + 32;

    int tid = threadIdx.x;
    int e0 = blockIdx.x * TIL;
    if (tid < TIL) {
        int e = e0 + tid;
        int r = 0, c = 0;
        if (e < E) { r = row[e]; c = col[e]; }
        s_row[tid] = r;
        s_col[tid] = c;
        s_cs[tid]  = g_csum[r];
    }
    __syncthreads();

    // gather: in = [h[row] | h[col] | radial]
    for (int m = 0; m < TIL; ++m) {
        int r = s_row[m], c = s_col[m];
        int e = e0 + m;
        in_s[tid * PAD + m]         = h[(size_t)r * F_ + tid];
        in_s[(128 + tid) * PAD + m] = h[(size_t)c * F_ + tid];
        in_s[(256 + tid) * PAD + m] = (e < E) ? g_radial[(size_t)e * F_ + tid] : 0.f;
    }
    __syncthreads();

    int jg = tid & 31, eg = tid >> 5;
    float t2[4][8];

    // GEMM1: 384 -> 128, silu -> t1_s
    gemm_tile<384>(e_w1, in_s, jg, eg, t2);
    {
        float4 b4 = *(const float4*)(e_b1 + jg * 4);
        float bb[4] = {b4.x, b4.y, b4.z, b4.w};
        #pragma unroll
        for (int a = 0; a < 4; ++a)
            #pragma unroll
            for (int e = 0; e < 8; ++e)
                t1_s[(jg * 4 + a) * PAD + eg * 8 + e] = silu_(t2[a][e] + bb[a]);
    }
    __syncthreads();

    // GEMM2: 128 -> 128, silu
    gemm_tile<128>(e_w2, t1_s, jg, eg, t2);
    {
        float4 b4 = *(const float4*)(e_b2 + jg * 4);
        float bb[4] = {b4.x, b4.y, b4.z, b4.w};
        #pragma unroll
        for (int a = 0; a < 4; ++a)
            #pragma unroll
            for (int e = 0; e < 8; ++e)
                t2[a][e] = silu_(t2[a][e] + bb[a]);
    }

    // attention gate: warp-level (warp owns all 128 features of its 8 edges)
    {
        float4 aw = *(const float4*)(att_w + jg * 4);
        float part[8];
        #pragma unroll
        for (int e = 0; e < 8; ++e)
            part[e] = t2[0][e] * aw.x + t2[1][e] * aw.y +
                      t2[2][e] * aw.z + t2[3][e] * aw.w;
        #pragma unroll
        for (int o = 16; o; o >>= 1)
            #pragma unroll
            for (int e = 0; e < 8; ++e)
                part[e] += __shfl_xor_sync(0xffffffffu, part[e], o);
        float ab = att_b[0];
        #pragma unroll
        for (int e = 0; e < 8; ++e) {
            float g = sigm_(part[e] + ab);
            #pragma unroll
            for (int a = 0; a < 4; ++a) t2[a][e] *= g;   // ef
        }
    }

    // stage ef into in_s (free after GEMM1) + scatter to per-col sums
    #pragma unroll
    for (int a = 0; a < 4; ++a)
        #pragma unroll
        for (int e = 0; e < 8; ++e)
            in_s[(jg * 4 + a) * PAD + eg * 8 + e] = t2[a][e];
    #pragma unroll
    for (int e = 0; e < 8; ++e) {
        int m = eg * 8 + e;
        if (e0 + m < E) {
            float* dst = g_ef_sum + (size_t)s_col[m] * F_ + jg * 4;
            atomicAdd(dst + 0, t2[0][e]);
            atomicAdd(dst + 1, t2[1][e]);
            atomicAdd(dst + 2, t2[2][e]);
            atomicAdd(dst + 3, t2[3][e]);
        }
    }
    if (tid < TIL && e0 + tid < E) {
        atomicAdd(&g_cnt_col[s_col[tid]], 1.f);
        atomicAdd(&g_cnt_row[s_row[tid]], 1.f);
    }
    __syncthreads();

    // GEMM3: ef (128) -> 128, silu -> t1_s (cmh)
    gemm_tile<128>(c_w1, in_s, jg, eg, t2);
    {
        float4 b4 = *(const float4*)(c_b1 + jg * 4);
        float bb[4] = {b4.x, b4.y, b4.z, b4.w};
        #pragma unroll
        for (int a = 0; a < 4; ++a)
            #pragma unroll
            for (int e = 0; e < 8; ++e)
                t1_s[(jg * 4 + a) * PAD + eg * 8 + e] = silu_(t2[a][e] + bb[a]);
    }
    __syncthreads();

    // c_w2: 128 -> 14 per edge
    for (int it = 0; it < 4; ++it) {
        int idx = it * 128 + tid;
        if (idx < TIL * C_) {
            int m = idx & 31, o = idx >> 5;
            float s = c_b2[o];
            #pragma unroll 4
            for (int k = 0; k < 128; ++k) s += t1_s[k * PAD + m] * c_w2[k * C_ + o];
            cm_s[m * 16 + o] = s;
        }
    }
    __syncthreads();

    // RollerPooling + trans scatter
    for (int idx = tid; idx < TIL * 42; idx += 128) {
        int m = idx / 42, rem = idx - m * 42;
        int e = e0 + m;
        if (e < E) {
            int i = rem / 3;
            int d = rem - i * 3;
            int ws = (C_ + 1) - s_cs[m];
            if (ws < 1)  ws = 1;
            if (ws > C_) ws = C_;
            int end = i + ws;
            if (end > C_) end = C_;
            float ps = 0.f;
            for (int q = i; q < end; ++q) ps += cm_s[m * 16 + q];
            float pooled = ps / (float)ws;
            float cd = x[(size_t)s_row[m] * 42 + rem] - g_pooled[s_col[m] * 3 + d];
            atomicAdd(&g_x_acc[(size_t)s_row[m] * 42 + rem], cd * pooled);
        }
    }
}

// ---------------------------------------------------------------------------
// K4: node update: agg mean -> node MLP -> residual -> LayerNorm, plus x_new
// ---------------------------------------------------------------------------
__global__ __launch_bounds__(128) void k_node(
    const float* __restrict__ h, const float* __restrict__ x,
    const float* __restrict__ n_w1, const float* __restrict__ n_b1,
    const float* __restrict__ n_w2, const float* __restrict__ n_b2,
    const float* __restrict__ ln_g, const float* __restrict__ ln_b,
    float* __restrict__ out, int N)
{
    extern __shared__ float sm[];
    float* in_s = sm;                  // [256][PAD]
    float* t1_s = in_s + 256 * PAD;    // [128][PAD]
    float* ic_s = t1_s + 128 * PAD;    // [32]

    int tid = threadIdx.x;
    int n0 = blockIdx.x * TIL;

    if (tid < TIL) {
        int n = n0 + tid;
        float c = (n < N) ? g_cnt_col[n] : 1.f;
        ic_s[tid] = 1.f / fmaxf(c, 1.f);
    }
    __syncthreads();

    for (int m = 0; m < TIL; ++m) {
        int n = n0 + m;
        if (n >= N) n = N - 1;
        in_s[tid * PAD + m]         = h[(size_t)n * F_ + tid];
        in_s[(128 + tid) * PAD + m] = g_ef_sum[(size_t)n * F_ + tid] * ic_s[m];
    }
    __syncthreads();

    int jg = tid & 31, eg = tid >> 5;
    float t2[4][8];

    // GEMM1: 256 -> 128, silu -> t1_s
    gemm_tile<256>(n_w1, in_s, jg, eg, t2);
    {
        float4 b4 = *(const float4*)(n_b1 + jg * 4);
        float bb[4] = {b4.x, b4.y, b4.z, b4.w};
        #pragma unroll
        for (int a = 0; a < 4; ++a)
            #pragma unroll
            for (int e = 0; e < 8; ++e)
                t1_s[(jg * 4 + a) * PAD + eg * 8 + e] = silu_(t2[a][e] + bb[a]);
    }
    __syncthreads();

    // GEMM2: 128 -> 128, + residual h
    gemm_tile<128>(n_w2, t1_s, jg, eg, t2);
    float hr[4][8];
    {
        float4 b4 = *(const float4*)(n_b2 + jg * 4);
        float bb[4] = {b4.x, b4.y, b4.z, b4.w};
        #pragma unroll
        for (int a = 0; a < 4; ++a)
            #pragma unroll
            for (int e = 0; e < 8; ++e)
                hr[a][e] = in_s[(jg * 4 + a) * PAD + eg * 8 + e] + t2[a][e] + bb[a];
    }

    // LayerNorm per warp (warp owns all 128 features of its 8 nodes)
    float s1[8], s2[8];
    #pragma unroll
    for (int e = 0; e < 8; ++e) {
        s1[e] = hr[0][e] + hr[1][e] + hr[2][e] + hr[3][e];
        s2[e] = hr[0][e] * hr[0][e] + hr[1][e] * hr[1][e] +
                hr[2][e] * hr[2][e] + hr[3][e] * hr[3][e];
    }
    #pragma unroll
    for (int o = 16; o; o >>= 1)
        #pragma unroll
        for (int e = 0; e < 8; ++e) {
            s1[e] += __shfl_xor_sync(0xffffffffu, s1[e], o);
            s2[e] += __shfl_xor_sync(0xffffffffu, s2[e], o);
        }

    {
        float4 g4 = *(const float4*)(ln_g + jg * 4);
        float4 bb4 = *(const float4*)(ln_b + jg * 4);
        #pragma unroll
        for (int e = 0; e < 8; ++e) {
            int n = n0 + eg * 8 + e;
            if (n < N) {
                float mu = s1[e] * (1.f / 128.f);
                float var = fmaxf(s2[e] * (1.f / 128.f) - mu * mu, 0.f);
                float rs = rsqrtf(var + 1e-5f);
                float4 o;
                o.x = (hr[0][e] - mu) * rs * g4.x + bb4.x;
                o.y = (hr[1][e] - mu) * rs * g4.y + bb4.y;
                o.z = (hr[2][e] - mu) * rs * g4.z + bb4.z;
                o.w = (hr[3][e] - mu) * rs * g4.w + bb4.w;
                *(float4*)(out + (size_t)n * F_ + jg * 4) = o;
            }
        }
    }

    // x_new = x + x_acc / max(cnt_row, 1)
    float* out_x = out + (size_t)N * F_;
    for (int idx = tid; idx < TIL * 42; idx += 128) {
        int m = idx / 42, rem = idx - m * 42;
        int n = n0 + m;
        if (n < N) {
            out_x[(size_t)n * 42 + rem] =
                x[(size_t)n * 42 + rem] +
                g_x_acc[(size_t)n * 42 + rem] / fmaxf(g_cnt_row[n], 1.f);
        }
    }
}

// ---------------------------------------------------------------------------
// launch
// ---------------------------------------------------------------------------
extern "C" void kernel_launch(void* const* d_in, const int* in_sizes, int n_in,
                              void* d_out, int out_size) {
    const float* h     = (const float*)d_in[0];
    const float* x     = (const float*)d_in[1];
    const float* attr  = (const float*)d_in[2];
    const float* cw    = (const float*)d_in[3];
    const int*   row   = (const int*)d_in[4];
    const int*   col   = (const int*)d_in[5];
    const float* rad_w = (const float*)d_in[6];
    const float* rad_b = (const float*)d_in[7];
    const float* e_w1  = (const float*)d_in[8];
    const float* e_b1  = (const float*)d_in[9];
    const float* e_w2  = (const float*)d_in[10];
    const float* e_b2  = (const float*)d_in[11];
    const float* att_w = (const float*)d_in[12];
    const float* att_b = (const float*)d_in[13];
    const float* c_w1  = (const float*)d_in[14];
    const float* c_b1  = (const float*)d_in[15];
    const float* c_w2  = (const float*)d_in[16];
    const float* c_b2  = (const float*)d_in[17];
    const float* n_w1  = (const float*)d_in[18];
    const float* n_b1  = (const float*)d_in[19];
    const float* n_w2  = (const float*)d_in[20];
    const float* n_b2  = (const float*)d_in[21];
    const float* ln_g  = (const float*)d_in[22];
    const float* ln_b  = (const float*)d_in[23];

    int N = in_sizes[0] / F_;
    int E = in_sizes[4];

    const int SMEM2 = (256 * PAD + 4 * 1024 + 32) * 4;
    const int SMEM3 = (384 * PAD + 128 * PAD + 32 * 16) * 4 + 3 * 32 * 4;
    const int SMEM4 = (256 * PAD + 128 * PAD + 32) * 4;

    cudaFuncSetAttribute(k_radial, cudaFuncAttributeMaxDynamicSharedMemorySize, SMEM2);
    cudaFuncSetAttribute(k_edge,   cudaFuncAttributeMaxDynamicSharedMemorySize, SMEM3);
    cudaFuncSetAttribute(k_node,   cudaFuncAttributeMaxDynamicSharedMemorySize, SMEM4);

    k_zero<<<256, 256>>>(N);
    k_prep<<<(N + 255) / 256, 256>>>(x, cw, N);
    k_radial<<<(E + TIL - 1) / TIL, 128, SMEM2>>>(x, attr, cw, row, col,
                                                  rad_w, rad_b, E);
    k_edge<<<(E + TIL - 1) / TIL, 128, SMEM3>>>(h, x, row, col,
                                                e_w1, e_b1, e_w2, e_b2,
                                                att_w, att_b,
                                                c_w1, c_b1, c_w2, c_b2, E);
    k_node<<<(N + TIL - 1) / TIL, 128, SMEM4>>>(h, x, n_w1, n_b1, n_w2, n_b2,
                                                ln_g, ln_b, (float*)d_out, N);
}

// round 3
// speedup vs baseline: 1.5214x; 1.2897x over previous
#include <cuda_runtime.h>

// Problem constants (fixed by the dataset)
#define NMAX 20000
#define EMAX 200000
#define C_   14
#define D_   3
#define A_   16
#define F_   128
#define TIL  32

typedef unsigned long long ull;

// ---- scratch (device globals: no allocations allowed) ----
// g_rad is stored pair-interleaved per 32-edge block:
//   g_rad[blk*4096 + p*256 + 2*k + s]  = radial[edge 2p+s of block][k]
__device__ float g_rad  [(size_t)EMAX * F_];
__device__ float g_ef_sum[(size_t)NMAX * F_];
__device__ float g_x_acc [(size_t)NMAX * C_ * D_];
__device__ float g_cnt_row[NMAX];
__device__ float g_cnt_col[NMAX];
__device__ float g_pooled [NMAX * D_];
__device__ int   g_csum   [NMAX];

__device__ __forceinline__ float sigm_(float v) { return 1.f / (1.f + __expf(-v)); }
__device__ __forceinline__ float silu_(float v) { return v * sigm_(v); }

// ---- packed f32x2 helpers (sm_10x) ----
__device__ __forceinline__ ull pack2(float v) {
    ull r;
    asm("mov.b64 %0, {%1, %1};" : "=l"(r) : "f"(v));
    return r;
}
__device__ __forceinline__ void fma2(ull& acc, ull a, ull b) {
    asm("fma.rn.f32x2 %0, %1, %2, %0;" : "+l"(acc) : "l"(a), "l"(b));
}
__device__ __forceinline__ float2 unpack2(ull v) {
    float2 f;
    asm("mov.b64 {%0, %1}, %2;" : "=f"(f.x), "=f"(f.y) : "l"(v));
    return f;
}

// ---------------------------------------------------------------------------
// Pair-interleaved GEMM accumulate.
// base points at this warp's 4 pair-rows (pairs eg*4..eg*4+3), stride S floats.
// acc[a][q] is an f32x2 accumulator: (.x = edge 2*(eg*4+q), .y = edge +1),
// output feature j = jg*4 + a.  W is row-major [K][128].
// Inner loop/k: 1 LDG.128 + 4 packs + 4 LDS.64 + 16 fma.f32x2.
// ---------------------------------------------------------------------------
template<int K, int S>
__device__ __forceinline__ void gemm_acc(const float* __restrict__ W,
                                         const float* __restrict__ base,
                                         int jg, ull acc[4][4])
{
    const float* wp = W + jg * 4;
    #pragma unroll 4
    for (int k = 0; k < K; ++k) {
        float4 w4 = *(const float4*)(wp + (size_t)k * F_);
        ull i0 = *(const ull*)(base + 0 * S + 2 * k);
        ull i1 = *(const ull*)(base + 1 * S + 2 * k);
        ull i2 = *(const ull*)(base + 2 * S + 2 * k);
        ull i3 = *(const ull*)(base + 3 * S + 2 * k);
        ull w0 = pack2(w4.x), w1 = pack2(w4.y), w2 = pack2(w4.z), w3 = pack2(w4.w);
        fma2(acc[0][0], i0, w0); fma2(acc[0][1], i1, w0);
        fma2(acc[0][2], i2, w0); fma2(acc[0][3], i3, w0);
        fma2(acc[1][0], i0, w1); fma2(acc[1][1], i1, w1);
        fma2(acc[1][2], i2, w1); fma2(acc[1][3], i3, w1);
        fma2(acc[2][0], i0, w2); fma2(acc[2][1], i1, w2);
        fma2(acc[2][2], i2, w2); fma2(acc[2][3], i3, w2);
        fma2(acc[3][0], i0, w3); fma2(acc[3][1], i1, w3);
        fma2(acc[3][2], i2, w3); fma2(acc[3][3], i3, w3);
    }
}

__device__ __forceinline__ void zero_acc(ull acc[4][4]) {
    #pragma unroll
    for (int a = 0; a < 4; ++a)
        #pragma unroll
        for (int q = 0; q < 4; ++q) acc[a][q] = 0ull;
}

// stage 128 contiguous floats from two global rows into one interleaved
// pair-row (dst = buf + pair*S [+offset]); one warp, conflict-free float4s.
__device__ __forceinline__ void stage2(float* dst, const float* __restrict__ s0,
                                       const float* __restrict__ s1, int lane)
{
    float4 a = *(const float4*)(s0 + lane * 4);
    float4 b = *(const float4*)(s1 + lane * 4);
    *(float4*)(dst + lane * 8)     = make_float4(a.x, b.x, a.y, b.y);
    *(float4*)(dst + lane * 8 + 4) = make_float4(a.z, b.z, a.w, b.w);
}

// ---------------------------------------------------------------------------
// K0: zero accumulators (graph replays -> must re-zero every launch)
// ---------------------------------------------------------------------------
__global__ void k_zero(int n_nodes) {
    int t0 = n_nodes * F_;
    int t1 = t0 + n_nodes * C_ * D_;
    int t2 = t1 + n_nodes;
    int t3 = t2 + n_nodes;
    for (int i = blockIdx.x * blockDim.x + threadIdx.x; i < t3;
         i += gridDim.x * blockDim.x) {
        if (i < t0)       g_ef_sum[i] = 0.f;
        else if (i < t1)  g_x_acc[i - t0] = 0.f;
        else if (i < t2)  g_cnt_row[i - t1] = 0.f;
        else              g_cnt_col[i - t2] = 0.f;
    }
}

// ---------------------------------------------------------------------------
// K1: per-node prep
// ---------------------------------------------------------------------------
__global__ void k_prep(const float* __restrict__ x, const float* __restrict__ cw,
                       int N) {
    int n = blockIdx.x * blockDim.x + threadIdx.x;
    if (n >= N) return;
    int s = 0;
    float px = 0.f, py = 0.f, pz = 0.f;
    #pragma unroll
    for (int i = 0; i < C_; ++i) {
        float w = cw[n * C_ + i];
        if (w != 0.f) {
            s++;
            px += x[n * C_ * D_ + i * 3 + 0];
            py += x[n * C_ * D_ + i * 3 + 1];
            pz += x[n * C_ * D_ + i * 3 + 2];
        }
    }
    g_csum[n] = s;
    float inv = 1.f / (float)(s > 0 ? s : 1);
    g_pooled[n * 3 + 0] = px * inv;
    g_pooled[n * 3 + 1] = py * inv;
    g_pooled[n * 3 + 2] = pz * inv;
}

// ---------------------------------------------------------------------------
// K2: per-edge radial: einsum prologue + GEMM 256->128, scaled by 1/(||R||+1)
// in_s pair-interleaved [16][516]
// ---------------------------------------------------------------------------
#define SR 516
__global__ __launch_bounds__(128) void k_radial(
    const float* __restrict__ x, const float* __restrict__ attr,
    const float* __restrict__ cw, const int* __restrict__ row,
    const int* __restrict__ col, const float* __restrict__ rad_w,
    const float* __restrict__ rad_b, int E)
{
    extern __shared__ float sm[];
    float* in_s     = sm;                 // 16*516
    float* wsc      = sm + 16 * SR;       // 4 warps * 1024
    float* inv_norm = wsc + 4 * 1024;     // [32]

    int tid = threadIdx.x, lane = tid & 31, wp = tid >> 5;
    int e0 = blockIdx.x * TIL;

    float* W     = wsc + wp * 1024;
    float* s_xr  = W;
    float* s_xc  = W + 48;
    float* s_cwr = W + 96;
    float* s_cwc = W + 112;
    float* s_ar  = W + 128;
    float* s_ac  = W + 352;
    float* s_msg = W + 576;
    float* s_T   = W + 772;

    for (int it = 0; it < 8; ++it) {
        int m = it * 4 + wp;
        int e = e0 + m;
        if (e >= E) e = E - 1;
        int r = row[e], c = col[e];
        for (int i = lane; i < 42; i += 32) {
            s_xr[i] = x[r * 42 + i];
            s_xc[i] = x[c * 42 + i];
        }
        for (int i = lane; i < 14; i += 32) {
            s_cwr[i] = cw[r * C_ + i];
            s_cwc[i] = cw[c * C_ + i];
        }
        for (int i = lane; i < 224; i += 32) {
            s_ar[i] = attr[r * 224 + i];
            s_ac[i] = attr[c * 224 + i];
        }
        __syncwarp();
        for (int i = lane; i < 196; i += 32) {
            int ci = i / 14, cj = i - ci * 14;
            float dx = s_xr[ci * 3 + 0] - s_xc[cj * 3 + 0];
            float dy = s_xr[ci * 3 + 1] - s_xc[cj * 3 + 1];
            float dz = s_xr[ci * 3 + 2] - s_xc[cj * 3 + 2];
            s_msg[i] = sqrtf(dx * dx + dy * dy + dz * dz) * s_cwr[ci] * s_cwc[cj];
        }
        __syncwarp();
        for (int i = lane; i < 224; i += 32) {
            int ci = i >> 4, b = i & 15;
            float t = 0.f;
            #pragma unroll
            for (int jj = 0; jj < C_; ++jj) t += s_msg[ci * 14 + jj] * s_ac[jj * 16 + b];
            s_T[i] = t;
        }
        __syncwarp();
        float ss = 0.f;
        for (int i = lane; i < 256; i += 32) {
            int a = i >> 4, b = i & 15;
            float t = 0.f;
            #pragma unroll
            for (int jj = 0; jj < C_; ++jj) t += s_ar[jj * 16 + a] * s_T[jj * 16 + b];
            in_s[(m >> 1) * SR + 2 * i + (m & 1)] = t;
            ss += t * t;
        }
        #pragma unroll
        for (int o = 16; o; o >>= 1) ss += __shfl_xor_sync(0xffffffffu, ss, o);
        if (lane == 0) inv_norm[m] = 1.f / (sqrtf(ss) + 1.f);
        __syncwarp();
    }
    __syncthreads();

    int jg = lane, eg = tid >> 5;
    ull acc[4][4];
    zero_acc(acc);
    gemm_acc<256, SR>(rad_w, in_s + eg * 4 * SR, jg, acc);

    float4 b4 = *(const float4*)(rad_b + jg * 4);
    float bb[4] = {b4.x, b4.y, b4.z, b4.w};
    float* outb = g_rad + (size_t)blockIdx.x * 4096;
    #pragma unroll
    for (int q = 0; q < 4; ++q) {
        int P = eg * 4 + q;
        float n0 = inv_norm[2 * P], n1 = inv_norm[2 * P + 1];
        #pragma unroll
        for (int a = 0; a < 4; ++a) {
            float2 f = unpack2(acc[a][q]);
            *(float2*)(outb + P * 256 + 2 * (jg * 4 + a)) =
                make_float2((f.x + bb[a]) * n0, (f.y + bb[a]) * n1);
        }
    }
}

// ---------------------------------------------------------------------------
// K3: fused edge kernel; double-buffered 128-k chunks, pair-interleaved.
// ---------------------------------------------------------------------------
#define SE 260
__global__ __launch_bounds__(128) void k_edge(
    const float* __restrict__ h, const float* __restrict__ x,
    const int* __restrict__ row, const int* __restrict__ col,
    const float* __restrict__ e_w1, const float* __restrict__ e_b1,
    const float* __restrict__ e_w2, const float* __restrict__ e_b2,
    const float* __restrict__ att_w, const float* __restrict__ att_b,
    const float* __restrict__ c_w1, const float* __restrict__ c_b1,
    const float* __restrict__ c_w2, const float* __restrict__ c_b2,
    int E)
{
    extern __shared__ float sm[];
    float* bufA  = sm;                    // 16*260
    float* bufB  = bufA + 16 * SE;        // 16*260
    float* cm_s  = bufB + 16 * SE;        // 32*16
    int*   s_row = (int*)(cm_s + 512);
    int*   s_col = s_row + 32;
    int*   s_cs  = s_col + 32;

    int tid = threadIdx.x, lane = tid & 31, eg = tid >> 5, jg = lane;
    int e0 = blockIdx.x * TIL;

    if (tid < TIL) {
        int e = e0 + tid;
        if (e >= E) e = E - 1;
        int r = row[e];
        s_row[tid] = r;
        s_col[tid] = col[e];
        s_cs[tid]  = g_csum[r];
    }
    __syncthreads();

    // stage h[row] -> A
    #pragma unroll
    for (int pp = 0; pp < 4; ++pp) {
        int p = eg + pp * 4;
        stage2(bufA + p * SE, h + (size_t)s_row[2 * p] * F_,
               h + (size_t)s_row[2 * p + 1] * F_, lane);
    }
    __syncthreads();

    ull acc[4][4];
    zero_acc(acc);

    // stage h[col] -> B, compute chunk0 from A
    #pragma unroll
    for (int pp = 0; pp < 4; ++pp) {
        int p = eg + pp * 4;
        stage2(bufB + p * SE, h + (size_t)s_col[2 * p] * F_,
               h + (size_t)s_col[2 * p + 1] * F_, lane);
    }
    gemm_acc<128, SE>(e_w1, bufA + eg * 4 * SE, jg, acc);
    __syncthreads();

    // stage radial -> A (straight copy, already pair-interleaved), chunk1 from B
    {
        const float* src = g_rad + (size_t)blockIdx.x * 4096;
        #pragma unroll
        for (int pp = 0; pp < 4; ++pp) {
            int p = eg + pp * 4;
            *(float4*)(bufA + p * SE + lane * 8) =
                *(const float4*)(src + p * 256 + lane * 8);
            *(float4*)(bufA + p * SE + lane * 8 + 4) =
                *(const float4*)(src + p * 256 + lane * 8 + 4);
        }
    }
    gemm_acc<128, SE>(e_w1 + 128 * F_, bufB + eg * 4 * SE, jg, acc);
    __syncthreads();

    gemm_acc<128, SE>(e_w1 + 256 * F_, bufA + eg * 4 * SE, jg, acc);

    // t1 = silu(acc + b1) -> B
    {
        float4 b4 = *(const float4*)(e_b1 + jg * 4);
        float bb[4] = {b4.x, b4.y, b4.z, b4.w};
        #pragma unroll
        for (int a = 0; a < 4; ++a)
            #pragma unroll
            for (int q = 0; q < 4; ++q) {
                float2 f = unpack2(acc[a][q]);
                *(float2*)(bufB + (eg * 4 + q) * SE + 2 * (jg * 4 + a)) =
                    make_float2(silu_(f.x + bb[a]), silu_(f.y + bb[a]));
            }
    }
    __syncthreads();

    // GEMM2: 128 -> 128 from B
    zero_acc(acc);
    gemm_acc<128, SE>(e_w2, bufB + eg * 4 * SE, jg, acc);

    float tx[4][4], ty[4][4];
    {
        float4 b4 = *(const float4*)(e_b2 + jg * 4);
        float bb[4] = {b4.x, b4.y, b4.z, b4.w};
        #pragma unroll
        for (int a = 0; a < 4; ++a)
            #pragma unroll
            for (int q = 0; q < 4; ++q) {
                float2 f = unpack2(acc[a][q]);
                tx[a][q] = silu_(f.x + bb[a]);
                ty[a][q] = silu_(f.y + bb[a]);
            }
    }

    // attention gate (warp owns all 128 features of its 8 edges)
    {
        float4 aw = *(const float4*)(att_w + jg * 4);
        float awv[4] = {aw.x, aw.y, aw.z, aw.w};
        float px[4], py[4];
        #pragma unroll
        for (int q = 0; q < 4; ++q) {
            px[q] = tx[0][q] * awv[0] + tx[1][q] * awv[1] +
                    tx[2][q] * awv[2] + tx[3][q] * awv[3];
            py[q] = ty[0][q] * awv[0] + ty[1][q] * awv[1] +
                    ty[2][q] * awv[2] + ty[3][q] * awv[3];
        }
        #pragma unroll
        for (int o = 16; o; o >>= 1)
            #pragma unroll
            for (int q = 0; q < 4; ++q) {
                px[q] += __shfl_xor_sync(0xffffffffu, px[q], o);
                py[q] += __shfl_xor_sync(0xffffffffu, py[q], o);
            }
        float ab = att_b[0];
        #pragma unroll
        for (int q = 0; q < 4; ++q) {
            float gx = sigm_(px[q] + ab);
            float gy = sigm_(py[q] + ab);
            #pragma unroll
            for (int a = 0; a < 4; ++a) { tx[a][q] *= gx; ty[a][q] *= gy; }
        }
    }

    // ef -> A (for GEMM3) + atomic scatter into per-col sums
    #pragma unroll
    for (int a = 0; a < 4; ++a)
        #pragma unroll
        for (int q = 0; q < 4; ++q)
            *(float2*)(bufA + (eg * 4 + q) * SE + 2 * (jg * 4 + a)) =
                make_float2(tx[a][q], ty[a][q]);
    #pragma unroll
    for (int q = 0; q < 4; ++q) {
        int m0 = eg * 8 + 2 * q;
        if (e0 + m0 < E) {
            float* d0 = g_ef_sum + (size_t)s_col[m0] * F_ + jg * 4;
            #pragma unroll
            for (int a = 0; a < 4; ++a) atomicAdd(d0 + a, tx[a][q]);
        }
        if (e0 + m0 + 1 < E) {
            float* d1 = g_ef_sum + (size_t)s_col[m0 + 1] * F_ + jg * 4;
            #pragma unroll
            for (int a = 0; a < 4; ++a) atomicAdd(d1 + a, ty[a][q]);
        }
    }
    if (tid < TIL && e0 + tid < E) {
        atomicAdd(&g_cnt_col[s_col[tid]], 1.f);
        atomicAdd(&g_cnt_row[s_row[tid]], 1.f);
    }
    __syncthreads();

    // GEMM3: c_w1 from A -> cmh -> B
    zero_acc(acc);
    gemm_acc<128, SE>(c_w1, bufA + eg * 4 * SE, jg, acc);
    {
        float4 b4 = *(const float4*)(c_b1 + jg * 4);
        float bb[4] = {b4.x, b4.y, b4.z, b4.w};
        #pragma unroll
        for (int a = 0; a < 4; ++a)
            #pragma unroll
            for (int q = 0; q < 4; ++q) {
                float2 f = unpack2(acc[a][q]);
                *(float2*)(bufB + (eg * 4 + q) * SE + 2 * (jg * 4 + a)) =
                    make_float2(silu_(f.x + bb[a]), silu_(f.y + bb[a]));
            }
    }
    __syncthreads();

    // c_w2: 128 -> 14 per edge
    for (int it = 0; it < 4; ++it) {
        int idx = it * 128 + tid;
        if (idx < TIL * C_) {
            int m = idx & 31, o = idx >> 5;
            float s = c_b2[o];
            const float* src = bufB + (m >> 1) * SE + (m & 1);
            #pragma unroll 4
            for (int k = 0; k < 128; ++k) s += src[2 * k] * c_w2[k * C_ + o];
            cm_s[m * 16 + o] = s;
        }
    }
    __syncthreads();

    // RollerPooling + trans scatter
    for (int idx = tid; idx < TIL * 42; idx += 128) {
        int m = idx / 42, rem = idx - m * 42;
        int e = e0 + m;
        if (e < E) {
            int i = rem / 3;
            int d = rem - i * 3;
            int ws = (C_ + 1) - s_cs[m];
            if (ws < 1)  ws = 1;
            if (ws > C_) ws = C_;
            int end = i + ws;
            if (end > C_) end = C_;
            float ps = 0.f;
            for (int q = i; q < end; ++q) ps += cm_s[m * 16 + q];
            float pooled = ps / (float)ws;
            float cd = x[(size_t)s_row[m] * 42 + rem] - g_pooled[s_col[m] * 3 + d];
            atomicAdd(&g_x_acc[(size_t)s_row[m] * 42 + rem], cd * pooled);
        }
    }
}

// ---------------------------------------------------------------------------
// K4: node update
// ---------------------------------------------------------------------------
__global__ __launch_bounds__(128) void k_node(
    const float* __restrict__ h, const float* __restrict__ x,
    const float* __restrict__ n_w1, const float* __restrict__ n_b1,
    const float* __restrict__ n_w2, const float* __restrict__ n_b2,
    const float* __restrict__ ln_g, const float* __restrict__ ln_b,
    float* __restrict__ out, int N)
{
    extern __shared__ float sm[];
    float* in_s = sm;              // 16*516 (k 0..127 = h, 128..255 = ef mean)
    float* t1_s = in_s + 16 * SR;  // 16*260

    int tid = threadIdx.x, lane = tid & 31, eg = tid >> 5, jg = lane;
    int n0 = blockIdx.x * TIL;

    #pragma unroll
    for (int pp = 0; pp < 4; ++pp) {
        int p = eg + pp * 4;
        int na = n0 + 2 * p, nb = na + 1;
        if (na >= N) na = N - 1;
        if (nb >= N) nb = N - 1;
        stage2(in_s + p * SR, h + (size_t)na * F_, h + (size_t)nb * F_, lane);
        float ia = 1.f / fmaxf(g_cnt_col[na], 1.f);
        float ib = 1.f / fmaxf(g_cnt_col[nb], 1.f);
        float4 a = *(const float4*)(g_ef_sum + (size_t)na * F_ + lane * 4);
        float4 b = *(const float4*)(g_ef_sum + (size_t)nb * F_ + lane * 4);
        float* d = in_s + p * SR + 256;
        *(float4*)(d + lane * 8)     = make_float4(a.x * ia, b.x * ib, a.y * ia, b.y * ib);
        *(float4*)(d + lane * 8 + 4) = make_float4(a.z * ia, b.z * ib, a.w * ia, b.w * ib);
    }
    __syncthreads();

    ull acc[4][4];
    zero_acc(acc);
    gemm_acc<256, SR>(n_w1, in_s + eg * 4 * SR, jg, acc);
    {
        float4 b4 = *(const float4*)(n_b1 + jg * 4);
        float bb[4] = {b4.x, b4.y, b4.z, b4.w};
        #pragma unroll
        for (int a = 0; a < 4; ++a)
            #pragma unroll
            for (int q = 0; q < 4; ++q) {
                float2 f = unpack2(acc[a][q]);
                *(float2*)(t1_s + (eg * 4 + q) * SE + 2 * (jg * 4 + a)) =
                    make_float2(silu_(f.x + bb[a]), silu_(f.y + bb[a]));
            }
    }
    __syncthreads();

    zero_acc(acc);
    gemm_acc<128, SE>(n_w2, t1_s + eg * 4 * SE, jg, acc);

    float hx[4][4], hy[4][4];
    {
        float4 b4 = *(const float4*)(n_b2 + jg * 4);
        float bb[4] = {b4.x, b4.y, b4.z, b4.w};
        #pragma unroll
        for (int a = 0; a < 4; ++a)
            #pragma unroll
            for (int q = 0; q < 4; ++q) {
                float2 f = unpack2(acc[a][q]);
                float2 r = *(const float2*)(in_s + (eg * 4 + q) * SR + 2 * (jg * 4 + a));
                hx[a][q] = r.x + f.x + bb[a];
                hy[a][q] = r.y + f.y + bb[a];
            }
    }

    // LayerNorm per node (warp reduce over 128 features)
    float s1x[4], s2x[4], s1y[4], s2y[4];
    #pragma unroll
    for (int q = 0; q < 4; ++q) {
        s1x[q] = hx[0][q] + hx[1][q] + hx[2][q] + hx[3][q];
        s1y[q] = hy[0][q] + hy[1][q] + hy[2][q] + hy[3][q];
        s2x[q] = hx[0][q]*hx[0][q] + hx[1][q]*hx[1][q] + hx[2][q]*hx[2][q] + hx[3][q]*hx[3][q];
        s2y[q] = hy[0][q]*hy[0][q] + hy[1][q]*hy[1][q] + hy[2][q]*hy[2][q] + hy[3][q]*hy[3][q];
    }
    #pragma unroll
    for (int o = 16; o; o >>= 1)
        #pragma unroll
        for (int q = 0; q < 4; ++q) {
            s1x[q] += __shfl_xor_sync(0xffffffffu, s1x[q], o);
            s2x[q] += __shfl_xor_sync(0xffffffffu, s2x[q], o);
            s1y[q] += __shfl_xor_sync(0xffffffffu, s1y[q], o);
            s2y[q] += __shfl_xor_sync(0xffffffffu, s2y[q], o);
        }

    {
        float4 g4 = *(const float4*)(ln_g + jg * 4);
        float4 bb4 = *(const float4*)(ln_b + jg * 4);
        float gv[4] = {g4.x, g4.y, g4.z, g4.w};
        float bv[4] = {bb4.x, bb4.y, bb4.z, bb4.w};
        #pragma unroll
        for (int q = 0; q < 4; ++q) {
            int na = n0 + eg * 8 + 2 * q;
            if (na < N) {
                float mu = s1x[q] * (1.f / 128.f);
                float var = fmaxf(s2x[q] * (1.f / 128.f) - mu * mu, 0.f);
                float rs = rsqrtf(var + 1e-5f);
                float4 o;
                o.x = (hx[0][q] - mu) * rs * gv[0] + bv[0];
                o.y = (hx[1][q] - mu) * rs * gv[1] + bv[1];
                o.z = (hx[2][q] - mu) * rs * gv[2] + bv[2];
                o.w = (hx[3][q] - mu) * rs * gv[3] + bv[3];
                *(float4*)(out + (size_t)na * F_ + jg * 4) = o;
            }
            if (na + 1 < N) {
                float mu = s1y[q] * (1.f / 128.f);
                float var = fmaxf(s2y[q] * (1.f / 128.f) - mu * mu, 0.f);
                float rs = rsqrtf(var + 1e-5f);
                float4 o;
                o.x = (hy[0][q] - mu) * rs * gv[0] + bv[0];
                o.y = (hy[1][q] - mu) * rs * gv[1] + bv[1];
                o.z = (hy[2][q] - mu) * rs * gv[2] + bv[2];
                o.w = (hy[3][q] - mu) * rs * gv[3] + bv[3];
                *(float4*)(out + (size_t)(na + 1) * F_ + jg * 4) = o;
            }
        }
    }

    // x_new = x + x_acc / max(cnt_row, 1)
    float* out_x = out + (size_t)N * F_;
    for (int idx = tid; idx < TIL * 42; idx += 128) {
        int m = idx / 42, rem = idx - m * 42;
        int n = n0 + m;
        if (n < N) {
            out_x[(size_t)n * 42 + rem] =
                x[(size_t)n * 42 + rem] +
                g_x_acc[(size_t)n * 42 + rem] / fmaxf(g_cnt_row[n], 1.f);
        }
    }
}

// ---------------------------------------------------------------------------
// launch
// ---------------------------------------------------------------------------
extern "C" void kernel_launch(void* const* d_in, const int* in_sizes, int n_in,
                              void* d_out, int out_size) {
    const float* h     = (const float*)d_in[0];
    const float* x     = (const float*)d_in[1];
    const float* attr  = (const float*)d_in[2];
    const float* cw    = (const float*)d_in[3];
    const int*   row   = (const int*)d_in[4];
    const int*   col   = (const int*)d_in[5];
    const float* rad_w = (const float*)d_in[6];
    const float* rad_b = (const float*)d_in[7];
    const float* e_w1  = (const float*)d_in[8];
    const float* e_b1  = (const float*)d_in[9];
    const float* e_w2  = (const float*)d_in[10];
    const float* e_b2  = (const float*)d_in[11];
    const float* att_w = (const float*)d_in[12];
    const float* att_b = (const float*)d_in[13];
    const float* c_w1  = (const float*)d_in[14];
    const float* c_b1  = (const float*)d_in[15];
    const float* c_w2  = (const float*)d_in[16];
    const float* c_b2  = (const float*)d_in[17];
    const float* n_w1  = (const float*)d_in[18];
    const float* n_b1  = (const float*)d_in[19];
    const float* n_w2  = (const float*)d_in[20];
    const float* n_b2  = (const float*)d_in[21];
    const float* ln_g  = (const float*)d_in[22];
    const float* ln_b  = (const float*)d_in[23];

    int N = in_sizes[0] / F_;
    int E = in_sizes[4];
    int EB = (E + TIL - 1) / TIL;
    int NB = (N + TIL - 1) / TIL;

    const int SMEM_R = (16 * SR + 4 * 1024 + 32) * 4;
    const int SMEM_E = (2 * 16 * SE + 512) * 4 + 96 * 4;
    const int SMEM_N = (16 * SR + 16 * SE) * 4;

    cudaFuncSetAttribute(k_radial, cudaFuncAttributeMaxDynamicSharedMemorySize, SMEM_R);
    cudaFuncSetAttribute(k_edge,   cudaFuncAttributeMaxDynamicSharedMemorySize, SMEM_E);
    cudaFuncSetAttribute(k_node,   cudaFuncAttributeMaxDynamicSharedMemorySize, SMEM_N);

    k_zero<<<256, 256>>>(N);
    k_prep<<<(N + 255) / 256, 256>>>(x, cw, N);
    k_radial<<<EB, 128, SMEM_R>>>(x, attr, cw, row, col, rad_w, rad_b, E);
    k_edge<<<EB, 128, SMEM_E>>>(h, x, row, col, e_w1, e_b1, e_w2, e_b2,
                                att_w, att_b, c_w1, c_b1, c_w2, c_b2, E);
    k_node<<<NB, 128, SMEM_N>>>(h, x, n_w1, n_b1, n_w2, n_b2,
                                ln_g, ln_b, (float*)d_out, N);
}

// round 4
// speedup vs baseline: 1.5238x; 1.0016x over previous
#include <cuda_runtime.h>

// Problem constants (fixed by the dataset)
#define NMAX 20000
#define EMAX 200000
#define C_   14
#define D_   3
#define A_   16
#define F_   128
#define TIL  32

typedef unsigned long long ull;

// ---- scratch (device globals: no allocations allowed) ----
// g_rad is stored pair-interleaved per 32-edge block:
//   g_rad[blk*4096 + p*256 + 2*k + s]  = radial[edge 2p+s of block][k]
__device__ float g_rad  [(size_t)EMAX * F_];
__device__ float g_ef_sum[(size_t)NMAX * F_];
__device__ float g_x_acc [(size_t)NMAX * C_ * D_];
__device__ float g_cnt_row[NMAX];
__device__ float g_cnt_col[NMAX];
__device__ float g_pooled [NMAX * D_];
__device__ int   g_csum   [NMAX];

__device__ __forceinline__ float sigm_(float v) { return 1.f / (1.f + __expf(-v)); }
__device__ __forceinline__ float silu_(float v) { return v * sigm_(v); }

// ---- packed f32x2 helpers (sm_10x) ----
__device__ __forceinline__ ull pack2(float v) {
    ull r;
    asm("mov.b64 %0, {%1, %1};" : "=l"(r) : "f"(v));
    return r;
}
__device__ __forceinline__ void fma2(ull& acc, ull a, ull b) {
    asm("fma.rn.f32x2 %0, %1, %2, %0;" : "+l"(acc) : "l"(a), "l"(b));
}
__device__ __forceinline__ float2 unpack2(ull v) {
    float2 f;
    asm("mov.b64 {%0, %1}, %2;" : "=f"(f.x), "=f"(f.y) : "l"(v));
    return f;
}

// ---------------------------------------------------------------------------
// Pair-interleaved GEMM accumulate.
// base points at this warp's 4 pair-rows (pairs eg*4..eg*4+3), stride S floats.
// acc[a][q] is an f32x2 accumulator: (.x = edge 2*(eg*4+q), .y = edge +1),
// output feature j = jg*4 + a.  W is row-major [K][128].
// Inner loop/k: 1 LDG.128 + 4 packs + 4 LDS.64 + 16 fma.f32x2.
// ---------------------------------------------------------------------------
template<int K, int S>
__device__ __forceinline__ void gemm_acc(const float* __restrict__ W,
                                         const float* __restrict__ base,
                                         int jg, ull acc[4][4])
{
    const float* wp = W + jg * 4;
    #pragma unroll 4
    for (int k = 0; k < K; ++k) {
        float4 w4 = *(const float4*)(wp + (size_t)k * F_);
        ull i0 = *(const ull*)(base + 0 * S + 2 * k);
        ull i1 = *(const ull*)(base + 1 * S + 2 * k);
        ull i2 = *(const ull*)(base + 2 * S + 2 * k);
        ull i3 = *(const ull*)(base + 3 * S + 2 * k);
        ull w0 = pack2(w4.x), w1 = pack2(w4.y), w2 = pack2(w4.z), w3 = pack2(w4.w);
        fma2(acc[0][0], i0, w0); fma2(acc[0][1], i1, w0);
        fma2(acc[0][2], i2, w0); fma2(acc[0][3], i3, w0);
        fma2(acc[1][0], i0, w1); fma2(acc[1][1], i1, w1);
        fma2(acc[1][2], i2, w1); fma2(acc[1][3], i3, w1);
        fma2(acc[2][0], i0, w2); fma2(acc[2][1], i1, w2);
        fma2(acc[2][2], i2, w2); fma2(acc[2][3], i3, w2);
        fma2(acc[3][0], i0, w3); fma2(acc[3][1], i1, w3);
        fma2(acc[3][2], i2, w3); fma2(acc[3][3], i3, w3);
    }
}

__device__ __forceinline__ void zero_acc(ull acc[4][4]) {
    #pragma unroll
    for (int a = 0; a < 4; ++a)
        #pragma unroll
        for (int q = 0; q < 4; ++q) acc[a][q] = 0ull;
}

// stage 128 contiguous floats from two global rows into one interleaved
// pair-row (dst = buf + pair*S [+offset]); one warp, conflict-free float4s.
__device__ __forceinline__ void stage2(float* dst, const float* __restrict__ s0,
                                       const float* __restrict__ s1, int lane)
{
    float4 a = *(const float4*)(s0 + lane * 4);
    float4 b = *(const float4*)(s1 + lane * 4);
    *(float4*)(dst + lane * 8)     = make_float4(a.x, b.x, a.y, b.y);
    *(float4*)(dst + lane * 8 + 4) = make_float4(a.z, b.z, a.w, b.w);
}

// ---------------------------------------------------------------------------
// K0: zero accumulators (graph replays -> must re-zero every launch)
// ---------------------------------------------------------------------------
__global__ void k_zero(int n_nodes) {
    int t0 = n_nodes * F_;
    int t1 = t0 + n_nodes * C_ * D_;
    int t2 = t1 + n_nodes;
    int t3 = t2 + n_nodes;
    for (int i = blockIdx.x * blockDim.x + threadIdx.x; i < t3;
         i += gridDim.x * blockDim.x) {
        if (i < t0)       g_ef_sum[i] = 0.f;
        else if (i < t1)  g_x_acc[i - t0] = 0.f;
        else if (i < t2)  g_cnt_row[i - t1] = 0.f;
        else              g_cnt_col[i - t2] = 0.f;
    }
}

// ---------------------------------------------------------------------------
// K1: per-node prep
// ---------------------------------------------------------------------------
__global__ void k_prep(const float* __restrict__ x, const float* __restrict__ cw,
                       int N) {
    int n = blockIdx.x * blockDim.x + threadIdx.x;
    if (n >= N) return;
    int s = 0;
    float px = 0.f, py = 0.f, pz = 0.f;
    #pragma unroll
    for (int i = 0; i < C_; ++i) {
        float w = cw[n * C_ + i];
        if (w != 0.f) {
            s++;
            px += x[n * C_ * D_ + i * 3 + 0];
            py += x[n * C_ * D_ + i * 3 + 1];
            pz += x[n * C_ * D_ + i * 3 + 2];
        }
    }
    g_csum[n] = s;
    float inv = 1.f / (float)(s > 0 ? s : 1);
    g_pooled[n * 3 + 0] = px * inv;
    g_pooled[n * 3 + 1] = py * inv;
    g_pooled[n * 3 + 2] = pz * inv;
}

// ---------------------------------------------------------------------------
// K2: per-edge radial: einsum prologue + GEMM 256->128, scaled by 1/(||R||+1)
// in_s pair-interleaved [16][516]
// ---------------------------------------------------------------------------
#define SR 516
__global__ __launch_bounds__(128) void k_radial(
    const float* __restrict__ x, const float* __restrict__ attr,
    const float* __restrict__ cw, const int* __restrict__ row,
    const int* __restrict__ col, const float* __restrict__ rad_w,
    const float* __restrict__ rad_b, int E)
{
    extern __shared__ float sm[];
    float* in_s     = sm;                 // 16*516
    float* wsc      = sm + 16 * SR;       // 4 warps * 1024
    float* inv_norm = wsc + 4 * 1024;     // [32]

    int tid = threadIdx.x, lane = tid & 31, wp = tid >> 5;
    int e0 = blockIdx.x * TIL;

    float* W     = wsc + wp * 1024;
    float* s_xr  = W;
    float* s_xc  = W + 48;
    float* s_cwr = W + 96;
    float* s_cwc = W + 112;
    float* s_ar  = W + 128;
    float* s_ac  = W + 352;
    float* s_msg = W + 576;
    float* s_T   = W + 772;

    for (int it = 0; it < 8; ++it) {
        int m = it * 4 + wp;
        int e = e0 + m;
        if (e >= E) e = E - 1;
        int r = row[e], c = col[e];
        for (int i = lane; i < 42; i += 32) {
            s_xr[i] = x[r * 42 + i];
            s_xc[i] = x[c * 42 + i];
        }
        for (int i = lane; i < 14; i += 32) {
            s_cwr[i] = cw[r * C_ + i];
            s_cwc[i] = cw[c * C_ + i];
        }
        for (int i = lane; i < 224; i += 32) {
            s_ar[i] = attr[r * 224 + i];
            s_ac[i] = attr[c * 224 + i];
        }
        __syncwarp();
        for (int i = lane; i < 196; i += 32) {
            int ci = i / 14, cj = i - ci * 14;
            float dx = s_xr[ci * 3 + 0] - s_xc[cj * 3 + 0];
            float dy = s_xr[ci * 3 + 1] - s_xc[cj * 3 + 1];
            float dz = s_xr[ci * 3 + 2] - s_xc[cj * 3 + 2];
            s_msg[i] = sqrtf(dx * dx + dy * dy + dz * dz) * s_cwr[ci] * s_cwc[cj];
        }
        __syncwarp();
        for (int i = lane; i < 224; i += 32) {
            int ci = i >> 4, b = i & 15;
            float t = 0.f;
            #pragma unroll
            for (int jj = 0; jj < C_; ++jj) t += s_msg[ci * 14 + jj] * s_ac[jj * 16 + b];
            s_T[i] = t;
        }
        __syncwarp();
        float ss = 0.f;
        for (int i = lane; i < 256; i += 32) {
            int a = i >> 4, b = i & 15;
            float t = 0.f;
            #pragma unroll
            for (int jj = 0; jj < C_; ++jj) t += s_ar[jj * 16 + a] * s_T[jj * 16 + b];
            in_s[(m >> 1) * SR + 2 * i + (m & 1)] = t;
            ss += t * t;
        }
        #pragma unroll
        for (int o = 16; o; o >>= 1) ss += __shfl_xor_sync(0xffffffffu, ss, o);
        if (lane == 0) inv_norm[m] = 1.f / (sqrtf(ss) + 1.f);
        __syncwarp();
    }
    __syncthreads();

    int jg = lane, eg = tid >> 5;
    ull acc[4][4];
    zero_acc(acc);
    gemm_acc<256, SR>(rad_w, in_s + eg * 4 * SR, jg, acc);

    float4 b4 = *(const float4*)(rad_b + jg * 4);
    float bb[4] = {b4.x, b4.y, b4.z, b4.w};
    float* outb = g_rad + (size_t)blockIdx.x * 4096;
    #pragma unroll
    for (int q = 0; q < 4; ++q) {
        int P = eg * 4 + q;
        float n0 = inv_norm[2 * P], n1 = inv_norm[2 * P + 1];
        #pragma unroll
        for (int a = 0; a < 4; ++a) {
            float2 f = unpack2(acc[a][q]);
            *(float2*)(outb + P * 256 + 2 * (jg * 4 + a)) =
                make_float2((f.x + bb[a]) * n0, (f.y + bb[a]) * n1);
        }
    }
}

// ---------------------------------------------------------------------------
// K3: fused edge kernel; double-buffered 128-k chunks, pair-interleaved.
// ---------------------------------------------------------------------------
#define SE 260
__global__ __launch_bounds__(128) void k_edge(
    const float* __restrict__ h, const float* __restrict__ x,
    const int* __restrict__ row, const int* __restrict__ col,
    const float* __restrict__ e_w1, const float* __restrict__ e_b1,
    const float* __restrict__ e_w2, const float* __restrict__ e_b2,
    const float* __restrict__ att_w, const float* __restrict__ att_b,
    const float* __restrict__ c_w1, const float* __restrict__ c_b1,
    const float* __restrict__ c_w2, const float* __restrict__ c_b2,
    int E)
{
    extern __shared__ float sm[];
    float* bufA  = sm;                    // 16*260
    float* bufB  = bufA + 16 * SE;        // 16*260
    float* cm_s  = bufB + 16 * SE;        // 32*16
    int*   s_row = (int*)(cm_s + 512);
    int*   s_col = s_row + 32;
    int*   s_cs  = s_col + 32;

    int tid = threadIdx.x, lane = tid & 31, eg = tid >> 5, jg = lane;
    int e0 = blockIdx.x * TIL;

    if (tid < TIL) {
        int e = e0 + tid;
        if (e >= E) e = E - 1;
        int r = row[e];
        s_row[tid] = r;
        s_col[tid] = col[e];
        s_cs[tid]  = g_csum[r];
    }
    __syncthreads();

    // stage h[row] -> A
    #pragma unroll
    for (int pp = 0; pp < 4; ++pp) {
        int p = eg + pp * 4;
        stage2(bufA + p * SE, h + (size_t)s_row[2 * p] * F_,
               h + (size_t)s_row[2 * p + 1] * F_, lane);
    }
    __syncthreads();

    ull acc[4][4];
    zero_acc(acc);

    // stage h[col] -> B, compute chunk0 from A
    #pragma unroll
    for (int pp = 0; pp < 4; ++pp) {
        int p = eg + pp * 4;
        stage2(bufB + p * SE, h + (size_t)s_col[2 * p] * F_,
               h + (size_t)s_col[2 * p + 1] * F_, lane);
    }
    gemm_acc<128, SE>(e_w1, bufA + eg * 4 * SE, jg, acc);
    __syncthreads();

    // stage radial -> A (straight copy, already pair-interleaved), chunk1 from B
    {
        const float* src = g_rad + (size_t)blockIdx.x * 4096;
        #pragma unroll
        for (int pp = 0; pp < 4; ++pp) {
            int p = eg + pp * 4;
            *(float4*)(bufA + p * SE + lane * 8) =
                *(const float4*)(src + p * 256 + lane * 8);
            *(float4*)(bufA + p * SE + lane * 8 + 4) =
                *(const float4*)(src + p * 256 + lane * 8 + 4);
        }
    }
    gemm_acc<128, SE>(e_w1 + 128 * F_, bufB + eg * 4 * SE, jg, acc);
    __syncthreads();

    gemm_acc<128, SE>(e_w1 + 256 * F_, bufA + eg * 4 * SE, jg, acc);

    // t1 = silu(acc + b1) -> B
    {
        float4 b4 = *(const float4*)(e_b1 + jg * 4);
        float bb[4] = {b4.x, b4.y, b4.z, b4.w};
        #pragma unroll
        for (int a = 0; a < 4; ++a)
            #pragma unroll
            for (int q = 0; q < 4; ++q) {
                float2 f = unpack2(acc[a][q]);
                *(float2*)(bufB + (eg * 4 + q) * SE + 2 * (jg * 4 + a)) =
                    make_float2(silu_(f.x + bb[a]), silu_(f.y + bb[a]));
            }
    }
    __syncthreads();

    // GEMM2: 128 -> 128 from B
    zero_acc(acc);
    gemm_acc<128, SE>(e_w2, bufB + eg * 4 * SE, jg, acc);

    float tx[4][4], ty[4][4];
    {
        float4 b4 = *(const float4*)(e_b2 + jg * 4);
        float bb[4] = {b4.x, b4.y, b4.z, b4.w};
        #pragma unroll
        for (int a = 0; a < 4; ++a)
            #pragma unroll
            for (int q = 0; q < 4; ++q) {
                float2 f = unpack2(acc[a][q]);
                tx[a][q] = silu_(f.x + bb[a]);
                ty[a][q] = silu_(f.y + bb[a]);
            }
    }

    // attention gate (warp owns all 128 features of its 8 edges)
    {
        float4 aw = *(const float4*)(att_w + jg * 4);
        float awv[4] = {aw.x, aw.y, aw.z, aw.w};
        float px[4], py[4];
        #pragma unroll
        for (int q = 0; q < 4; ++q) {
            px[q] = tx[0][q] * awv[0] + tx[1][q] * awv[1] +
                    tx[2][q] * awv[2] + tx[3][q] * awv[3];
            py[q] = ty[0][q] * awv[0] + ty[1][q] * awv[1] +
                    ty[2][q] * awv[2] + ty[3][q] * awv[3];
        }
        #pragma unroll
        for (int o = 16; o; o >>= 1)
            #pragma unroll
            for (int q = 0; q < 4; ++q) {
                px[q] += __shfl_xor_sync(0xffffffffu, px[q], o);
                py[q] += __shfl_xor_sync(0xffffffffu, py[q], o);
            }
        float ab = att_b[0];
        #pragma unroll
        for (int q = 0; q < 4; ++q) {
            float gx = sigm_(px[q] + ab);
            float gy = sigm_(py[q] + ab);
            #pragma unroll
            for (int a = 0; a < 4; ++a) { tx[a][q] *= gx; ty[a][q] *= gy; }
        }
    }

    // ef -> A (for GEMM3) + atomic scatter into per-col sums
    #pragma unroll
    for (int a = 0; a < 4; ++a)
        #pragma unroll
        for (int q = 0; q < 4; ++q)
            *(float2*)(bufA + (eg * 4 + q) * SE + 2 * (jg * 4 + a)) =
                make_float2(tx[a][q], ty[a][q]);
    #pragma unroll
    for (int q = 0; q < 4; ++q) {
        int m0 = eg * 8 + 2 * q;
        if (e0 + m0 < E) {
            float* d0 = g_ef_sum + (size_t)s_col[m0] * F_ + jg * 4;
            #pragma unroll
            for (int a = 0; a < 4; ++a) atomicAdd(d0 + a, tx[a][q]);
        }
        if (e0 + m0 + 1 < E) {
            float* d1 = g_ef_sum + (size_t)s_col[m0 + 1] * F_ + jg * 4;
            #pragma unroll
            for (int a = 0; a < 4; ++a) atomicAdd(d1 + a, ty[a][q]);
        }
    }
    if (tid < TIL && e0 + tid < E) {
        atomicAdd(&g_cnt_col[s_col[tid]], 1.f);
        atomicAdd(&g_cnt_row[s_row[tid]], 1.f);
    }
    __syncthreads();

    // GEMM3: c_w1 from A -> cmh -> B
    zero_acc(acc);
    gemm_acc<128, SE>(c_w1, bufA + eg * 4 * SE, jg, acc);
    {
        float4 b4 = *(const float4*)(c_b1 + jg * 4);
        float bb[4] = {b4.x, b4.y, b4.z, b4.w};
        #pragma unroll
        for (int a = 0; a < 4; ++a)
            #pragma unroll
            for (int q = 0; q < 4; ++q) {
                float2 f = unpack2(acc[a][q]);
                *(float2*)(bufB + (eg * 4 + q) * SE + 2 * (jg * 4 + a)) =
                    make_float2(silu_(f.x + bb[a]), silu_(f.y + bb[a]));
            }
    }
    __syncthreads();

    // c_w2: 128 -> 14 per edge
    for (int it = 0; it < 4; ++it) {
        int idx = it * 128 + tid;
        if (idx < TIL * C_) {
            int m = idx & 31, o = idx >> 5;
            float s = c_b2[o];
            const float* src = bufB + (m >> 1) * SE + (m & 1);
            #pragma unroll 4
            for (int k = 0; k < 128; ++k) s += src[2 * k] * c_w2[k * C_ + o];
            cm_s[m * 16 + o] = s;
        }
    }
    __syncthreads();

    // RollerPooling + trans scatter
    for (int idx = tid; idx < TIL * 42; idx += 128) {
        int m = idx / 42, rem = idx - m * 42;
        int e = e0 + m;
        if (e < E) {
            int i = rem / 3;
            int d = rem - i * 3;
            int ws = (C_ + 1) - s_cs[m];
            if (ws < 1)  ws = 1;
            if (ws > C_) ws = C_;
            int end = i + ws;
            if (end > C_) end = C_;
            float ps = 0.f;
            for (int q = i; q < end; ++q) ps += cm_s[m * 16 + q];
            float pooled = ps / (float)ws;
            float cd = x[(size_t)s_row[m] * 42 + rem] - g_pooled[s_col[m] * 3 + d];
            atomicAdd(&g_x_acc[(size_t)s_row[m] * 42 + rem], cd * pooled);
        }
    }
}

// ---------------------------------------------------------------------------
// K4: node update
// ---------------------------------------------------------------------------
__global__ __launch_bounds__(128) void k_node(
    const float* __restrict__ h, const float* __restrict__ x,
    const float* __restrict__ n_w1, const float* __restrict__ n_b1,
    const float* __restrict__ n_w2, const float* __restrict__ n_b2,
    const float* __restrict__ ln_g, const float* __restrict__ ln_b,
    float* __restrict__ out, int N)
{
    extern __shared__ float sm[];
    float* in_s = sm;              // 16*516 (k 0..127 = h, 128..255 = ef mean)
    float* t1_s = in_s + 16 * SR;  // 16*260

    int tid = threadIdx.x, lane = tid & 31, eg = tid >> 5, jg = lane;
    int n0 = blockIdx.x * TIL;

    #pragma unroll
    for (int pp = 0; pp < 4; ++pp) {
        int p = eg + pp * 4;
        int na = n0 + 2 * p, nb = na + 1;
        if (na >= N) na = N - 1;
        if (nb >= N) nb = N - 1;
        stage2(in_s + p * SR, h + (size_t)na * F_, h + (size_t)nb * F_, lane);
        float ia = 1.f / fmaxf(g_cnt_col[na], 1.f);
        float ib = 1.f / fmaxf(g_cnt_col[nb], 1.f);
        float4 a = *(const float4*)(g_ef_sum + (size_t)na * F_ + lane * 4);
        float4 b = *(const float4*)(g_ef_sum + (size_t)nb * F_ + lane * 4);
        float* d = in_s + p * SR + 256;
        *(float4*)(d + lane * 8)     = make_float4(a.x * ia, b.x * ib, a.y * ia, b.y * ib);
        *(float4*)(d + lane * 8 + 4) = make_float4(a.z * ia, b.z * ib, a.w * ia, b.w * ib);
    }
    __syncthreads();

    ull acc[4][4];
    zero_acc(acc);
    gemm_acc<256, SR>(n_w1, in_s + eg * 4 * SR, jg, acc);
    {
        float4 b4 = *(const float4*)(n_b1 + jg * 4);
        float bb[4] = {b4.x, b4.y, b4.z, b4.w};
        #pragma unroll
        for (int a = 0; a < 4; ++a)
            #pragma unroll
            for (int q = 0; q < 4; ++q) {
                float2 f = unpack2(acc[a][q]);
                *(float2*)(t1_s + (eg * 4 + q) * SE + 2 * (jg * 4 + a)) =
                    make_float2(silu_(f.x + bb[a]), silu_(f.y + bb[a]));
            }
    }
    __syncthreads();

    zero_acc(acc);
    gemm_acc<128, SE>(n_w2, t1_s + eg * 4 * SE, jg, acc);

    float hx[4][4], hy[4][4];
    {
        float4 b4 = *(const float4*)(n_b2 + jg * 4);
        float bb[4] = {b4.x, b4.y, b4.z, b4.w};
        #pragma unroll
        for (int a = 0; a < 4; ++a)
            #pragma unroll
            for (int q = 0; q < 4; ++q) {
                float2 f = unpack2(acc[a][q]);
                float2 r = *(const float2*)(in_s + (eg * 4 + q) * SR + 2 * (jg * 4 + a));
                hx[a][q] = r.x + f.x + bb[a];
                hy[a][q] = r.y + f.y + bb[a];
            }
    }

    // LayerNorm per node (warp reduce over 128 features)
    float s1x[4], s2x[4], s1y[4], s2y[4];
    #pragma unroll
    for (int q = 0; q < 4; ++q) {
        s1x[q] = hx[0][q] + hx[1][q] + hx[2][q] + hx[3][q];
        s1y[q] = hy[0][q] + hy[1][q] + hy[2][q] + hy[3][q];
        s2x[q] = hx[0][q]*hx[0][q] + hx[1][q]*hx[1][q] + hx[2][q]*hx[2][q] + hx[3][q]*hx[3][q];
        s2y[q] = hy[0][q]*hy[0][q] + hy[1][q]*hy[1][q] + hy[2][q]*hy[2][q] + hy[3][q]*hy[3][q];
    }
    #pragma unroll
    for (int o = 16; o; o >>= 1)
        #pragma unroll
        for (int q = 0; q < 4; ++q) {
            s1x[q] += __shfl_xor_sync(0xffffffffu, s1x[q], o);
            s2x[q] += __shfl_xor_sync(0xffffffffu, s2x[q], o);
            s1y[q] += __shfl_xor_sync(0xffffffffu, s1y[q], o);
            s2y[q] += __shfl_xor_sync(0xffffffffu, s2y[q], o);
        }

    {
        float4 g4 = *(const float4*)(ln_g + jg * 4);
        float4 bb4 = *(const float4*)(ln_b + jg * 4);
        float gv[4] = {g4.x, g4.y, g4.z, g4.w};
        float bv[4] = {bb4.x, bb4.y, bb4.z, bb4.w};
        #pragma unroll
        for (int q = 0; q < 4; ++q) {
            int na = n0 + eg * 8 + 2 * q;
            if (na < N) {
                float mu = s1x[q] * (1.f / 128.f);
                float var = fmaxf(s2x[q] * (1.f / 128.f) - mu * mu, 0.f);
                float rs = rsqrtf(var + 1e-5f);
                float4 o;
                o.x = (hx[0][q] - mu) * rs * gv[0] + bv[0];
                o.y = (hx[1][q] - mu) * rs * gv[1] + bv[1];
                o.z = (hx[2][q] - mu) * rs * gv[2] + bv[2];
                o.w = (hx[3][q] - mu) * rs * gv[3] + bv[3];
                *(float4*)(out + (size_t)na * F_ + jg * 4) = o;
            }
            if (na + 1 < N) {
                float mu = s1y[q] * (1.f / 128.f);
                float var = fmaxf(s2y[q] * (1.f / 128.f) - mu * mu, 0.f);
                float rs = rsqrtf(var + 1e-5f);
                float4 o;
                o.x = (hy[0][q] - mu) * rs * gv[0] + bv[0];
                o.y = (hy[1][q] - mu) * rs * gv[1] + bv[1];
                o.z = (hy[2][q] - mu) * rs * gv[2] + bv[2];
                o.w = (hy[3][q] - mu) * rs * gv[3] + bv[3];
                *(float4*)(out + (size_t)(na + 1) * F_ + jg * 4) = o;
            }
        }
    }

    // x_new = x + x_acc / max(cnt_row, 1)
    float* out_x = out + (size_t)N * F_;
    for (int idx = tid; idx < TIL * 42; idx += 128) {
        int m = idx / 42, rem = idx - m * 42;
        int n = n0 + m;
        if (n < N) {
            out_x[(size_t)n * 42 + rem] =
                x[(size_t)n * 42 + rem] +
                g_x_acc[(size_t)n * 42 + rem] / fmaxf(g_cnt_row[n], 1.f);
        }
    }
}

// ---------------------------------------------------------------------------
// launch
// ---------------------------------------------------------------------------
extern "C" void kernel_launch(void* const* d_in, const int* in_sizes, int n_in,
                              void* d_out, int out_size) {
    const float* h     = (const float*)d_in[0];
    const float* x     = (const float*)d_in[1];
    const float* attr  = (const float*)d_in[2];
    const float* cw    = (const float*)d_in[3];
    const int*   row   = (const int*)d_in[4];
    const int*   col   = (const int*)d_in[5];
    const float* rad_w = (const float*)d_in[6];
    const float* rad_b = (const float*)d_in[7];
    const float* e_w1  = (const float*)d_in[8];
    const float* e_b1  = (const float*)d_in[9];
    const float* e_w2  = (const float*)d_in[10];
    const float* e_b2  = (const float*)d_in[11];
    const float* att_w = (const float*)d_in[12];
    const float* att_b = (const float*)d_in[13];
    const float* c_w1  = (const float*)d_in[14];
    const float* c_b1  = (const float*)d_in[15];
    const float* c_w2  = (const float*)d_in[16];
    const float* c_b2  = (const float*)d_in[17];
    const float* n_w1  = (const float*)d_in[18];
    const float* n_b1  = (const float*)d_in[19];
    const float* n_w2  = (const float*)d_in[20];
    const float* n_b2  = (const float*)d_in[21];
    const float* ln_g  = (const float*)d_in[22];
    const float* ln_b  = (const float*)d_in[23];

    int N = in_sizes[0] / F_;
    int E = in_sizes[4];
    int EB = (E + TIL - 1) / TIL;
    int NB = (N + TIL - 1) / TIL;

    const int SMEM_R = (16 * SR + 4 * 1024 + 32) * 4;
    const int SMEM_E = (2 * 16 * SE + 512) * 4 + 96 * 4;
    const int SMEM_N = (16 * SR + 16 * SE) * 4;

    cudaFuncSetAttribute(k_radial, cudaFuncAttributeMaxDynamicSharedMemorySize, SMEM_R);
    cudaFuncSetAttribute(k_edge,   cudaFuncAttributeMaxDynamicSharedMemorySize, SMEM_E);
    cudaFuncSetAttribute(k_node,   cudaFuncAttributeMaxDynamicSharedMemorySize, SMEM_N);

    k_zero<<<256, 256>>>(N);
    k_prep<<<(N + 255) / 256, 256>>>(x, cw, N);
    k_radial<<<EB, 128, SMEM_R>>>(x, attr, cw, row, col, rad_w, rad_b, E);
    k_edge<<<EB, 128, SMEM_E>>>(h, x, row, col, e_w1, e_b1, e_w2, e_b2,
                                att_w, att_b, c_w1, c_b1, c_w2, c_b2, E);
    k_node<<<NB, 128, SMEM_N>>>(h, x, n_w1, n_b1, n_w2, n_b2,
                                ln_g, ln_b, (float*)d_out, N);
}

// round 6
// speedup vs baseline: 3.0869x; 2.0258x over previous
#include <cuda_runtime.h>

#define NMAX 20000
#define EMAX 200000
#define C_   14
#define F_   128
#define TIL  32
#define S_E  132
#define S_N  260

typedef unsigned int u32;

// ---- scratch ----
__device__ __align__(16) float g_rad [(size_t)EMAX * F_];   // row-major [E][128], tf32 bits
__device__ __align__(16) float g_wt  [165888];              // fragment-major weights (tf32)
__device__ float g_ef_sum[(size_t)NMAX * F_];
__device__ float g_x_acc [(size_t)NMAX * C_ * 3];
__device__ float g_cnt_row[NMAX];
__device__ float g_cnt_col[NMAX];
__device__ float g_pooled [NMAX * 3];
__device__ int   g_csum   [NMAX];

// fragment-image offsets in float2 units
#define WF_E1 0
#define WF_E2 24576
#define WF_C1 32768
#define WF_C2 40960
#define WF_RW 41984
#define WF_N1 58368
#define WF_N2 74752

__device__ __forceinline__ float sigm_(float v) { return 1.f / (1.f + __expf(-v)); }
__device__ __forceinline__ float silu_(float v) { return v * sigm_(v); }
__device__ __forceinline__ u32 tf32r(float v) {
    u32 r; asm("cvt.rna.tf32.f32 %0, %1;" : "=r"(r) : "f"(v)); return r;
}
__device__ __forceinline__ float u2f(u32 v) { return __uint_as_float(v); }
__device__ __forceinline__ float4 cvt4(float4 v) {
    return make_float4(u2f(tf32r(v.x)), u2f(tf32r(v.y)), u2f(tf32r(v.z)), u2f(tf32r(v.w)));
}

// mma.sync m16n8k8 tf32: D += A*B
__device__ __forceinline__ void mma8(float4& d, u32 a0, u32 a1, u32 a2, u32 a3,
                                     u32 b0, u32 b1) {
    asm volatile(
        "mma.sync.aligned.m16n8k8.row.col.f32.tf32.tf32.f32 "
        "{%0,%1,%2,%3},{%4,%5,%6,%7},{%8,%9},{%0,%1,%2,%3};"
        : "+f"(d.x), "+f"(d.y), "+f"(d.z), "+f"(d.w)
        : "r"(a0), "r"(a1), "r"(a2), "r"(a3), "r"(b0), "r"(b1));
}

// in_s: row-major [32][S] (tf32 bits). wf: fragment-major float2 for this weight.
// Warp handles ntiles nt0..nt0+3, ksteps [ks0, ks0+nks) of KST total.
// d[mt][nt]: D rows {mt*16+g, +8}, cols {nt*8+2tig, +1}.
template<int S>
__device__ __forceinline__ void gemm_chunk(const float* in_s, const float2* wf,
                                           int nt0, int ks0, int nks, int KST,
                                           int g, int tig, int lane, float4 d[2][4])
{
    #pragma unroll 4
    for (int ks = 0; ks < nks; ++ks) {
        int k0 = ks * 8;
        u32 a[2][4];
        #pragma unroll
        for (int mt = 0; mt < 2; ++mt) {
            const float* r0 = in_s + (mt * 16 + g) * S + k0;
            const float* r1 = in_s + (mt * 16 + g + 8) * S + k0;
            a[mt][0] = __float_as_uint(r0[tig]);
            a[mt][1] = __float_as_uint(r1[tig]);
            a[mt][2] = __float_as_uint(r0[tig + 4]);
            a[mt][3] = __float_as_uint(r1[tig + 4]);
        }
        #pragma unroll
        for (int nt = 0; nt < 4; ++nt) {
            float2 b = wf[((size_t)(nt0 + nt) * KST + ks0 + ks) * 32 + lane];
            u32 b0 = __float_as_uint(b.x), b1 = __float_as_uint(b.y);
            mma8(d[0][nt], a[0][0], a[0][1], a[0][2], a[0][3], b0, b1);
            mma8(d[1][nt], a[1][0], a[1][1], a[1][2], a[1][3], b0, b1);
        }
    }
}

__device__ __forceinline__ void zero_d(float4 d[2][4]) {
    #pragma unroll
    for (int mt = 0; mt < 2; ++mt)
        #pragma unroll
        for (int nt = 0; nt < 4; ++nt) d[mt][nt] = make_float4(0.f, 0.f, 0.f, 0.f);
}

// store activated fragment rows into row-major buf as tf32 bits
__device__ __forceinline__ void store_frag(float* buf, int S, int g, int f, int mt,
                                           float4 v) {
    *(float2*)(buf + (mt * 16 + g) * S + f) =
        make_float2(u2f(tf32r(v.x)), u2f(tf32r(v.y)));
    *(float2*)(buf + (mt * 16 + g + 8) * S + f) =
        make_float2(u2f(tf32r(v.z)), u2f(tf32r(v.w)));
}

// ---------------------------------------------------------------------------
__global__ void k_zero(int n_nodes) {
    int t0 = n_nodes * F_, t1 = t0 + n_nodes * C_ * 3, t2 = t1 + n_nodes, t3 = t2 + n_nodes;
    for (int i = blockIdx.x * blockDim.x + threadIdx.x; i < t3; i += gridDim.x * blockDim.x) {
        if (i < t0)       g_ef_sum[i] = 0.f;
        else if (i < t1)  g_x_acc[i - t0] = 0.f;
        else if (i < t2)  g_cnt_row[i - t1] = 0.f;
        else              g_cnt_col[i - t2] = 0.f;
    }
}

__global__ void k_prep(const float* __restrict__ x, const float* __restrict__ cw, int N) {
    int n = blockIdx.x * blockDim.x + threadIdx.x;
    if (n >= N) return;
    int s = 0; float px = 0.f, py = 0.f, pz = 0.f;
    #pragma unroll
    for (int i = 0; i < C_; ++i) {
        float w = cw[n * C_ + i];
        if (w != 0.f) {
            s++; px += x[n * 42 + i * 3]; py += x[n * 42 + i * 3 + 1]; pz += x[n * 42 + i * 3 + 2];
        }
    }
    g_csum[n] = s;
    float inv = 1.f / (float)(s > 0 ? s : 1);
    g_pooled[n * 3] = px * inv; g_pooled[n * 3 + 1] = py * inv; g_pooled[n * 3 + 2] = pz * inv;
}

// fragment-major weight images: per (nt, ks, lane): (b0,b1)=(W[k][n], W[k+4][n])
__global__ void k_wprep(const float* __restrict__ e_w1, const float* __restrict__ e_w2,
                        const float* __restrict__ c_w1, const float* __restrict__ c_w2,
                        const float* __restrict__ rad_w, const float* __restrict__ n_w1,
                        const float* __restrict__ n_w2) {
    int t = blockIdx.x * blockDim.x + threadIdx.x;
    if (t >= 82944) return;
    int u = t, base; const float* W; int KST, Ncol;
    if      (u < 24576) { base = WF_E1; W = e_w1; KST = 48; Ncol = 128; }
    else if (u < 32768) { u -= 24576; base = WF_E2; W = e_w2;  KST = 16; Ncol = 128; }
    else if (u < 40960) { u -= 32768; base = WF_C1; W = c_w1;  KST = 16; Ncol = 128; }
    else if (u < 41984) { u -= 40960; base = WF_C2; W = c_w2;  KST = 16; Ncol = 14;  }
    else if (u < 58368) { u -= 41984; base = WF_RW; W = rad_w; KST = 32; Ncol = 128; }
    else if (u < 74752) { u -= 58368; base = WF_N1; W = n_w1;  KST = 32; Ncol = 128; }
    else                { u -= 74752; base = WF_N2; W = n_w2;  KST = 16; Ncol = 128; }
    int lane = u & 31, ks = (u >> 5) % KST, nt = u / (KST * 32);
    int g = lane >> 2, tig = lane & 3;
    int n = nt * 8 + g, k = ks * 8 + tig;
    float b0 = 0.f, b1 = 0.f;
    if (n < Ncol) { b0 = W[k * Ncol + n]; b1 = W[(k + 4) * Ncol + n]; }
    ((float2*)g_wt)[base + u] = make_float2(u2f(tf32r(b0)), u2f(tf32r(b1)));
}

// ---------------------------------------------------------------------------
// K2: radial — SIMT einsum prologue + mma GEMM K=256
// ---------------------------------------------------------------------------
__global__ __launch_bounds__(128) void k_radial(
    const float* __restrict__ x, const float* __restrict__ attr,
    const float* __restrict__ cw, const int* __restrict__ row,
    const int* __restrict__ col, const float* __restrict__ rad_b, int E)
{
    extern __shared__ float sm[];
    float* in_s = sm;                    // [32][260], tf32 bits
    float* wsc  = sm + 32 * S_N;         // 4*1024
    float* inv_norm = wsc + 4 * 1024;    // 32

    int tid = threadIdx.x, lane = tid & 31, w = tid >> 5;
    int g = lane >> 2, tig = lane & 3;
    int e0 = blockIdx.x * TIL;
    float* W = wsc + w * 1024;
    float *s_xr = W, *s_xc = W+48, *s_cwr = W+96, *s_cwc = W+112,
          *s_ar = W+128, *s_ac = W+352, *s_msg = W+576, *s_T = W+772;

    for (int it = 0; it < 8; ++it) {
        int m = it * 4 + w;
        int e = e0 + m; if (e >= E) e = E - 1;
        int r = row[e], c = col[e];
        for (int i = lane; i < 42; i += 32) { s_xr[i] = x[r*42+i]; s_xc[i] = x[c*42+i]; }
        for (int i = lane; i < 14; i += 32) { s_cwr[i] = cw[r*C_+i]; s_cwc[i] = cw[c*C_+i]; }
        for (int i = lane; i < 224; i += 32) { s_ar[i] = attr[r*224+i]; s_ac[i] = attr[c*224+i]; }
        __syncwarp();
        for (int i = lane; i < 196; i += 32) {
            int ci = i / 14, cj = i - ci * 14;
            float dx = s_xr[ci*3]-s_xc[cj*3], dy = s_xr[ci*3+1]-s_xc[cj*3+1],
                  dz = s_xr[ci*3+2]-s_xc[cj*3+2];
            s_msg[i] = sqrtf(dx*dx+dy*dy+dz*dz) * s_cwr[ci] * s_cwc[cj];
        }
        __syncwarp();
        for (int i = lane; i < 224; i += 32) {
            int ci = i >> 4, b = i & 15; float t = 0.f;
            #pragma unroll
            for (int jj = 0; jj < C_; ++jj) t += s_msg[ci*14+jj] * s_ac[jj*16+b];
            s_T[i] = t;
        }
        __syncwarp();
        float ss = 0.f;
        for (int i = lane; i < 256; i += 32) {
            int a = i >> 4, b = i & 15; float t = 0.f;
            #pragma unroll
            for (int jj = 0; jj < C_; ++jj) t += s_ar[jj*16+a] * s_T[jj*16+b];
            in_s[m * S_N + i] = u2f(tf32r(t));
            ss += t * t;
        }
        #pragma unroll
        for (int o = 16; o; o >>= 1) ss += __shfl_xor_sync(0xffffffffu, ss, o);
        if (lane == 0) inv_norm[m] = 1.f / (sqrtf(ss) + 1.f);
        __syncwarp();
    }
    __syncthreads();

    const float2* gw = (const float2*)g_wt;
    float4 d[2][4]; zero_d(d);
    gemm_chunk<S_N>(in_s, gw + WF_RW, w * 4, 0, 32, 32, g, tig, lane, d);

    #pragma unroll
    for (int mt = 0; mt < 2; ++mt)
        #pragma unroll
        for (int nt = 0; nt < 4; ++nt) {
            int f = w * 32 + nt * 8 + 2 * tig;
            float2 rb = *(const float2*)(rad_b + f);
            int e = mt * 16 + g;
            float na = inv_norm[e], nb = inv_norm[e + 8];
            int ea = e0 + e;
            if (ea < E)
                *(float2*)(g_rad + (size_t)ea * F_ + f) =
                    make_float2(u2f(tf32r((d[mt][nt].x + rb.x) * na)),
                                u2f(tf32r((d[mt][nt].y + rb.y) * na)));
            if (ea + 8 < E)
                *(float2*)(g_rad + (size_t)(ea + 8) * F_ + f) =
                    make_float2(u2f(tf32r((d[mt][nt].z + rb.x) * nb)),
                                u2f(tf32r((d[mt][nt].w + rb.y) * nb)));
        }
}

// ---------------------------------------------------------------------------
// K3: fused edge kernel, all GEMMs via mma.sync tf32
// ---------------------------------------------------------------------------
__global__ __launch_bounds__(128) void k_edge(
    const float* __restrict__ h, const float* __restrict__ x,
    const int* __restrict__ row, const int* __restrict__ col,
    const float* __restrict__ e_b1, const float* __restrict__ e_b2,
    const float* __restrict__ att_w, const float* __restrict__ att_b,
    const float* __restrict__ c_b1, const float* __restrict__ c_b2, int E)
{
    extern __shared__ float sm[];
    float* bufA = sm;                    // [32][132]
    float* bufB = bufA + 32 * S_E;       // [32][132]
    float* cm_s = bufB + 32 * S_E;       // [32][16]
    float* gp   = cm_s + 512;            // [4][36]
    float* gate_s = gp + 144;            // [32]
    int* s_row = (int*)(gate_s + 32);
    int* s_col = s_row + 32;
    int* s_cs  = s_col + 32;

    int tid = threadIdx.x, lane = tid & 31, w = tid >> 5;
    int g = lane >> 2, tig = lane & 3, nt0 = w * 4;
    int e0 = blockIdx.x * TIL;
    const float2* gw = (const float2*)g_wt;

    if (tid < TIL) {
        int e = e0 + tid; if (e >= E) e = E - 1;
        int r = row[e];
        s_row[tid] = r; s_col[tid] = col[e]; s_cs[tid] = g_csum[r];
    }
    __syncthreads();

    // ---- GEMM1: K=384 in 3 chunks ----
    float4 d[2][4]; zero_d(d);
    for (int r = 0; r < 3; ++r) {
        for (int i = tid; i < 1024; i += 128) {
            int e = i >> 5, q = i & 31;
            float4 v;
            if (r == 0)      v = cvt4(*(const float4*)(h + (size_t)s_row[e] * F_ + q * 4));
            else if (r == 1) v = cvt4(*(const float4*)(h + (size_t)s_col[e] * F_ + q * 4));
            else {
                int eg = e0 + e; if (eg >= E) eg = E - 1;
                v = *(const float4*)(g_rad + (size_t)eg * F_ + q * 4);
            }
            *(float4*)(bufA + e * S_E + q * 4) = v;
        }
        __syncthreads();
        gemm_chunk<S_E>(bufA, gw + WF_E1, nt0, r * 16, 16, 48, g, tig, lane, d);
        __syncthreads();
    }

    // ep1: t1 = silu(D + e_b1) -> bufB
    #pragma unroll
    for (int mt = 0; mt < 2; ++mt)
        #pragma unroll
        for (int nt = 0; nt < 4; ++nt) {
            int f = w * 32 + nt * 8 + 2 * tig;
            float2 bb = *(const float2*)(e_b1 + f);
            store_frag(bufB, S_E, g, f, mt,
                make_float4(silu_(d[mt][nt].x + bb.x), silu_(d[mt][nt].y + bb.y),
                            silu_(d[mt][nt].z + bb.x), silu_(d[mt][nt].w + bb.y)));
        }
    __syncthreads();

    // ---- GEMM2 ----
    zero_d(d);
    gemm_chunk<S_E>(bufB, gw + WF_E2, nt0, 0, 16, 16, g, tig, lane, d);

    // ep2: t2 = silu(+e_b2); gate; ef -> bufA + atomics
    {
        float p[4] = {0.f, 0.f, 0.f, 0.f};
        #pragma unroll
        for (int mt = 0; mt < 2; ++mt)
            #pragma unroll
            for (int nt = 0; nt < 4; ++nt) {
                int f = w * 32 + nt * 8 + 2 * tig;
                float2 bb = *(const float2*)(e_b2 + f);
                float2 aw = *(const float2*)(att_w + f);
                float c0 = silu_(d[mt][nt].x + bb.x), c1 = silu_(d[mt][nt].y + bb.y);
                float c2 = silu_(d[mt][nt].z + bb.x), c3 = silu_(d[mt][nt].w + bb.y);
                d[mt][nt] = make_float4(c0, c1, c2, c3);
                p[mt * 2 + 0] += c0 * aw.x + c1 * aw.y;
                p[mt * 2 + 1] += c2 * aw.x + c3 * aw.y;
            }
        #pragma unroll
        for (int o = 1; o <= 2; o <<= 1)
            #pragma unroll
            for (int q = 0; q < 4; ++q) p[q] += __shfl_xor_sync(0xffffffffu, p[q], o);
        if (tig == 0) {
            gp[w * 36 + g]      = p[0];
            gp[w * 36 + g + 8]  = p[1];
            gp[w * 36 + g + 16] = p[2];
            gp[w * 36 + g + 24] = p[3];
        }
    }
    __syncthreads();
    if (tid < TIL)
        gate_s[tid] = sigm_(gp[tid] + gp[36 + tid] + gp[72 + tid] + gp[108 + tid]
                            + __ldg(att_b));
    __syncthreads();
    #pragma unroll
    for (int mt = 0; mt < 2; ++mt) {
        int ea = mt * 16 + g, eb = ea + 8;
        float ga = gate_s[ea], gb = gate_s[eb];
        #pragma unroll
        for (int nt = 0; nt < 4; ++nt) {
            int f = w * 32 + nt * 8 + 2 * tig;
            float c0 = d[mt][nt].x * ga, c1 = d[mt][nt].y * ga;
            float c2 = d[mt][nt].z * gb, c3 = d[mt][nt].w * gb;
            store_frag(bufA, S_E, g, f, mt, make_float4(c0, c1, c2, c3));
            if (e0 + ea < E) {
                float* dst = g_ef_sum + (size_t)s_col[ea] * F_ + f;
                atomicAdd(dst, c0); atomicAdd(dst + 1, c1);
            }
            if (e0 + eb < E) {
                float* dst = g_ef_sum + (size_t)s_col[eb] * F_ + f;
                atomicAdd(dst, c2); atomicAdd(dst + 1, c3);
            }
        }
    }
    if (tid < TIL && e0 + tid < E) {
        atomicAdd(&g_cnt_col[s_col[tid]], 1.f);
        atomicAdd(&g_cnt_row[s_row[tid]], 1.f);
    }
    __syncthreads();

    // ---- GEMM3 ----
    zero_d(d);
    gemm_chunk<S_E>(bufA, gw + WF_C1, nt0, 0, 16, 16, g, tig, lane, d);
    #pragma unroll
    for (int mt = 0; mt < 2; ++mt)
        #pragma unroll
        for (int nt = 0; nt < 4; ++nt) {
            int f = w * 32 + nt * 8 + 2 * tig;
            float2 bb = *(const float2*)(c_b1 + f);
            store_frag(bufB, S_E, g, f, mt,
                make_float4(silu_(d[mt][nt].x + bb.x), silu_(d[mt][nt].y + bb.y),
                            silu_(d[mt][nt].z + bb.x), silu_(d[mt][nt].w + bb.y)));
        }
    __syncthreads();

    // ---- GEMM4: c_w2 (N=16, warps 0-1) ----
    if (w < 2) {
        float4 dc[2] = {make_float4(0,0,0,0), make_float4(0,0,0,0)};
        #pragma unroll 4
        for (int ks = 0; ks < 16; ++ks) {
            int k0 = ks * 8;
            float2 b = gw[WF_C2 + ((size_t)w * 16 + ks) * 32 + lane];
            u32 b0 = __float_as_uint(b.x), b1 = __float_as_uint(b.y);
            #pragma unroll
            for (int mt = 0; mt < 2; ++mt) {
                const float* r0 = bufB + (mt * 16 + g) * S_E + k0;
                const float* r1 = bufB + (mt * 16 + g + 8) * S_E + k0;
                mma8(dc[mt], __float_as_uint(r0[tig]), __float_as_uint(r1[tig]),
                     __float_as_uint(r0[tig + 4]), __float_as_uint(r1[tig + 4]), b0, b1);
            }
        }
        int o = w * 8 + 2 * tig;
        float cbx = (o < 14)     ? __ldg(c_b2 + o)     : 0.f;
        float cby = (o + 1 < 14) ? __ldg(c_b2 + o + 1) : 0.f;
        #pragma unroll
        for (int mt = 0; mt < 2; ++mt) {
            *(float2*)(cm_s + (mt * 16 + g) * 16 + o) =
                make_float2(dc[mt].x + cbx, dc[mt].y + cby);
            *(float2*)(cm_s + (mt * 16 + g + 8) * 16 + o) =
                make_float2(dc[mt].z + cbx, dc[mt].w + cby);
        }
    }
    __syncthreads();

    // ---- roller pooling + x scatter ----
    for (int idx = tid; idx < TIL * 42; idx += 128) {
        int m = idx / 42, rem = idx - m * 42;
        int e = e0 + m;
        if (e < E) {
            int i = rem / 3, dd = rem - i * 3;
            int ws = 15 - s_cs[m];
            if (ws < 1)  ws = 1;
            if (ws > 14) ws = 14;
            int end = i + ws; if (end > 14) end = 14;
            float ps = 0.f;
            for (int q = i; q < end; ++q) ps += cm_s[m * 16 + q];
            float pooled = ps / (float)ws;
            float cd = x[(size_t)s_row[m] * 42 + rem] - g_pooled[s_col[m] * 3 + dd];
            atomicAdd(&g_x_acc[(size_t)s_row[m] * 42 + rem], cd * pooled);
        }
    }
}

// ---------------------------------------------------------------------------
// K4: node update via mma
// ---------------------------------------------------------------------------
__global__ __launch_bounds__(128) void k_node(
    const float* __restrict__ h, const float* __restrict__ x,
    const float* __restrict__ n_b1, const float* __restrict__ n_b2,
    const float* __restrict__ ln_g, const float* __restrict__ ln_b,
    float* __restrict__ out, int N)
{
    extern __shared__ float sm[];
    float* in_s = sm;                    // [32][260]
    float* bufB = in_s + 32 * S_N;       // [32][132]
    float* gp1  = bufB + 32 * S_E;       // [4][36]
    float* gp2  = gp1 + 144;
    float* mu_s = gp2 + 144;             // [32]
    float* rs_s = mu_s + 32;
    float* ic_s = rs_s + 32;

    int tid = threadIdx.x, lane = tid & 31, w = tid >> 5;
    int g = lane >> 2, tig = lane & 3, nt0 = w * 4;
    int n0 = blockIdx.x * TIL;
    const float2* gw = (const float2*)g_wt;

    if (tid < TIL) {
        int n = n0 + tid;
        float c = (n < N) ? g_cnt_col[n] : 1.f;
        ic_s[tid] = 1.f / fmaxf(c, 1.f);
    }
    __syncthreads();

    for (int i = tid; i < 2048; i += 128) {
        int e = i >> 6, q = i & 63;
        int n = n0 + e; if (n >= N) n = N - 1;
        float4 v;
        if (q < 32) v = *(const float4*)(h + (size_t)n * F_ + q * 4);
        else {
            v = *(const float4*)(g_ef_sum + (size_t)n * F_ + (q - 32) * 4);
            float ic = ic_s[e];
            v = make_float4(v.x * ic, v.y * ic, v.z * ic, v.w * ic);
        }
        *(float4*)(in_s + e * S_N + q * 4) = cvt4(v);
    }
    __syncthreads();

    float4 d[2][4]; zero_d(d);
    gemm_chunk<S_N>(in_s, gw + WF_N1, nt0, 0, 32, 32, g, tig, lane, d);
    #pragma unroll
    for (int mt = 0; mt < 2; ++mt)
        #pragma unroll
        for (int nt = 0; nt < 4; ++nt) {
            int f = w * 32 + nt * 8 + 2 * tig;
            float2 bb = *(const float2*)(n_b1 + f);
            store_frag(bufB, S_E, g, f, mt,
                make_float4(silu_(d[mt][nt].x + bb.x), silu_(d[mt][nt].y + bb.y),
                            silu_(d[mt][nt].z + bb.x), silu_(d[mt][nt].w + bb.y)));
        }
    __syncthreads();

    zero_d(d);
    gemm_chunk<S_E>(bufB, gw + WF_N2, nt0, 0, 16, 16, g, tig, lane, d);

    // hr = h + D + n_b2 (residual from gmem, full precision); LN partials
    {
        float p1[4] = {0,0,0,0}, p2[4] = {0,0,0,0};
        #pragma unroll
        for (int mt = 0; mt < 2; ++mt) {
            int na = n0 + mt * 16 + g, nb = na + 8;
            if (na >= N) na = N - 1;
            if (nb >= N) nb = N - 1;
            #pragma unroll
            for (int nt = 0; nt < 4; ++nt) {
                int f = w * 32 + nt * 8 + 2 * tig;
                float2 bb = *(const float2*)(n_b2 + f);
                float2 ra = *(const float2*)(h + (size_t)na * F_ + f);
                float2 rb = *(const float2*)(h + (size_t)nb * F_ + f);
                float h0 = ra.x + d[mt][nt].x + bb.x, h1 = ra.y + d[mt][nt].y + bb.y;
                float h2 = rb.x + d[mt][nt].z + bb.x, h3 = rb.y + d[mt][nt].w + bb.y;
                d[mt][nt] = make_float4(h0, h1, h2, h3);
                p1[mt*2]   += h0 + h1;  p2[mt*2]   += h0*h0 + h1*h1;
                p1[mt*2+1] += h2 + h3;  p2[mt*2+1] += h2*h2 + h3*h3;
            }
        }
        #pragma unroll
        for (int o = 1; o <= 2; o <<= 1)
            #pragma unroll
            for (int q = 0; q < 4; ++q) {
                p1[q] += __shfl_xor_sync(0xffffffffu, p1[q], o);
                p2[q] += __shfl_xor_sync(0xffffffffu, p2[q], o);
            }
        if (tig == 0) {
            #pragma unroll
            for (int q = 0; q < 4; ++q) {
                int e = (q >> 1) * 16 + g + (q & 1) * 8;
                gp1[w * 36 + e] = p1[q];
                gp2[w * 36 + e] = p2[q];
            }
        }
    }
    __syncthreads();
    if (tid < TIL) {
        float s1 = gp1[tid] + gp1[36 + tid] + gp1[72 + tid] + gp1[108 + tid];
        float s2 = gp2[tid] + gp2[36 + tid] + gp2[72 + tid] + gp2[108 + tid];
        float mu = s1 * (1.f / 128.f);
        float var = fmaxf(s2 * (1.f / 128.f) - mu * mu, 0.f);
        mu_s[tid] = mu;
        rs_s[tid] = rsqrtf(var + 1e-5f);
    }
    __syncthreads();

    #pragma unroll
    for (int mt = 0; mt < 2; ++mt) {
        int ea = mt * 16 + g, eb = ea + 8;
        int na = n0 + ea, nb = n0 + eb;
        float mua = mu_s[ea], rsa = rs_s[ea];
        float mub = mu_s[eb], rsb = rs_s[eb];
        #pragma unroll
        for (int nt = 0; nt < 4; ++nt) {
            int f = w * 32 + nt * 8 + 2 * tig;
            float2 gv = *(const float2*)(ln_g + f);
            float2 bv = *(const float2*)(ln_b + f);
            if (na < N)
                *(float2*)(out + (size_t)na * F_ + f) = make_float2(
                    (d[mt][nt].x - mua) * rsa * gv.x + bv.x,
                    (d[mt][nt].y - mua) * rsa * gv.y + bv.y);
            if (nb < N)
                *(float2*)(out + (size_t)nb * F_ + f) = make_float2(
                    (d[mt][nt].z - mub) * rsb * gv.x + bv.x,
                    (d[mt][nt].w - mub) * rsb * gv.y + bv.y);
        }
    }

    float* out_x = out + (size_t)N * F_;
    for (int idx = tid; idx < TIL * 42; idx += 128) {
        int m = idx / 42, rem = idx - m * 42;
        int n = n0 + m;
        if (n < N)
            out_x[(size_t)n * 42 + rem] = x[(size_t)n * 42 + rem] +
                g_x_acc[(size_t)n * 42 + rem] / fmaxf(g_cnt_row[n], 1.f);
    }
}

// ---------------------------------------------------------------------------
extern "C" void kernel_launch(void* const* d_in, const int* in_sizes, int n_in,
                              void* d_out, int out_size) {
    const float* h     = (const float*)d_in[0];
    const float* x     = (const float*)d_in[1];
    const float* attr  = (const float*)d_in[2];
    const float* cw    = (const float*)d_in[3];
    const int*   row   = (const int*)d_in[4];
    const int*   col   = (const int*)d_in[5];
    const float* rad_w = (const float*)d_in[6];
    const float* rad_b = (const float*)d_in[7];
    const float* e_w1  = (const float*)d_in[8];
    const float* e_b1  = (const float*)d_in[9];
    const float* e_w2  = (const float*)d_in[10];
    const float* e_b2  = (const float*)d_in[11];
    const float* att_w = (const float*)d_in[12];
    const float* att_b = (const float*)d_in[13];
    const float* c_w1  = (const float*)d_in[14];
    const float* c_b1  = (const float*)d_in[15];
    const float* c_w2  = (const float*)d_in[16];
    const float* c_b2  = (const float*)d_in[17];
    const float* n_w1  = (const float*)d_in[18];
    const float* n_b1  = (const float*)d_in[19];
    const float* n_w2  = (const float*)d_in[20];
    const float* n_b2  = (const float*)d_in[21];
    const float* ln_g  = (const float*)d_in[22];
    const float* ln_b  = (const float*)d_in[23];
    (void)c_b1;

    int N = in_sizes[0] / F_;
    int E = in_sizes[4];

    const int SMEM_R = (32 * S_N + 4 * 1024 + 32) * 4;
    const int SMEM_E = (2 * 32 * S_E + 512 + 144 + 32) * 4 + 96 * 4;
    const int SMEM_N = (32 * S_N + 32 * S_E + 144 + 144 + 32 + 32 + 32) * 4;

    cudaFuncSetAttribute(k_radial, cudaFuncAttributeMaxDynamicSharedMemorySize, SMEM_R);
    cudaFuncSetAttribute(k_edge,   cudaFuncAttributeMaxDynamicSharedMemorySize, SMEM_E);
    cudaFuncSetAttribute(k_node,   cudaFuncAttributeMaxDynamicSharedMemorySize, SMEM_N);

    k_zero<<<256, 256>>>(N);
    k_prep<<<(N + 255) / 256, 256>>>(x, cw, N);
    k_wprep<<<324, 256>>>(e_w1, e_w2, c_w1, c_w2, rad_w, n_w1, n_w2);
    k_radial<<<(E + TIL - 1) / TIL, 128, SMEM_R>>>(x, attr, cw, row, col, rad_b, E);
    k_edge<<<(E + TIL - 1) / TIL, 128, SMEM_E>>>(h, x, row, col, e_b1, e_b2,
                                                 att_w, att_b, c_b1, c_b2, E);
    k_node<<<(N + TIL - 1) / TIL, 128, SMEM_N>>>(h, x, n_b1, n_b2,
                                                 ln_g, ln_b, (float*)d_out, N);
}

// round 7
// speedup vs baseline: 3.3478x; 1.0845x over previous
#include <cuda_runtime.h>

#define NMAX 20000
#define EMAX 200000
#define C_   14
#define F_   128
#define TIL  32
#define S_E  132
#define S_N  260

typedef unsigned int u32;

// ---- scratch ----
__device__ __align__(16) float g_rad [(size_t)EMAX * F_];   // row-major [E][128], tf32 bits
__device__ __align__(16) float g_wt  [165888];              // fragment-major weights (tf32)
__device__ float g_ef_sum[(size_t)NMAX * F_];
__device__ float g_x_acc [(size_t)NMAX * C_ * 3];
__device__ float g_cnt_row[NMAX];
__device__ float g_cnt_col[NMAX];
__device__ float g_pooled [NMAX * 3];
__device__ int   g_csum   [NMAX];

// fragment-image offsets in float2 units
#define WF_E1 0
#define WF_E2 24576
#define WF_C1 32768
#define WF_C2 40960
#define WF_RW 41984
#define WF_N1 58368
#define WF_N2 74752

__device__ __forceinline__ float sigm_(float v) { return 1.f / (1.f + __expf(-v)); }
__device__ __forceinline__ float silu_(float v) { return v * sigm_(v); }
__device__ __forceinline__ u32 tf32r(float v) {
    u32 r; asm("cvt.rna.tf32.f32 %0, %1;" : "=r"(r) : "f"(v)); return r;
}
__device__ __forceinline__ float u2f(u32 v) { return __uint_as_float(v); }
__device__ __forceinline__ float4 cvt4(float4 v) {
    return make_float4(u2f(tf32r(v.x)), u2f(tf32r(v.y)), u2f(tf32r(v.z)), u2f(tf32r(v.w)));
}

// mma.sync m16n8k8 tf32: D += A*B
__device__ __forceinline__ void mma8(float4& d, u32 a0, u32 a1, u32 a2, u32 a3,
                                     u32 b0, u32 b1) {
    asm volatile(
        "mma.sync.aligned.m16n8k8.row.col.f32.tf32.tf32.f32 "
        "{%0,%1,%2,%3},{%4,%5,%6,%7},{%8,%9},{%0,%1,%2,%3};"
        : "+f"(d.x), "+f"(d.y), "+f"(d.z), "+f"(d.w)
        : "r"(a0), "r"(a1), "r"(a2), "r"(a3), "r"(b0), "r"(b1));
}

template<int S>
__device__ __forceinline__ void gemm_chunk(const float* in_s, const float2* wf,
                                           int nt0, int ks0, int nks, int KST,
                                           int g, int tig, int lane, float4 d[2][4])
{
    #pragma unroll 4
    for (int ks = 0; ks < nks; ++ks) {
        int k0 = ks * 8;
        u32 a[2][4];
        #pragma unroll
        for (int mt = 0; mt < 2; ++mt) {
            const float* r0 = in_s + (mt * 16 + g) * S + k0;
            const float* r1 = in_s + (mt * 16 + g + 8) * S + k0;
            a[mt][0] = __float_as_uint(r0[tig]);
            a[mt][1] = __float_as_uint(r1[tig]);
            a[mt][2] = __float_as_uint(r0[tig + 4]);
            a[mt][3] = __float_as_uint(r1[tig + 4]);
        }
        #pragma unroll
        for (int nt = 0; nt < 4; ++nt) {
            float2 b = wf[((size_t)(nt0 + nt) * KST + ks0 + ks) * 32 + lane];
            u32 b0 = __float_as_uint(b.x), b1 = __float_as_uint(b.y);
            mma8(d[0][nt], a[0][0], a[0][1], a[0][2], a[0][3], b0, b1);
            mma8(d[1][nt], a[1][0], a[1][1], a[1][2], a[1][3], b0, b1);
        }
    }
}

__device__ __forceinline__ void zero_d(float4 d[2][4]) {
    #pragma unroll
    for (int mt = 0; mt < 2; ++mt)
        #pragma unroll
        for (int nt = 0; nt < 4; ++nt) d[mt][nt] = make_float4(0.f, 0.f, 0.f, 0.f);
}

__device__ __forceinline__ void store_frag(float* buf, int S, int g, int f, int mt,
                                           float4 v) {
    *(float2*)(buf + (mt * 16 + g) * S + f) =
        make_float2(u2f(tf32r(v.x)), u2f(tf32r(v.y)));
    *(float2*)(buf + (mt * 16 + g + 8) * S + f) =
        make_float2(u2f(tf32r(v.z)), u2f(tf32r(v.w)));
}

// ---------------------------------------------------------------------------
__global__ void k_zero(int n_nodes) {
    int t0 = n_nodes * F_, t1 = t0 + n_nodes * C_ * 3, t2 = t1 + n_nodes, t3 = t2 + n_nodes;
    for (int i = blockIdx.x * blockDim.x + threadIdx.x; i < t3; i += gridDim.x * blockDim.x) {
        if (i < t0)       g_ef_sum[i] = 0.f;
        else if (i < t1)  g_x_acc[i - t0] = 0.f;
        else if (i < t2)  g_cnt_row[i - t1] = 0.f;
        else              g_cnt_col[i - t2] = 0.f;
    }
}

__global__ void k_prep(const float* __restrict__ x, const float* __restrict__ cw, int N) {
    int n = blockIdx.x * blockDim.x + threadIdx.x;
    if (n >= N) return;
    int s = 0; float px = 0.f, py = 0.f, pz = 0.f;
    #pragma unroll
    for (int i = 0; i < C_; ++i) {
        float w = cw[n * C_ + i];
        if (w != 0.f) {
            s++; px += x[n * 42 + i * 3]; py += x[n * 42 + i * 3 + 1]; pz += x[n * 42 + i * 3 + 2];
        }
    }
    g_csum[n] = s;
    float inv = 1.f / (float)(s > 0 ? s : 1);
    g_pooled[n * 3] = px * inv; g_pooled[n * 3 + 1] = py * inv; g_pooled[n * 3 + 2] = pz * inv;
}

__global__ void k_wprep(const float* __restrict__ e_w1, const float* __restrict__ e_w2,
                        const float* __restrict__ c_w1, const float* __restrict__ c_w2,
                        const float* __restrict__ rad_w, const float* __restrict__ n_w1,
                        const float* __restrict__ n_w2) {
    int t = blockIdx.x * blockDim.x + threadIdx.x;
    if (t >= 82944) return;
    int u = t, base; const float* W; int KST, Ncol;
    if      (u < 24576) { base = WF_E1; W = e_w1; KST = 48; Ncol = 128; }
    else if (u < 32768) { u -= 24576; base = WF_E2; W = e_w2;  KST = 16; Ncol = 128; }
    else if (u < 40960) { u -= 32768; base = WF_C1; W = c_w1;  KST = 16; Ncol = 128; }
    else if (u < 41984) { u -= 40960; base = WF_C2; W = c_w2;  KST = 16; Ncol = 14;  }
    else if (u < 58368) { u -= 41984; base = WF_RW; W = rad_w; KST = 32; Ncol = 128; }
    else if (u < 74752) { u -= 58368; base = WF_N1; W = n_w1;  KST = 32; Ncol = 128; }
    else                { u -= 74752; base = WF_N2; W = n_w2;  KST = 16; Ncol = 128; }
    int lane = u & 31, ks = (u >> 5) % KST, nt = u / (KST * 32);
    int g = lane >> 2, tig = lane & 3;
    int n = nt * 8 + g, k = ks * 8 + tig;
    float b0 = 0.f, b1 = 0.f;
    if (n < Ncol) { b0 = W[k * Ncol + n]; b1 = W[(k + 4) * Ncol + n]; }
    ((float2*)g_wt)[base + u] = make_float2(u2f(tf32r(b0)), u2f(tf32r(b1)));
}

// ---------------------------------------------------------------------------
// K2: radial — mma-based einsum prologue + mma GEMM K=256
// per-warp scratch (floats): msg[16*17]=272, T[16*17]=272, xr 48, xc 48,
// cwr 16, cwc 16, ar 224, ac 224  -> 1120
// ---------------------------------------------------------------------------
#define WSC 1120
__global__ __launch_bounds__(128) void k_radial(
    const float* __restrict__ x, const float* __restrict__ attr,
    const float* __restrict__ cw, const int* __restrict__ row,
    const int* __restrict__ col, const float* __restrict__ rad_b, int E)
{
    extern __shared__ float sm[];
    float* in_s = sm;                    // [32][260], tf32 bits
    float* wsc  = sm + 32 * S_N;         // 4*WSC
    float* inv_norm = wsc + 4 * WSC;     // 32

    int tid = threadIdx.x, lane = tid & 31, w = tid >> 5;
    int g = lane >> 2, tig = lane & 3;
    int e0 = blockIdx.x * TIL;

    float* W = wsc + w * WSC;
    float *s_msg = W, *s_T = W + 272, *s_xr = W + 544, *s_xc = W + 592,
          *s_cwr = W + 640, *s_cwc = W + 656, *s_ar = W + 672, *s_ac = W + 896;

    for (int it = 0; it < 8; ++it) {
        int m = w * 8 + it;
        int e = e0 + m; if (e >= E) e = E - 1;
        int r = row[e], c = col[e];

        for (int i = lane; i < 48; i += 32) {
            s_xr[i] = (i < 42) ? x[r * 42 + i] : 0.f;
            s_xc[i] = (i < 42) ? x[c * 42 + i] : 0.f;
        }
        if (lane < 16) {
            s_cwr[lane] = (lane < 14) ? cw[r * C_ + lane] : 0.f;
            s_cwc[lane] = (lane < 14) ? cw[c * C_ + lane] : 0.f;
        }
        for (int i = lane; i < 224; i += 32) {
            s_ar[i] = attr[r * 224 + i];
            s_ac[i] = attr[c * 224 + i];
        }
        __syncwarp();

        // msg[ci][cj] (16x16, rows/cols >=14 are zero via cw=0, x padded 0)
        #pragma unroll
        for (int q = 0; q < 8; ++q) {
            int i = q * 32 + lane;
            int ci = i >> 4, cj = i & 15;
            float dx = s_xr[ci * 3] - s_xc[cj * 3];
            float dy = s_xr[ci * 3 + 1] - s_xc[cj * 3 + 1];
            float dz = s_xr[ci * 3 + 2] - s_xc[cj * 3 + 2];
            s_msg[ci * 17 + cj] =
                sqrtf(dx * dx + dy * dy + dz * dz) * s_cwr[ci] * s_cwc[cj];
        }
        __syncwarp();

        // T = msg @ ac  (mma, 2 k-chunks x 2 n-tiles)
        float4 dT[2] = {make_float4(0,0,0,0), make_float4(0,0,0,0)};
        #pragma unroll
        for (int kk = 0; kk < 2; ++kk) {
            int k0 = kk * 8 + tig, k1 = k0 + 4;
            u32 a0 = tf32r(s_msg[g * 17 + k0]);
            u32 a1 = tf32r(s_msg[(g + 8) * 17 + k0]);
            u32 a2 = tf32r(s_msg[g * 17 + k1]);
            u32 a3 = tf32r(s_msg[(g + 8) * 17 + k1]);
            #pragma unroll
            for (int nt = 0; nt < 2; ++nt) {
                float b0f = (k0 < 14) ? s_ac[k0 * 16 + nt * 8 + g] : 0.f;
                float b1f = (k1 < 14) ? s_ac[k1 * 16 + nt * 8 + g] : 0.f;
                mma8(dT[nt], a0, a1, a2, a3, tf32r(b0f), tf32r(b1f));
            }
        }
        // store T fragments (tf32 bits)
        #pragma unroll
        for (int nt = 0; nt < 2; ++nt) {
            int fc = nt * 8 + 2 * tig;
            s_T[g * 17 + fc]           = u2f(tf32r(dT[nt].x));
            s_T[g * 17 + fc + 1]       = u2f(tf32r(dT[nt].y));
            s_T[(g + 8) * 17 + fc]     = u2f(tf32r(dT[nt].z));
            s_T[(g + 8) * 17 + fc + 1] = u2f(tf32r(dT[nt].w));
        }
        __syncwarp();

        // R = ar^T @ T  (mma)
        float4 dR[2] = {make_float4(0,0,0,0), make_float4(0,0,0,0)};
        #pragma unroll
        for (int kk = 0; kk < 2; ++kk) {
            int k0 = kk * 8 + tig, k1 = k0 + 4;
            u32 a0 = tf32r(s_ar[k0 * 16 + g]);        // k0 <= 11 always valid
            u32 a1 = tf32r(s_ar[k0 * 16 + g + 8]);
            u32 a2 = tf32r((k1 < 14) ? s_ar[k1 * 16 + g] : 0.f);
            u32 a3 = tf32r((k1 < 14) ? s_ar[k1 * 16 + g + 8] : 0.f);
            #pragma unroll
            for (int nt = 0; nt < 2; ++nt) {
                u32 b0 = __float_as_uint(s_T[k0 * 17 + nt * 8 + g]);
                u32 b1 = __float_as_uint(s_T[k1 * 17 + nt * 8 + g]);
                mma8(dR[nt], a0, a1, a2, a3, b0, b1);
            }
        }

        // norm + store R into in_s row m (tf32 bits)
        float ss = dR[0].x*dR[0].x + dR[0].y*dR[0].y + dR[0].z*dR[0].z + dR[0].w*dR[0].w
                 + dR[1].x*dR[1].x + dR[1].y*dR[1].y + dR[1].z*dR[1].z + dR[1].w*dR[1].w;
        #pragma unroll
        for (int o = 16; o; o >>= 1) ss += __shfl_xor_sync(0xffffffffu, ss, o);
        if (lane == 0) inv_norm[m] = 1.f / (sqrtf(ss) + 1.f);

        #pragma unroll
        for (int nt = 0; nt < 2; ++nt) {
            int fc = nt * 8 + 2 * tig;
            *(float2*)(in_s + m * S_N + g * 16 + fc) =
                make_float2(u2f(tf32r(dR[nt].x)), u2f(tf32r(dR[nt].y)));
            *(float2*)(in_s + m * S_N + (g + 8) * 16 + fc) =
                make_float2(u2f(tf32r(dR[nt].z)), u2f(tf32r(dR[nt].w)));
        }
        __syncwarp();
    }
    __syncthreads();

    const float2* gw = (const float2*)g_wt;
    float4 d[2][4]; zero_d(d);
    gemm_chunk<S_N>(in_s, gw + WF_RW, w * 4, 0, 32, 32, g, tig, lane, d);

    #pragma unroll
    for (int mt = 0; mt < 2; ++mt)
        #pragma unroll
        for (int nt = 0; nt < 4; ++nt) {
            int f = w * 32 + nt * 8 + 2 * tig;
            float2 rb = *(const float2*)(rad_b + f);
            int e = mt * 16 + g;
            float na = inv_norm[e], nb = inv_norm[e + 8];
            int ea = e0 + e;
            if (ea < E)
                *(float2*)(g_rad + (size_t)ea * F_ + f) =
                    make_float2(u2f(tf32r((d[mt][nt].x + rb.x) * na)),
                                u2f(tf32r((d[mt][nt].y + rb.y) * na)));
            if (ea + 8 < E)
                *(float2*)(g_rad + (size_t)(ea + 8) * F_ + f) =
                    make_float2(u2f(tf32r((d[mt][nt].z + rb.x) * nb)),
                                u2f(tf32r((d[mt][nt].w + rb.y) * nb)));
        }
}

// ---------------------------------------------------------------------------
// K3: fused edge kernel (unchanged from passing Round-6)
// ---------------------------------------------------------------------------
__global__ __launch_bounds__(128) void k_edge(
    const float* __restrict__ h, const float* __restrict__ x,
    const int* __restrict__ row, const int* __restrict__ col,
    const float* __restrict__ e_b1, const float* __restrict__ e_b2,
    const float* __restrict__ att_w, const float* __restrict__ att_b,
    const float* __restrict__ c_b1, const float* __restrict__ c_b2, int E)
{
    extern __shared__ float sm[];
    float* bufA = sm;
    float* bufB = bufA + 32 * S_E;
    float* cm_s = bufB + 32 * S_E;
    float* gp   = cm_s + 512;
    float* gate_s = gp + 144;
    int* s_row = (int*)(gate_s + 32);
    int* s_col = s_row + 32;
    int* s_cs  = s_col + 32;

    int tid = threadIdx.x, lane = tid & 31, w = tid >> 5;
    int g = lane >> 2, tig = lane & 3, nt0 = w * 4;
    int e0 = blockIdx.x * TIL;
    const float2* gw = (const float2*)g_wt;

    if (tid < TIL) {
        int e = e0 + tid; if (e >= E) e = E - 1;
        int r = row[e];
        s_row[tid] = r; s_col[tid] = col[e]; s_cs[tid] = g_csum[r];
    }
    __syncthreads();

    float4 d[2][4]; zero_d(d);
    for (int r = 0; r < 3; ++r) {
        for (int i = tid; i < 1024; i += 128) {
            int e = i >> 5, q = i & 31;
            float4 v;
            if (r == 0)      v = cvt4(*(const float4*)(h + (size_t)s_row[e] * F_ + q * 4));
            else if (r == 1) v = cvt4(*(const float4*)(h + (size_t)s_col[e] * F_ + q * 4));
            else {
                int eg = e0 + e; if (eg >= E) eg = E - 1;
                v = *(const float4*)(g_rad + (size_t)eg * F_ + q * 4);
            }
            *(float4*)(bufA + e * S_E + q * 4) = v;
        }
        __syncthreads();
        gemm_chunk<S_E>(bufA, gw + WF_E1, nt0, r * 16, 16, 48, g, tig, lane, d);
        __syncthreads();
    }

    #pragma unroll
    for (int mt = 0; mt < 2; ++mt)
        #pragma unroll
        for (int nt = 0; nt < 4; ++nt) {
            int f = w * 32 + nt * 8 + 2 * tig;
            float2 bb = *(const float2*)(e_b1 + f);
            store_frag(bufB, S_E, g, f, mt,
                make_float4(silu_(d[mt][nt].x + bb.x), silu_(d[mt][nt].y + bb.y),
                            silu_(d[mt][nt].z + bb.x), silu_(d[mt][nt].w + bb.y)));
        }
    __syncthreads();

    zero_d(d);
    gemm_chunk<S_E>(bufB, gw + WF_E2, nt0, 0, 16, 16, g, tig, lane, d);

    {
        float p[4] = {0.f, 0.f, 0.f, 0.f};
        #pragma unroll
        for (int mt = 0; mt < 2; ++mt)
            #pragma unroll
            for (int nt = 0; nt < 4; ++nt) {
                int f = w * 32 + nt * 8 + 2 * tig;
                float2 bb = *(const float2*)(e_b2 + f);
                float2 aw = *(const float2*)(att_w + f);
                float c0 = silu_(d[mt][nt].x + bb.x), c1 = silu_(d[mt][nt].y + bb.y);
                float c2 = silu_(d[mt][nt].z + bb.x), c3 = silu_(d[mt][nt].w + bb.y);
                d[mt][nt] = make_float4(c0, c1, c2, c3);
                p[mt * 2 + 0] += c0 * aw.x + c1 * aw.y;
                p[mt * 2 + 1] += c2 * aw.x + c3 * aw.y;
            }
        #pragma unroll
        for (int o = 1; o <= 2; o <<= 1)
            #pragma unroll
            for (int q = 0; q < 4; ++q) p[q] += __shfl_xor_sync(0xffffffffu, p[q], o);
        if (tig == 0) {
            gp[w * 36 + g]      = p[0];
            gp[w * 36 + g + 8]  = p[1];
            gp[w * 36 + g + 16] = p[2];
            gp[w * 36 + g + 24] = p[3];
        }
    }
    __syncthreads();
    if (tid < TIL)
        gate_s[tid] = sigm_(gp[tid] + gp[36 + tid] + gp[72 + tid] + gp[108 + tid]
                            + __ldg(att_b));
    __syncthreads();
    #pragma unroll
    for (int mt = 0; mt < 2; ++mt) {
        int ea = mt * 16 + g, eb = ea + 8;
        float ga = gate_s[ea], gb = gate_s[eb];
        #pragma unroll
        for (int nt = 0; nt < 4; ++nt) {
            int f = w * 32 + nt * 8 + 2 * tig;
            float c0 = d[mt][nt].x * ga, c1 = d[mt][nt].y * ga;
            float c2 = d[mt][nt].z * gb, c3 = d[mt][nt].w * gb;
            store_frag(bufA, S_E, g, f, mt, make_float4(c0, c1, c2, c3));
            if (e0 + ea < E) {
                float* dst = g_ef_sum + (size_t)s_col[ea] * F_ + f;
                atomicAdd(dst, c0); atomicAdd(dst + 1, c1);
            }
            if (e0 + eb < E) {
                float* dst = g_ef_sum + (size_t)s_col[eb] * F_ + f;
                atomicAdd(dst, c2); atomicAdd(dst + 1, c3);
            }
        }
    }
    if (tid < TIL && e0 + tid < E) {
        atomicAdd(&g_cnt_col[s_col[tid]], 1.f);
        atomicAdd(&g_cnt_row[s_row[tid]], 1.f);
    }
    __syncthreads();

    zero_d(d);
    gemm_chunk<S_E>(bufA, gw + WF_C1, nt0, 0, 16, 16, g, tig, lane, d);
    #pragma unroll
    for (int mt = 0; mt < 2; ++mt)
        #pragma unroll
        for (int nt = 0; nt < 4; ++nt) {
            int f = w * 32 + nt * 8 + 2 * tig;
            float2 bb = *(const float2*)(c_b1 + f);
            store_frag(bufB, S_E, g, f, mt,
                make_float4(silu_(d[mt][nt].x + bb.x), silu_(d[mt][nt].y + bb.y),
                            silu_(d[mt][nt].z + bb.x), silu_(d[mt][nt].w + bb.y)));
        }
    __syncthreads();

    if (w < 2) {
        float4 dc[2] = {make_float4(0,0,0,0), make_float4(0,0,0,0)};
        #pragma unroll 4
        for (int ks = 0; ks < 16; ++ks) {
            int k0 = ks * 8;
            float2 b = gw[WF_C2 + ((size_t)w * 16 + ks) * 32 + lane];
            u32 b0 = __float_as_uint(b.x), b1 = __float_as_uint(b.y);
            #pragma unroll
            for (int mt = 0; mt < 2; ++mt) {
                const float* r0 = bufB + (mt * 16 + g) * S_E + k0;
                const float* r1 = bufB + (mt * 16 + g + 8) * S_E + k0;
                mma8(dc[mt], __float_as_uint(r0[tig]), __float_as_uint(r1[tig]),
                     __float_as_uint(r0[tig + 4]), __float_as_uint(r1[tig + 4]), b0, b1);
            }
        }
        int o = w * 8 + 2 * tig;
        float cbx = (o < 14)     ? __ldg(c_b2 + o)     : 0.f;
        float cby = (o + 1 < 14) ? __ldg(c_b2 + o + 1) : 0.f;
        #pragma unroll
        for (int mt = 0; mt < 2; ++mt) {
            *(float2*)(cm_s + (mt * 16 + g) * 16 + o) =
                make_float2(dc[mt].x + cbx, dc[mt].y + cby);
            *(float2*)(cm_s + (mt * 16 + g + 8) * 16 + o) =
                make_float2(dc[mt].z + cbx, dc[mt].w + cby);
        }
    }
    __syncthreads();

    for (int idx = tid; idx < TIL * 42; idx += 128) {
        int m = idx / 42, rem = idx - m * 42;
        int e = e0 + m;
        if (e < E) {
            int i = rem / 3, dd = rem - i * 3;
            int ws = 15 - s_cs[m];
            if (ws < 1)  ws = 1;
            if (ws > 14) ws = 14;
            int end = i + ws; if (end > 14) end = 14;
            float ps = 0.f;
            for (int q = i; q < end; ++q) ps += cm_s[m * 16 + q];
            float pooled = ps / (float)ws;
            float cd = x[(size_t)s_row[m] * 42 + rem] - g_pooled[s_col[m] * 3 + dd];
            atomicAdd(&g_x_acc[(size_t)s_row[m] * 42 + rem], cd * pooled);
        }
    }
}

// ---------------------------------------------------------------------------
// K4: node update via mma (unchanged from passing Round-6)
// ---------------------------------------------------------------------------
__global__ __launch_bounds__(128) void k_node(
    const float* __restrict__ h, const float* __restrict__ x,
    const float* __restrict__ n_b1, const float* __restrict__ n_b2,
    const float* __restrict__ ln_g, const float* __restrict__ ln_b,
    float* __restrict__ out, int N)
{
    extern __shared__ float sm[];
    float* in_s = sm;
    float* bufB = in_s + 32 * S_N;
    float* gp1  = bufB + 32 * S_E;
    float* gp2  = gp1 + 144;
    float* mu_s = gp2 + 144;
    float* rs_s = mu_s + 32;
    float* ic_s = rs_s + 32;

    int tid = threadIdx.x, lane = tid & 31, w = tid >> 5;
    int g = lane >> 2, tig = lane & 3, nt0 = w * 4;
    int n0 = blockIdx.x * TIL;
    const float2* gw = (const float2*)g_wt;

    if (tid < TIL) {
        int n = n0 + tid;
        float c = (n < N) ? g_cnt_col[n] : 1.f;
        ic_s[tid] = 1.f / fmaxf(c, 1.f);
    }
    __syncthreads();

    for (int i = tid; i < 2048; i += 128) {
        int e = i >> 6, q = i & 63;
        int n = n0 + e; if (n >= N) n = N - 1;
        float4 v;
        if (q < 32) v = *(const float4*)(h + (size_t)n * F_ + q * 4);
        else {
            v = *(const float4*)(g_ef_sum + (size_t)n * F_ + (q - 32) * 4);
            float ic = ic_s[e];
            v = make_float4(v.x * ic, v.y * ic, v.z * ic, v.w * ic);
        }
        *(float4*)(in_s + e * S_N + q * 4) = cvt4(v);
    }
    __syncthreads();

    float4 d[2][4]; zero_d(d);
    gemm_chunk<S_N>(in_s, gw + WF_N1, nt0, 0, 32, 32, g, tig, lane, d);
    #pragma unroll
    for (int mt = 0; mt < 2; ++mt)
        #pragma unroll
        for (int nt = 0; nt < 4; ++nt) {
            int f = w * 32 + nt * 8 + 2 * tig;
            float2 bb = *(const float2*)(n_b1 + f);
            store_frag(bufB, S_E, g, f, mt,
                make_float4(silu_(d[mt][nt].x + bb.x), silu_(d[mt][nt].y + bb.y),
                            silu_(d[mt][nt].z + bb.x), silu_(d[mt][nt].w + bb.y)));
        }
    __syncthreads();

    zero_d(d);
    gemm_chunk<S_E>(bufB, gw + WF_N2, nt0, 0, 16, 16, g, tig, lane, d);

    {
        float p1[4] = {0,0,0,0}, p2[4] = {0,0,0,0};
        #pragma unroll
        for (int mt = 0; mt < 2; ++mt) {
            int na = n0 + mt * 16 + g, nb = na + 8;
            if (na >= N) na = N - 1;
            if (nb >= N) nb = N - 1;
            #pragma unroll
            for (int nt = 0; nt < 4; ++nt) {
                int f = w * 32 + nt * 8 + 2 * tig;
                float2 bb = *(const float2*)(n_b2 + f);
                float2 ra = *(const float2*)(h + (size_t)na * F_ + f);
                float2 rb = *(const float2*)(h + (size_t)nb * F_ + f);
                float h0 = ra.x + d[mt][nt].x + bb.x, h1 = ra.y + d[mt][nt].y + bb.y;
                float h2 = rb.x + d[mt][nt].z + bb.x, h3 = rb.y + d[mt][nt].w + bb.y;
                d[mt][nt] = make_float4(h0, h1, h2, h3);
                p1[mt*2]   += h0 + h1;  p2[mt*2]   += h0*h0 + h1*h1;
                p1[mt*2+1] += h2 + h3;  p2[mt*2+1] += h2*h2 + h3*h3;
            }
        }
        #pragma unroll
        for (int o = 1; o <= 2; o <<= 1)
            #pragma unroll
            for (int q = 0; q < 4; ++q) {
                p1[q] += __shfl_xor_sync(0xffffffffu, p1[q], o);
                p2[q] += __shfl_xor_sync(0xffffffffu, p2[q], o);
            }
        if (tig == 0) {
            #pragma unroll
            for (int q = 0; q < 4; ++q) {
                int e = (q >> 1) * 16 + g + (q & 1) * 8;
                gp1[w * 36 + e] = p1[q];
                gp2[w * 36 + e] = p2[q];
            }
        }
    }
    __syncthreads();
    if (tid < TIL) {
        float s1 = gp1[tid] + gp1[36 + tid] + gp1[72 + tid] + gp1[108 + tid];
        float s2 = gp2[tid] + gp2[36 + tid] + gp2[72 + tid] + gp2[108 + tid];
        float mu = s1 * (1.f / 128.f);
        float var = fmaxf(s2 * (1.f / 128.f) - mu * mu, 0.f);
        mu_s[tid] = mu;
        rs_s[tid] = rsqrtf(var + 1e-5f);
    }
    __syncthreads();

    #pragma unroll
    for (int mt = 0; mt < 2; ++mt) {
        int ea = mt * 16 + g, eb = ea + 8;
        int na = n0 + ea, nb = n0 + eb;
        float mua = mu_s[ea], rsa = rs_s[ea];
        float mub = mu_s[eb], rsb = rs_s[eb];
        #pragma unroll
        for (int nt = 0; nt < 4; ++nt) {
            int f = w * 32 + nt * 8 + 2 * tig;
            float2 gv = *(const float2*)(ln_g + f);
            float2 bv = *(const float2*)(ln_b + f);
            if (na < N)
                *(float2*)(out + (size_t)na * F_ + f) = make_float2(
                    (d[mt][nt].x - mua) * rsa * gv.x + bv.x,
                    (d[mt][nt].y - mua) * rsa * gv.y + bv.y);
            if (nb < N)
                *(float2*)(out + (size_t)nb * F_ + f) = make_float2(
                    (d[mt][nt].z - mub) * rsb * gv.x + bv.x,
                    (d[mt][nt].w - mub) * rsb * gv.y + bv.y);
        }
    }

    float* out_x = out + (size_t)N * F_;
    for (int idx = tid; idx < TIL * 42; idx += 128) {
        int m = idx / 42, rem = idx - m * 42;
        int n = n0 + m;
        if (n < N)
            out_x[(size_t)n * 42 + rem] = x[(size_t)n * 42 + rem] +
                g_x_acc[(size_t)n * 42 + rem] / fmaxf(g_cnt_row[n], 1.f);
    }
}

// ---------------------------------------------------------------------------
extern "C" void kernel_launch(void* const* d_in, const int* in_sizes, int n_in,
                              void* d_out, int out_size) {
    const float* h     = (const float*)d_in[0];
    const float* x     = (const float*)d_in[1];
    const float* attr  = (const float*)d_in[2];
    const float* cw    = (const float*)d_in[3];
    const int*   row   = (const int*)d_in[4];
    const int*   col   = (const int*)d_in[5];
    const float* rad_w = (const float*)d_in[6];
    const float* rad_b = (const float*)d_in[7];
    const float* e_w1  = (const float*)d_in[8];
    const float* e_b1  = (const float*)d_in[9];
    const float* e_w2  = (const float*)d_in[10];
    const float* e_b2  = (const float*)d_in[11];
    const float* att_w = (const float*)d_in[12];
    const float* att_b = (const float*)d_in[13];
    const float* c_w1  = (const float*)d_in[14];
    const float* c_b1  = (const float*)d_in[15];
    const float* c_w2  = (const float*)d_in[16];
    const float* c_b2  = (const float*)d_in[17];
    const float* n_w1  = (const float*)d_in[18];
    const float* n_b1  = (const float*)d_in[19];
    const float* n_w2  = (const float*)d_in[20];
    const float* n_b2  = (const float*)d_in[21];
    const float* ln_g  = (const float*)d_in[22];
    const float* ln_b  = (const float*)d_in[23];

    int N = in_sizes[0] / F_;
    int E = in_sizes[4];

    const int SMEM_R = (32 * S_N + 4 * WSC + 32) * 4;
    const int SMEM_E = (2 * 32 * S_E + 512 + 144 + 32) * 4 + 96 * 4;
    const int SMEM_N = (32 * S_N + 32 * S_E + 144 + 144 + 32 + 32 + 32) * 4;

    cudaFuncSetAttribute(k_radial, cudaFuncAttributeMaxDynamicSharedMemorySize, SMEM_R);
    cudaFuncSetAttribute(k_edge,   cudaFuncAttributeMaxDynamicSharedMemorySize, SMEM_E);
    cudaFuncSetAttribute(k_node,   cudaFuncAttributeMaxDynamicSharedMemorySize, SMEM_N);

    k_zero<<<256, 256>>>(N);
    k_prep<<<(N + 255) / 256, 256>>>(x, cw, N);
    k_wprep<<<324, 256>>>(e_w1, e_w2, c_w1, c_w2, rad_w, n_w1, n_w2);
    k_radial<<<(E + TIL - 1) / TIL, 128, SMEM_R>>>(x, attr, cw, row, col, rad_b, E);
    k_edge<<<(E + TIL - 1) / TIL, 128, SMEM_E>>>(h, x, row, col, e_b1, e_b2,
                                                 att_w, att_b, c_b1, c_b2, E);
    k_node<<<(N + TIL - 1) / TIL, 128, SMEM_N>>>(h, x, n_b1, n_b2,
                                                 ln_g, ln_b, (float*)d_out, N);
}

// round 8
// speedup vs baseline: 4.1151x; 1.2292x over previous
#include <cuda_runtime.h>

#define NMAX 20000
#define EMAX 200000
#define C_   14
#define F_   128
#define TIL  32
#define S_E  132
#define S_N  260

typedef unsigned int u32;

// ---- scratch ----
__device__ __align__(16) float g_rad [(size_t)EMAX * F_];   // row-major [E][128], tf32 bits
__device__ __align__(16) float g_wt  [165888];              // fragment-major weights (tf32)
__device__ float g_ef_sum[(size_t)NMAX * F_];
__device__ float g_x_acc [(size_t)NMAX * C_ * 3];
__device__ float g_cnt_row[NMAX];
__device__ float g_cnt_col[NMAX];
__device__ float g_pooled [NMAX * 3];
__device__ int   g_csum   [NMAX];

// fragment-image offsets in float2 units
#define WF_E1 0
#define WF_E2 24576
#define WF_C1 32768
#define WF_C2 40960
#define WF_RW 41984
#define WF_N1 58368
#define WF_N2 74752

__device__ __forceinline__ float sigm_(float v) { return 1.f / (1.f + __expf(-v)); }
__device__ __forceinline__ float silu_(float v) { return v * sigm_(v); }
__device__ __forceinline__ u32 tf32r(float v) {
    u32 r; asm("cvt.rna.tf32.f32 %0, %1;" : "=r"(r) : "f"(v)); return r;
}
__device__ __forceinline__ float u2f(u32 v) { return __uint_as_float(v); }
__device__ __forceinline__ float4 cvt4(float4 v) {
    return make_float4(u2f(tf32r(v.x)), u2f(tf32r(v.y)), u2f(tf32r(v.z)), u2f(tf32r(v.w)));
}

// mma.sync m16n8k8 tf32: D += A*B
__device__ __forceinline__ void mma8(float4& d, u32 a0, u32 a1, u32 a2, u32 a3,
                                     u32 b0, u32 b1) {
    asm volatile(
        "mma.sync.aligned.m16n8k8.row.col.f32.tf32.tf32.f32 "
        "{%0,%1,%2,%3},{%4,%5,%6,%7},{%8,%9},{%0,%1,%2,%3};"
        : "+f"(d.x), "+f"(d.y), "+f"(d.z), "+f"(d.w)
        : "r"(a0), "r"(a1), "r"(a2), "r"(a3), "r"(b0), "r"(b1));
}

template<int S, int NT>
__device__ __forceinline__ void gemm_chunkT(const float* in_s, const float2* wf,
                                            int nt0, int ks0, int nks, int KST,
                                            int g, int tig, int lane, float4 d[2][NT])
{
    #pragma unroll 4
    for (int ks = 0; ks < nks; ++ks) {
        int k0 = ks * 8;
        u32 a[2][4];
        #pragma unroll
        for (int mt = 0; mt < 2; ++mt) {
            const float* r0 = in_s + (mt * 16 + g) * S + k0;
            const float* r1 = in_s + (mt * 16 + g + 8) * S + k0;
            a[mt][0] = __float_as_uint(r0[tig]);
            a[mt][1] = __float_as_uint(r1[tig]);
            a[mt][2] = __float_as_uint(r0[tig + 4]);
            a[mt][3] = __float_as_uint(r1[tig + 4]);
        }
        #pragma unroll
        for (int nt = 0; nt < NT; ++nt) {
            float2 b = wf[((size_t)(nt0 + nt) * KST + ks0 + ks) * 32 + lane];
            u32 b0 = __float_as_uint(b.x), b1 = __float_as_uint(b.y);
            mma8(d[0][nt], a[0][0], a[0][1], a[0][2], a[0][3], b0, b1);
            mma8(d[1][nt], a[1][0], a[1][1], a[1][2], a[1][3], b0, b1);
        }
    }
}

__device__ __forceinline__ void zero_d4(float4 d[2][4]) {
    #pragma unroll
    for (int mt = 0; mt < 2; ++mt)
        #pragma unroll
        for (int nt = 0; nt < 4; ++nt) d[mt][nt] = make_float4(0.f, 0.f, 0.f, 0.f);
}

__device__ __forceinline__ void store_frag(float* buf, int S, int g, int f, int mt,
                                           float4 v) {
    *(float2*)(buf + (mt * 16 + g) * S + f) =
        make_float2(u2f(tf32r(v.x)), u2f(tf32r(v.y)));
    *(float2*)(buf + (mt * 16 + g + 8) * S + f) =
        make_float2(u2f(tf32r(v.z)), u2f(tf32r(v.w)));
}

// ---------------------------------------------------------------------------
__global__ void k_zero(int n_nodes) {
    int t0 = n_nodes * F_, t1 = t0 + n_nodes * C_ * 3, t2 = t1 + n_nodes, t3 = t2 + n_nodes;
    for (int i = blockIdx.x * blockDim.x + threadIdx.x; i < t3; i += gridDim.x * blockDim.x) {
        if (i < t0)       g_ef_sum[i] = 0.f;
        else if (i < t1)  g_x_acc[i - t0] = 0.f;
        else if (i < t2)  g_cnt_row[i - t1] = 0.f;
        else              g_cnt_col[i - t2] = 0.f;
    }
}

__global__ void k_prep(const float* __restrict__ x, const float* __restrict__ cw, int N) {
    int n = blockIdx.x * blockDim.x + threadIdx.x;
    if (n >= N) return;
    int s = 0; float px = 0.f, py = 0.f, pz = 0.f;
    #pragma unroll
    for (int i = 0; i < C_; ++i) {
        float w = cw[n * C_ + i];
        if (w != 0.f) {
            s++; px += x[n * 42 + i * 3]; py += x[n * 42 + i * 3 + 1]; pz += x[n * 42 + i * 3 + 2];
        }
    }
    g_csum[n] = s;
    float inv = 1.f / (float)(s > 0 ? s : 1);
    g_pooled[n * 3] = px * inv; g_pooled[n * 3 + 1] = py * inv; g_pooled[n * 3 + 2] = pz * inv;
}

__global__ void k_wprep(const float* __restrict__ e_w1, const float* __restrict__ e_w2,
                        const float* __restrict__ c_w1, const float* __restrict__ c_w2,
                        const float* __restrict__ rad_w, const float* __restrict__ n_w1,
                        const float* __restrict__ n_w2) {
    int t = blockIdx.x * blockDim.x + threadIdx.x;
    if (t >= 82944) return;
    int u = t, base; const float* W; int KST, Ncol;
    if      (u < 24576) { base = WF_E1; W = e_w1; KST = 48; Ncol = 128; }
    else if (u < 32768) { u -= 24576; base = WF_E2; W = e_w2;  KST = 16; Ncol = 128; }
    else if (u < 40960) { u -= 32768; base = WF_C1; W = c_w1;  KST = 16; Ncol = 128; }
    else if (u < 41984) { u -= 40960; base = WF_C2; W = c_w2;  KST = 16; Ncol = 14;  }
    else if (u < 58368) { u -= 41984; base = WF_RW; W = rad_w; KST = 32; Ncol = 128; }
    else if (u < 74752) { u -= 58368; base = WF_N1; W = n_w1;  KST = 32; Ncol = 128; }
    else                { u -= 74752; base = WF_N2; W = n_w2;  KST = 16; Ncol = 128; }
    int lane = u & 31, ks = (u >> 5) % KST, nt = u / (KST * 32);
    int g = lane >> 2, tig = lane & 3;
    int n = nt * 8 + g, k = ks * 8 + tig;
    float b0 = 0.f, b1 = 0.f;
    if (n < Ncol) { b0 = W[k * Ncol + n]; b1 = W[(k + 4) * Ncol + n]; }
    ((float2*)g_wt)[base + u] = make_float2(u2f(tf32r(b0)), u2f(tf32r(b1)));
}

// ---------------------------------------------------------------------------
// K2: radial — 256 threads, 8 warps x 4 edges, register-prefetched gathers,
// mma einsum prologue + mma GEMM K=256 (2 n-tiles per warp)
// per-warp scratch: msg 272, T 272, xr 48, xc 48, cwr 16, cwc 16, ar 224, ac 224 = 1120
// ---------------------------------------------------------------------------
#define WSC 1120
__global__ __launch_bounds__(256, 3) void k_radial(
    const float* __restrict__ x, const float* __restrict__ attr,
    const float* __restrict__ cw, const int* __restrict__ row,
    const int* __restrict__ col, const float* __restrict__ rad_b, int E)
{
    extern __shared__ float sm[];
    float* in_s = sm;                    // [32][260], tf32 bits
    float* wsc  = sm + 32 * S_N;         // 8*WSC
    float* inv_norm = wsc + 8 * WSC;     // 32

    int tid = threadIdx.x, lane = tid & 31, w = tid >> 5;
    int g = lane >> 2, tig = lane & 3;
    int e0 = blockIdx.x * TIL;

    float* W = wsc + w * WSC;
    float *s_msg = W, *s_T = W + 272, *s_xr = W + 544, *s_xc = W + 592,
          *s_cwr = W + 640, *s_cwc = W + 656, *s_ar = W + 672, *s_ac = W + 896;

    // register prefetch buffers (attr gathers, the big ones)
    float p_ar[7], p_ac[7];
    int p_r, p_c;

    {   // prefetch edge for it=0
        int e = e0 + w * 4; if (e >= E) e = E - 1;
        p_r = row[e]; p_c = col[e];
        #pragma unroll
        for (int q = 0; q < 7; ++q) {
            p_ar[q] = attr[p_r * 224 + q * 32 + lane];
            p_ac[q] = attr[p_c * 224 + q * 32 + lane];
        }
    }

    for (int it = 0; it < 4; ++it) {
        int m = w * 4 + it;
        int r = p_r, c = p_c;

        // commit prefetched attr to smem
        #pragma unroll
        for (int q = 0; q < 7; ++q) {
            s_ar[q * 32 + lane] = p_ar[q];
            s_ac[q * 32 + lane] = p_ac[q];
        }
        // short gathers (x, cw) — issued here, consumed after syncwarp
        s_xr[lane] = x[r * 42 + lane];
        s_xc[lane] = x[c * 42 + lane];
        if (lane < 16) {
            s_xr[32 + lane] = (lane < 10) ? x[r * 42 + 32 + lane] : 0.f;
            s_xc[32 + lane] = (lane < 10) ? x[c * 42 + 32 + lane] : 0.f;
            s_cwr[lane] = (lane < 14) ? cw[r * C_ + lane] : 0.f;
            s_cwc[lane] = (lane < 14) ? cw[c * C_ + lane] : 0.f;
        }

        // issue next iteration's attr prefetch (overlaps with compute below)
        if (it < 3) {
            int e = e0 + m + 1; if (e >= E) e = E - 1;
            p_r = row[e]; p_c = col[e];
            #pragma unroll
            for (int q = 0; q < 7; ++q) {
                p_ar[q] = attr[p_r * 224 + q * 32 + lane];
                p_ac[q] = attr[p_c * 224 + q * 32 + lane];
            }
        }
        __syncwarp();

        // msg[ci][cj] (16x16; rows/cols >=14 zero via cw=0, x padded 0)
        #pragma unroll
        for (int q = 0; q < 8; ++q) {
            int i = q * 32 + lane;
            int ci = i >> 4, cj = i & 15;
            float dx = s_xr[ci * 3] - s_xc[cj * 3];
            float dy = s_xr[ci * 3 + 1] - s_xc[cj * 3 + 1];
            float dz = s_xr[ci * 3 + 2] - s_xc[cj * 3 + 2];
            s_msg[ci * 17 + cj] =
                sqrtf(dx * dx + dy * dy + dz * dz) * s_cwr[ci] * s_cwc[cj];
        }
        __syncwarp();

        // T = msg @ ac
        float4 dT[2] = {make_float4(0,0,0,0), make_float4(0,0,0,0)};
        #pragma unroll
        for (int kk = 0; kk < 2; ++kk) {
            int k0 = kk * 8 + tig, k1 = k0 + 4;
            u32 a0 = tf32r(s_msg[g * 17 + k0]);
            u32 a1 = tf32r(s_msg[(g + 8) * 17 + k0]);
            u32 a2 = tf32r(s_msg[g * 17 + k1]);
            u32 a3 = tf32r(s_msg[(g + 8) * 17 + k1]);
            #pragma unroll
            for (int nt = 0; nt < 2; ++nt) {
                float b0f = (k0 < 14) ? s_ac[k0 * 16 + nt * 8 + g] : 0.f;
                float b1f = (k1 < 14) ? s_ac[k1 * 16 + nt * 8 + g] : 0.f;
                mma8(dT[nt], a0, a1, a2, a3, tf32r(b0f), tf32r(b1f));
            }
        }
        #pragma unroll
        for (int nt = 0; nt < 2; ++nt) {
            int fc = nt * 8 + 2 * tig;
            s_T[g * 17 + fc]           = u2f(tf32r(dT[nt].x));
            s_T[g * 17 + fc + 1]       = u2f(tf32r(dT[nt].y));
            s_T[(g + 8) * 17 + fc]     = u2f(tf32r(dT[nt].z));
            s_T[(g + 8) * 17 + fc + 1] = u2f(tf32r(dT[nt].w));
        }
        __syncwarp();

        // R = ar^T @ T
        float4 dR[2] = {make_float4(0,0,0,0), make_float4(0,0,0,0)};
        #pragma unroll
        for (int kk = 0; kk < 2; ++kk) {
            int k0 = kk * 8 + tig, k1 = k0 + 4;
            u32 a0 = tf32r(s_ar[k0 * 16 + g]);
            u32 a1 = tf32r(s_ar[k0 * 16 + g + 8]);
            u32 a2 = tf32r((k1 < 14) ? s_ar[k1 * 16 + g] : 0.f);
            u32 a3 = tf32r((k1 < 14) ? s_ar[k1 * 16 + g + 8] : 0.f);
            #pragma unroll
            for (int nt = 0; nt < 2; ++nt) {
                u32 b0 = __float_as_uint(s_T[k0 * 17 + nt * 8 + g]);
                u32 b1 = __float_as_uint(s_T[k1 * 17 + nt * 8 + g]);
                mma8(dR[nt], a0, a1, a2, a3, b0, b1);
            }
        }

        float ss = dR[0].x*dR[0].x + dR[0].y*dR[0].y + dR[0].z*dR[0].z + dR[0].w*dR[0].w
                 + dR[1].x*dR[1].x + dR[1].y*dR[1].y + dR[1].z*dR[1].z + dR[1].w*dR[1].w;
        #pragma unroll
        for (int o = 16; o; o >>= 1) ss += __shfl_xor_sync(0xffffffffu, ss, o);
        if (lane == 0) inv_norm[m] = 1.f / (sqrtf(ss) + 1.f);

        #pragma unroll
        for (int nt = 0; nt < 2; ++nt) {
            int fc = nt * 8 + 2 * tig;
            *(float2*)(in_s + m * S_N + g * 16 + fc) =
                make_float2(u2f(tf32r(dR[nt].x)), u2f(tf32r(dR[nt].y)));
            *(float2*)(in_s + m * S_N + (g + 8) * 16 + fc) =
                make_float2(u2f(tf32r(dR[nt].z)), u2f(tf32r(dR[nt].w)));
        }
        __syncwarp();
    }
    __syncthreads();

    const float2* gw = (const float2*)g_wt;
    float4 d[2][2];
    d[0][0] = d[0][1] = d[1][0] = d[1][1] = make_float4(0.f, 0.f, 0.f, 0.f);
    gemm_chunkT<S_N, 2>(in_s, gw + WF_RW, w * 2, 0, 32, 32, g, tig, lane, d);

    #pragma unroll
    for (int mt = 0; mt < 2; ++mt)
        #pragma unroll
        for (int nt = 0; nt < 2; ++nt) {
            int f = w * 16 + nt * 8 + 2 * tig;
            float2 rb = *(const float2*)(rad_b + f);
            int e = mt * 16 + g;
            float na = inv_norm[e], nb = inv_norm[e + 8];
            int ea = e0 + e;
            if (ea < E)
                *(float2*)(g_rad + (size_t)ea * F_ + f) =
                    make_float2(u2f(tf32r((d[mt][nt].x + rb.x) * na)),
                                u2f(tf32r((d[mt][nt].y + rb.y) * na)));
            if (ea + 8 < E)
                *(float2*)(g_rad + (size_t)(ea + 8) * F_ + f) =
                    make_float2(u2f(tf32r((d[mt][nt].z + rb.x) * nb)),
                                u2f(tf32r((d[mt][nt].w + rb.y) * nb)));
        }
}

// ---------------------------------------------------------------------------
// K3: fused edge kernel
// ---------------------------------------------------------------------------
__global__ __launch_bounds__(128) void k_edge(
    const float* __restrict__ h, const float* __restrict__ x,
    const int* __restrict__ row, const int* __restrict__ col,
    const float* __restrict__ e_b1, const float* __restrict__ e_b2,
    const float* __restrict__ att_w, const float* __restrict__ att_b,
    const float* __restrict__ c_b1, const float* __restrict__ c_b2, int E)
{
    extern __shared__ float sm[];
    float* bufA = sm;
    float* bufB = bufA + 32 * S_E;
    float* cm_s = bufB + 32 * S_E;
    float* gp   = cm_s + 512;
    float* gate_s = gp + 144;
    int* s_row = (int*)(gate_s + 32);
    int* s_col = s_row + 32;
    int* s_cs  = s_col + 32;

    int tid = threadIdx.x, lane = tid & 31, w = tid >> 5;
    int g = lane >> 2, tig = lane & 3, nt0 = w * 4;
    int e0 = blockIdx.x * TIL;
    const float2* gw = (const float2*)g_wt;

    if (tid < TIL) {
        int e = e0 + tid; if (e >= E) e = E - 1;
        int r = row[e];
        s_row[tid] = r; s_col[tid] = col[e]; s_cs[tid] = g_csum[r];
    }
    __syncthreads();

    float4 d[2][4]; zero_d4(d);
    for (int r = 0; r < 3; ++r) {
        for (int i = tid; i < 1024; i += 128) {
            int e = i >> 5, q = i & 31;
            float4 v;
            if (r == 0)      v = cvt4(*(const float4*)(h + (size_t)s_row[e] * F_ + q * 4));
            else if (r == 1) v = cvt4(*(const float4*)(h + (size_t)s_col[e] * F_ + q * 4));
            else {
                int eg = e0 + e; if (eg >= E) eg = E - 1;
                v = *(const float4*)(g_rad + (size_t)eg * F_ + q * 4);
            }
            *(float4*)(bufA + e * S_E + q * 4) = v;
        }
        __syncthreads();
        gemm_chunkT<S_E, 4>(bufA, gw + WF_E1, nt0, r * 16, 16, 48, g, tig, lane, d);
        __syncthreads();
    }

    #pragma unroll
    for (int mt = 0; mt < 2; ++mt)
        #pragma unroll
        for (int nt = 0; nt < 4; ++nt) {
            int f = w * 32 + nt * 8 + 2 * tig;
            float2 bb = *(const float2*)(e_b1 + f);
            store_frag(bufB, S_E, g, f, mt,
                make_float4(silu_(d[mt][nt].x + bb.x), silu_(d[mt][nt].y + bb.y),
                            silu_(d[mt][nt].z + bb.x), silu_(d[mt][nt].w + bb.y)));
        }
    __syncthreads();

    zero_d4(d);
    gemm_chunkT<S_E, 4>(bufB, gw + WF_E2, nt0, 0, 16, 16, g, tig, lane, d);

    {
        float p[4] = {0.f, 0.f, 0.f, 0.f};
        #pragma unroll
        for (int mt = 0; mt < 2; ++mt)
            #pragma unroll
            for (int nt = 0; nt < 4; ++nt) {
                int f = w * 32 + nt * 8 + 2 * tig;
                float2 bb = *(const float2*)(e_b2 + f);
                float2 aw = *(const float2*)(att_w + f);
                float c0 = silu_(d[mt][nt].x + bb.x), c1 = silu_(d[mt][nt].y + bb.y);
                float c2 = silu_(d[mt][nt].z + bb.x), c3 = silu_(d[mt][nt].w + bb.y);
                d[mt][nt] = make_float4(c0, c1, c2, c3);
                p[mt * 2 + 0] += c0 * aw.x + c1 * aw.y;
                p[mt * 2 + 1] += c2 * aw.x + c3 * aw.y;
            }
        #pragma unroll
        for (int o = 1; o <= 2; o <<= 1)
            #pragma unroll
            for (int q = 0; q < 4; ++q) p[q] += __shfl_xor_sync(0xffffffffu, p[q], o);
        if (tig == 0) {
            gp[w * 36 + g]      = p[0];
            gp[w * 36 + g + 8]  = p[1];
            gp[w * 36 + g + 16] = p[2];
            gp[w * 36 + g + 24] = p[3];
        }
    }
    __syncthreads();
    if (tid < TIL)
        gate_s[tid] = sigm_(gp[tid] + gp[36 + tid] + gp[72 + tid] + gp[108 + tid]
                            + __ldg(att_b));
    __syncthreads();
    #pragma unroll
    for (int mt = 0; mt < 2; ++mt) {
        int ea = mt * 16 + g, eb = ea + 8;
        float ga = gate_s[ea], gb = gate_s[eb];
        #pragma unroll
        for (int nt = 0; nt < 4; ++nt) {
            int f = w * 32 + nt * 8 + 2 * tig;
            float c0 = d[mt][nt].x * ga, c1 = d[mt][nt].y * ga;
            float c2 = d[mt][nt].z * gb, c3 = d[mt][nt].w * gb;
            store_frag(bufA, S_E, g, f, mt, make_float4(c0, c1, c2, c3));
            if (e0 + ea < E) {
                float* dst = g_ef_sum + (size_t)s_col[ea] * F_ + f;
                atomicAdd(dst, c0); atomicAdd(dst + 1, c1);
            }
            if (e0 + eb < E) {
                float* dst = g_ef_sum + (size_t)s_col[eb] * F_ + f;
                atomicAdd(dst, c2); atomicAdd(dst + 1, c3);
            }
        }
    }
    if (tid < TIL && e0 + tid < E) {
        atomicAdd(&g_cnt_col[s_col[tid]], 1.f);
        atomicAdd(&g_cnt_row[s_row[tid]], 1.f);
    }
    __syncthreads();

    zero_d4(d);
    gemm_chunkT<S_E, 4>(bufA, gw + WF_C1, nt0, 0, 16, 16, g, tig, lane, d);
    #pragma unroll
    for (int mt = 0; mt < 2; ++mt)
        #pragma unroll
        for (int nt = 0; nt < 4; ++nt) {
            int f = w * 32 + nt * 8 + 2 * tig;
            float2 bb = *(const float2*)(c_b1 + f);
            store_frag(bufB, S_E, g, f, mt,
                make_float4(silu_(d[mt][nt].x + bb.x), silu_(d[mt][nt].y + bb.y),
                            silu_(d[mt][nt].z + bb.x), silu_(d[mt][nt].w + bb.y)));
        }
    __syncthreads();

    if (w < 2) {
        float4 dc[2] = {make_float4(0,0,0,0), make_float4(0,0,0,0)};
        #pragma unroll 4
        for (int ks = 0; ks < 16; ++ks) {
            int k0 = ks * 8;
            float2 b = gw[WF_C2 + ((size_t)w * 16 + ks) * 32 + lane];
            u32 b0 = __float_as_uint(b.x), b1 = __float_as_uint(b.y);
            #pragma unroll
            for (int mt = 0; mt < 2; ++mt) {
                const float* r0 = bufB + (mt * 16 + g) * S_E + k0;
                const float* r1 = bufB + (mt * 16 + g + 8) * S_E + k0;
                mma8(dc[mt], __float_as_uint(r0[tig]), __float_as_uint(r1[tig]),
                     __float_as_uint(r0[tig + 4]), __float_as_uint(r1[tig + 4]), b0, b1);
            }
        }
        int o = w * 8 + 2 * tig;
        float cbx = (o < 14)     ? __ldg(c_b2 + o)     : 0.f;
        float cby = (o + 1 < 14) ? __ldg(c_b2 + o + 1) : 0.f;
        #pragma unroll
        for (int mt = 0; mt < 2; ++mt) {
            *(float2*)(cm_s + (mt * 16 + g) * 16 + o) =
                make_float2(dc[mt].x + cbx, dc[mt].y + cby);
            *(float2*)(cm_s + (mt * 16 + g + 8) * 16 + o) =
                make_float2(dc[mt].z + cbx, dc[mt].w + cby);
        }
    }
    __syncthreads();

    for (int idx = tid; idx < TIL * 42; idx += 128) {
        int m = idx / 42, rem = idx - m * 42;
        int e = e0 + m;
        if (e < E) {
            int i = rem / 3, dd = rem - i * 3;
            int ws = 15 - s_cs[m];
            if (ws < 1)  ws = 1;
            if (ws > 14) ws = 14;
            int end = i + ws; if (end > 14) end = 14;
            float ps = 0.f;
            for (int q = i; q < end; ++q) ps += cm_s[m * 16 + q];
            float pooled = ps / (float)ws;
            float cd = x[(size_t)s_row[m] * 42 + rem] - g_pooled[s_col[m] * 3 + dd];
            atomicAdd(&g_x_acc[(size_t)s_row[m] * 42 + rem], cd * pooled);
        }
    }
}

// ---------------------------------------------------------------------------
// K4: node update via mma
// ---------------------------------------------------------------------------
__global__ __launch_bounds__(128) void k_node(
    const float* __restrict__ h, const float* __restrict__ x,
    const float* __restrict__ n_b1, const float* __restrict__ n_b2,
    const float* __restrict__ ln_g, const float* __restrict__ ln_b,
    float* __restrict__ out, int N)
{
    extern __shared__ float sm[];
    float* in_s = sm;
    float* bufB = in_s + 32 * S_N;
    float* gp1  = bufB + 32 * S_E;
    float* gp2  = gp1 + 144;
    float* mu_s = gp2 + 144;
    float* rs_s = mu_s + 32;
    float* ic_s = rs_s + 32;

    int tid = threadIdx.x, lane = tid & 31, w = tid >> 5;
    int g = lane >> 2, tig = lane & 3, nt0 = w * 4;
    int n0 = blockIdx.x * TIL;
    const float2* gw = (const float2*)g_wt;

    if (tid < TIL) {
        int n = n0 + tid;
        float c = (n < N) ? g_cnt_col[n] : 1.f;
        ic_s[tid] = 1.f / fmaxf(c, 1.f);
    }
    __syncthreads();

    for (int i = tid; i < 2048; i += 128) {
        int e = i >> 6, q = i & 63;
        int n = n0 + e; if (n >= N) n = N - 1;
        float4 v;
        if (q < 32) v = *(const float4*)(h + (size_t)n * F_ + q * 4);
        else {
            v = *(const float4*)(g_ef_sum + (size_t)n * F_ + (q - 32) * 4);
            float ic = ic_s[e];
            v = make_float4(v.x * ic, v.y * ic, v.z * ic, v.w * ic);
        }
        *(float4*)(in_s + e * S_N + q * 4) = cvt4(v);
    }
    __syncthreads();

    float4 d[2][4]; zero_d4(d);
    gemm_chunkT<S_N, 4>(in_s, gw + WF_N1, nt0, 0, 32, 32, g, tig, lane, d);
    #pragma unroll
    for (int mt = 0; mt < 2; ++mt)
        #pragma unroll
        for (int nt = 0; nt < 4; ++nt) {
            int f = w * 32 + nt * 8 + 2 * tig;
            float2 bb = *(const float2*)(n_b1 + f);
            store_frag(bufB, S_E, g, f, mt,
                make_float4(silu_(d[mt][nt].x + bb.x), silu_(d[mt][nt].y + bb.y),
                            silu_(d[mt][nt].z + bb.x), silu_(d[mt][nt].w + bb.y)));
        }
    __syncthreads();

    zero_d4(d);
    gemm_chunkT<S_E, 4>(bufB, gw + WF_N2, nt0, 0, 16, 16, g, tig, lane, d);

    {
        float p1[4] = {0,0,0,0}, p2[4] = {0,0,0,0};
        #pragma unroll
        for (int mt = 0; mt < 2; ++mt) {
            int na = n0 + mt * 16 + g, nb = na + 8;
            if (na >= N) na = N - 1;
            if (nb >= N) nb = N - 1;
            #pragma unroll
            for (int nt = 0; nt < 4; ++nt) {
                int f = w * 32 + nt * 8 + 2 * tig;
                float2 bb = *(const float2*)(n_b2 + f);
                float2 ra = *(const float2*)(h + (size_t)na * F_ + f);
                float2 rb = *(const float2*)(h + (size_t)nb * F_ + f);
                float h0 = ra.x + d[mt][nt].x + bb.x, h1 = ra.y + d[mt][nt].y + bb.y;
                float h2 = rb.x + d[mt][nt].z + bb.x, h3 = rb.y + d[mt][nt].w + bb.y;
                d[mt][nt] = make_float4(h0, h1, h2, h3);
                p1[mt*2]   += h0 + h1;  p2[mt*2]   += h0*h0 + h1*h1;
                p1[mt*2+1] += h2 + h3;  p2[mt*2+1] += h2*h2 + h3*h3;
            }
        }
        #pragma unroll
        for (int o = 1; o <= 2; o <<= 1)
            #pragma unroll
            for (int q = 0; q < 4; ++q) {
                p1[q] += __shfl_xor_sync(0xffffffffu, p1[q], o);
                p2[q] += __shfl_xor_sync(0xffffffffu, p2[q], o);
            }
        if (tig == 0) {
            #pragma unroll
            for (int q = 0; q < 4; ++q) {
                int e = (q >> 1) * 16 + g + (q & 1) * 8;
                gp1[w * 36 + e] = p1[q];
                gp2[w * 36 + e] = p2[q];
            }
        }
    }
    __syncthreads();
    if (tid < TIL) {
        float s1 = gp1[tid] + gp1[36 + tid] + gp1[72 + tid] + gp1[108 + tid];
        float s2 = gp2[tid] + gp2[36 + tid] + gp2[72 + tid] + gp2[108 + tid];
        float mu = s1 * (1.f / 128.f);
        float var = fmaxf(s2 * (1.f / 128.f) - mu * mu, 0.f);
        mu_s[tid] = mu;
        rs_s[tid] = rsqrtf(var + 1e-5f);
    }
    __syncthreads();

    #pragma unroll
    for (int mt = 0; mt < 2; ++mt) {
        int ea = mt * 16 + g, eb = ea + 8;
        int na = n0 + ea, nb = n0 + eb;
        float mua = mu_s[ea], rsa = rs_s[ea];
        float mub = mu_s[eb], rsb = rs_s[eb];
        #pragma unroll
        for (int nt = 0; nt < 4; ++nt) {
            int f = w * 32 + nt * 8 + 2 * tig;
            float2 gv = *(const float2*)(ln_g + f);
            float2 bv = *(const float2*)(ln_b + f);
            if (na < N)
                *(float2*)(out + (size_t)na * F_ + f) = make_float2(
                    (d[mt][nt].x - mua) * rsa * gv.x + bv.x,
                    (d[mt][nt].y - mua) * rsa * gv.y + bv.y);
            if (nb < N)
                *(float2*)(out + (size_t)nb * F_ + f) = make_float2(
                    (d[mt][nt].z - mub) * rsb * gv.x + bv.x,
                    (d[mt][nt].w - mub) * rsb * gv.y + bv.y);
        }
    }

    float* out_x = out + (size_t)N * F_;
    for (int idx = tid; idx < TIL * 42; idx += 128) {
        int m = idx / 42, rem = idx - m * 42;
        int n = n0 + m;
        if (n < N)
            out_x[(size_t)n * 42 + rem] = x[(size_t)n * 42 + rem] +
                g_x_acc[(size_t)n * 42 + rem] / fmaxf(g_cnt_row[n], 1.f);
    }
}

// ---------------------------------------------------------------------------
extern "C" void kernel_launch(void* const* d_in, const int* in_sizes, int n_in,
                              void* d_out, int out_size) {
    const float* h     = (const float*)d_in[0];
    const float* x     = (const float*)d_in[1];
    const float* attr  = (const float*)d_in[2];
    const float* cw    = (const float*)d_in[3];
    const int*   row   = (const int*)d_in[4];
    const int*   col   = (const int*)d_in[5];
    const float* rad_w = (const float*)d_in[6];
    const float* rad_b = (const float*)d_in[7];
    const float* e_w1  = (const float*)d_in[8];
    const float* e_b1  = (const float*)d_in[9];
    const float* e_w2  = (const float*)d_in[10];
    const float* e_b2  = (const float*)d_in[11];
    const float* att_w = (const float*)d_in[12];
    const float* att_b = (const float*)d_in[13];
    const float* c_w1  = (const float*)d_in[14];
    const float* c_b1  = (const float*)d_in[15];
    const float* c_w2  = (const float*)d_in[16];
    const float* c_b2  = (const float*)d_in[17];
    const float* n_w1  = (const float*)d_in[18];
    const float* n_b1  = (const float*)d_in[19];
    const float* n_w2  = (const float*)d_in[20];
    const float* n_b2  = (const float*)d_in[21];
    const float* ln_g  = (const float*)d_in[22];
    const float* ln_b  = (const float*)d_in[23];

    int N = in_sizes[0] / F_;
    int E = in_sizes[4];

    const int SMEM_R = (32 * S_N + 8 * WSC + 32) * 4;
    const int SMEM_E = (2 * 32 * S_E + 512 + 144 + 32) * 4 + 96 * 4;
    const int SMEM_N = (32 * S_N + 32 * S_E + 144 + 144 + 32 + 32 + 32) * 4;

    cudaFuncSetAttribute(k_radial, cudaFuncAttributeMaxDynamicSharedMemorySize, SMEM_R);
    cudaFuncSetAttribute(k_edge,   cudaFuncAttributeMaxDynamicSharedMemorySize, SMEM_E);
    cudaFuncSetAttribute(k_node,   cudaFuncAttributeMaxDynamicSharedMemorySize, SMEM_N);

    k_zero<<<256, 256>>>(N);
    k_prep<<<(N + 255) / 256, 256>>>(x, cw, N);
    k_wprep<<<324, 256>>>(e_w1, e_w2, c_w1, c_w2, rad_w, n_w1, n_w2);
    k_radial<<<(E + TIL - 1) / TIL, 256, SMEM_R>>>(x, attr, cw, row, col, rad_b, E);
    k_edge<<<(E + TIL - 1) / TIL, 128, SMEM_E>>>(h, x, row, col, e_b1, e_b2,
                                                 att_w, att_b, c_b1, c_b2, E);
    k_node<<<(N + TIL - 1) / TIL, 128, SMEM_N>>>(h, x, n_b1, n_b2,
                                                 ln_g, ln_b, (float*)d_out, N);
}